// round 2
// baseline (speedup 1.0000x reference)
#include <cuda_runtime.h>
#include <math.h>

#define NMAX 50000
#define EMAX 1600000
#define BOND_BLKS ((EMAX + 31) / 32)
#define TM_BLKS ((NMAX + 7) / 8)

// ---------------- scratch (device globals; no allocation allowed) ----------------
__device__ float d_h0 [(size_t)NMAX * 64];
__device__ float d_lin[(size_t)NMAX * 128];
__device__ float d_h  [(size_t)NMAX * 128];
__device__ float d_g  [(size_t)NMAX * 64];
__device__ float d_t1 [(size_t)NMAX * 64];
__device__ float d_t2h[(size_t)NMAX * 32];
__device__ float d_t2e[(size_t)NMAX * 32];
__device__ float d_dinv[NMAX];
__device__ int   d_deg[NMAX];
__device__ int   d_off[NMAX + 1];
__device__ int   d_cur[NMAX];
__device__ int   d_srcs[EMAX];
__device__ double d_pbond[BOND_BLKS];
__device__ double d_ptm[TM_BLKS];

// ---------------- degree / CSR build ----------------
__global__ void k_zero_deg(int n) {
    int i = blockIdx.x * blockDim.x + threadIdx.x;
    if (i < n) d_deg[i] = 0;
}

__global__ void k_count(const int* __restrict__ dst, int e) {
    int i = blockIdx.x * blockDim.x + threadIdx.x;
    if (i < e) atomicAdd(&d_deg[dst[i]], 1);
}

__global__ void k_dinv(int n) {
    int i = blockIdx.x * blockDim.x + threadIdx.x;
    if (i < n) d_dinv[i] = rsqrtf((float)(d_deg[i] + 1));  // +1: self loop
}

// single-block scan over deg -> exclusive offsets (+ cursor copy)
__global__ void k_scan(int n) {
    __shared__ int wsum[32];
    __shared__ int carry;
    int tid = threadIdx.x, lane = tid & 31, wid = tid >> 5;
    if (tid == 0) carry = 0;
    __syncthreads();
    for (int base = 0; base < n; base += 1024) {
        int i = base + tid;
        int v = (i < n) ? d_deg[i] : 0;
        int sc = v;
        #pragma unroll
        for (int st = 1; st < 32; st <<= 1) {
            int t = __shfl_up_sync(0xffffffffu, sc, st);
            if (lane >= st) sc += t;
        }
        if (lane == 31) wsum[wid] = sc;
        __syncthreads();
        if (wid == 0) {
            int s = wsum[lane];
            #pragma unroll
            for (int st = 1; st < 32; st <<= 1) {
                int t = __shfl_up_sync(0xffffffffu, s, st);
                if (lane >= st) s += t;
            }
            wsum[lane] = s;
        }
        __syncthreads();
        int excl = carry + (wid ? wsum[wid - 1] : 0) + sc - v;
        if (i < n) { d_off[i] = excl; d_cur[i] = excl; }
        __syncthreads();
        if (tid == 0) carry += wsum[31];
        __syncthreads();
    }
    if (threadIdx.x == 0) d_off[n] = carry;
}

__global__ void k_fill(const int* __restrict__ src, const int* __restrict__ dst, int e) {
    int i = blockIdx.x * blockDim.x + threadIdx.x;
    if (i < e) {
        int d = dst[i];
        int p = atomicAdd(&d_cur[d], 1);
        d_srcs[p] = src[i];
    }
}

// ---------------- generic small GEMM: out[n,DOUT] = act((in[n,K] @ W[DOUT,K]^T + bias) * scale) --------
template <int K, int DOUT, bool BIAS, bool RELU, bool SCALE>
__global__ __launch_bounds__(256) void k_gemm(const float* __restrict__ in,
                                              const float* __restrict__ W,
                                              const float* __restrict__ bias,
                                              float* __restrict__ out, int n) {
    const int NPB = 2048 / DOUT;      // nodes per block (threads=256, 8 outputs/thread)
    const int XSTR = K + 4;           // padded x stride (bank-conflict break)
    extern __shared__ float sm[];
    float* sWt = sm;                  // [K][DOUT] transposed weights
    float* sX  = sm + K * DOUT;       // [NPB][XSTR]

    for (int idx = threadIdx.x; idx < K * DOUT; idx += 256) {
        int k = idx / DOUT, o = idx % DOUT;
        sWt[idx] = W[o * K + k];
    }
    int base = blockIdx.x * NPB;
    for (int idx = threadIdx.x; idx < NPB * K; idx += 256) {
        int nn = idx / K, k = idx % K;
        sX[nn * XSTR + k] = (base + nn < n) ? in[(size_t)(base + nn) * K + k] : 0.f;
    }
    __syncthreads();

    const int OG = DOUT / 8;
    int node = threadIdx.x / OG;
    int o0 = (threadIdx.x % OG) * 8;
    if (base + node >= n) return;

    float acc[8];
    #pragma unroll
    for (int j = 0; j < 8; j++) acc[j] = BIAS ? bias[o0 + j] : 0.f;

    const float* xr = sX + node * XSTR;
    #pragma unroll 4
    for (int k = 0; k < K; k++) {
        float xv = xr[k];
        float4 w0 = *(const float4*)(sWt + k * DOUT + o0);
        float4 w1 = *(const float4*)(sWt + k * DOUT + o0 + 4);
        acc[0] += xv * w0.x; acc[1] += xv * w0.y; acc[2] += xv * w0.z; acc[3] += xv * w0.w;
        acc[4] += xv * w1.x; acc[5] += xv * w1.y; acc[6] += xv * w1.z; acc[7] += xv * w1.w;
    }
    float s = SCALE ? d_dinv[base + node] : 1.f;
    float r[8];
    #pragma unroll
    for (int j = 0; j < 8; j++) {
        float v = acc[j] * s;
        r[j] = RELU ? fmaxf(v, 0.f) : v;
    }
    float* op = out + (size_t)(base + node) * DOUT + o0;
    *(float4*)(op)     = make_float4(r[0], r[1], r[2], r[3]);
    *(float4*)(op + 4) = make_float4(r[4], r[5], r[6], r[7]);
}

// ---------------- GCN aggregation: out_i = relu(dinv_i*(sum_in hs_j + hs_i) + b) -----------
// hs = (h @ W^T) * dinv (precomputed). One warp per node, lane owns 4 floats of the 128-row.
__global__ __launch_bounds__(256) void k_agg(const float* __restrict__ hs,
                                             const float* __restrict__ bias,
                                             float* __restrict__ out, int n) {
    int w = (blockIdx.x * blockDim.x + threadIdx.x) >> 5;
    int lane = threadIdx.x & 31;
    if (w >= n) return;
    int c = lane * 4;
    float4 acc = *(const float4*)(hs + (size_t)w * 128 + c);   // self term
    int j0 = d_off[w], j1 = d_off[w + 1];
    int j = j0;
    for (; j + 1 < j1; j += 2) {
        int s0 = d_srcs[j], s1 = d_srcs[j + 1];
        float4 v0 = *(const float4*)(hs + (size_t)s0 * 128 + c);
        float4 v1 = *(const float4*)(hs + (size_t)s1 * 128 + c);
        acc.x += v0.x + v1.x; acc.y += v0.y + v1.y;
        acc.z += v0.z + v1.z; acc.w += v0.w + v1.w;
    }
    if (j < j1) {
        int s0 = d_srcs[j];
        float4 v0 = *(const float4*)(hs + (size_t)s0 * 128 + c);
        acc.x += v0.x; acc.y += v0.y; acc.z += v0.z; acc.w += v0.w;
    }
    float dv = d_dinv[w];
    float4 b = *(const float4*)(bias + c);
    float4 o;
    o.x = fmaxf(acc.x * dv + b.x, 0.f);
    o.y = fmaxf(acc.y * dv + b.y, 0.f);
    o.z = fmaxf(acc.z * dv + b.z, 0.f);
    o.w = fmaxf(acc.w * dv + b.w, 0.f);
    *(float4*)(out + (size_t)w * 128 + c) = o;
}

// ---------------- bond energy over edges (8 threads/edge) ----------------
__global__ __launch_bounds__(256) void k_bond(const int* __restrict__ src,
                                              const int* __restrict__ dst,
                                              const float* __restrict__ pos,
                                              const float* __restrict__ w2,
                                              const float* __restrict__ b2p, int e) {
    __shared__ double sred[256];
    int tid = threadIdx.x;
    int eid = blockIdx.x * 32 + (tid >> 3);
    int sub = tid & 7;
    int eidc = eid < e ? eid : e - 1;
    int s = src[eidc], d = dst[eidc];
    const float* gs = d_g + (size_t)s * 64 + sub * 8;
    const float* gd = d_g + (size_t)d * 64 + sub * 8;
    float4 a0 = *(const float4*)(gs), a1 = *(const float4*)(gs + 4);
    float4 b0 = *(const float4*)(gd), b1 = *(const float4*)(gd + 4);
    const float* w = w2 + sub * 8;
    float p = 0.f;
    p += fmaxf(0.5f * (a0.x + b0.x), 0.f) * w[0];
    p += fmaxf(0.5f * (a0.y + b0.y), 0.f) * w[1];
    p += fmaxf(0.5f * (a0.z + b0.z), 0.f) * w[2];
    p += fmaxf(0.5f * (a0.w + b0.w), 0.f) * w[3];
    p += fmaxf(0.5f * (a1.x + b1.x), 0.f) * w[4];
    p += fmaxf(0.5f * (a1.y + b1.y), 0.f) * w[5];
    p += fmaxf(0.5f * (a1.z + b1.z), 0.f) * w[6];
    p += fmaxf(0.5f * (a1.w + b1.w), 0.f) * w[7];
    p += __shfl_down_sync(0xffffffffu, p, 4, 8);
    p += __shfl_down_sync(0xffffffffu, p, 2, 8);
    p += __shfl_down_sync(0xffffffffu, p, 1, 8);
    float term = 0.f;
    if (sub == 0 && eid < e) {
        float dx = pos[d * 3 + 0] - pos[s * 3 + 0];
        float dy = pos[d * 3 + 1] - pos[s * 3 + 1];
        float dz = pos[d * 3 + 2] - pos[s * 3 + 2];
        float L = sqrtf(dx * dx + dy * dy + dz * dz);
        float t = L - 1.5f;
        term = p + b2p[0] + 1000.f * t * t;
    }
    sred[tid] = (double)term;
    __syncthreads();
    #pragma unroll
    for (int st = 128; st > 0; st >>= 1) {
        if (tid < st) sred[tid] += sred[tid + st];
        __syncthreads();
    }
    if (tid == 0) d_pbond[blockIdx.x] = sred[0];
}

// ---------------- tm final layer (warp per node) ----------------
__global__ __launch_bounds__(256) void k_tm(const float* __restrict__ w3h, const float* __restrict__ b3h,
                                            const float* __restrict__ w3e, const float* __restrict__ b3e,
                                            int n) {
    __shared__ double sred[256];
    int w = (blockIdx.x * 256 + threadIdx.x) >> 5;
    int lane = threadIdx.x & 31;
    int wn = w < n ? w : n - 1;
    float ph = d_t2h[(size_t)wn * 32 + lane] * w3h[lane];
    float pe = d_t2e[(size_t)wn * 32 + lane] * w3e[lane];
    #pragma unroll
    for (int st = 16; st > 0; st >>= 1) {
        ph += __shfl_down_sync(0xffffffffu, ph, st);
        pe += __shfl_down_sync(0xffffffffu, pe, st);
    }
    float v = 0.f;
    if (lane == 0 && w < n) {
        float sh = 1.f / (1.f + expf(-(ph + b3h[0])));
        float se = 1.f / (1.f + expf(-(pe + b3e[0])));
        v = 0.5f * (sh + se);
    }
    sred[threadIdx.x] = (double)v;
    __syncthreads();
    #pragma unroll
    for (int st = 128; st > 0; st >>= 1) {
        if (threadIdx.x < st) sred[threadIdx.x] += sred[threadIdx.x + st];
        __syncthreads();
    }
    if (threadIdx.x == 0) d_ptm[blockIdx.x] = sred[0];
}

// ---------------- final scalar assembly ----------------
__global__ void k_final(float* __restrict__ out, int nb_bond, int nb_tm, int n) {
    __shared__ double sr[256];
    int tid = threadIdx.x;
    double s = 0.0;
    for (int i = tid; i < nb_bond; i += 256) s += d_pbond[i];
    sr[tid] = s;
    __syncthreads();
    for (int st = 128; st > 0; st >>= 1) { if (tid < st) sr[tid] += sr[tid + st]; __syncthreads(); }
    double ebond = sr[0];
    __syncthreads();
    s = 0.0;
    for (int i = tid; i < nb_tm; i += 256) s += d_ptm[i];
    sr[tid] = s;
    __syncthreads();
    for (int st = 128; st > 0; st >>= 1) { if (tid < st) sr[tid] += sr[tid + st]; __syncthreads(); }
    if (tid == 0) {
        double tm = sr[0] / (double)n;
        double et = ebond + 3.0;
        if (tm < 0.5) et += (1.0 - tm) * 10.0;
        out[0] = (float)ebond;
        out[1] = 1.0f; out[2] = 1.0f; out[3] = 1.0f;
        out[4] = (float)et;
        out[5] = (float)tm;
    }
}

// ---------------- host launcher ----------------
extern "C" void kernel_launch(void* const* d_in, const int* in_sizes, int n_in,
                              void* d_out, int out_size) {
    const float* x     = (const float*)d_in[0];
    const int*   ei    = (const int*)  d_in[1];
    const float* pos   = (const float*)d_in[2];
    /* d_in[3] = batch (unused) */
    const float* emb_w = (const float*)d_in[4];
    const float* emb_b = (const float*)d_in[5];
    const float* c1_w  = (const float*)d_in[6];
    const float* c1_b  = (const float*)d_in[7];
    const float* c2_w  = (const float*)d_in[8];
    const float* c2_b  = (const float*)d_in[9];
    const float* bw1   = (const float*)d_in[10];
    const float* bb1   = (const float*)d_in[11];
    const float* bw2   = (const float*)d_in[12];
    const float* bb2   = (const float*)d_in[13];
    const float* hw1   = (const float*)d_in[14];
    const float* hb1   = (const float*)d_in[15];
    const float* hw2   = (const float*)d_in[16];
    const float* hb2   = (const float*)d_in[17];
    const float* hw3   = (const float*)d_in[18];
    const float* hb3   = (const float*)d_in[19];
    const float* ew1   = (const float*)d_in[20];
    const float* eb1   = (const float*)d_in[21];
    const float* ew2   = (const float*)d_in[22];
    const float* eb2   = (const float*)d_in[23];
    const float* ew3   = (const float*)d_in[24];
    const float* eb3   = (const float*)d_in[25];

    int n = in_sizes[0] / 128;
    int e = in_sizes[1] / 2;
    const int* src = ei;
    const int* dst = ei + e;
    float* out = (float*)d_out;

    // dynamic smem sizes per instantiation
    const int SM_A = (128 * 64 + 32 * 132) * 4;   // K=128,DOUT=64  -> 49664
    const int SM_B = (64 * 128 + 16 * 68) * 4;    // K=64, DOUT=128 -> 37120
    const int SM_C = (128 * 128 + 16 * 132) * 4;  // K=128,DOUT=128 -> 73984
    const int SM_E = (64 * 32 + 64 * 68) * 4;     // K=64, DOUT=32  -> 25600

    cudaFuncSetAttribute((const void*)k_gemm<128, 64, true, true, false>,
                         cudaFuncAttributeMaxDynamicSharedMemorySize, SM_A);
    cudaFuncSetAttribute((const void*)k_gemm<128, 64, true, false, false>,
                         cudaFuncAttributeMaxDynamicSharedMemorySize, SM_A);
    cudaFuncSetAttribute((const void*)k_gemm<64, 128, false, false, true>,
                         cudaFuncAttributeMaxDynamicSharedMemorySize, SM_B);
    cudaFuncSetAttribute((const void*)k_gemm<128, 128, false, false, true>,
                         cudaFuncAttributeMaxDynamicSharedMemorySize, SM_C);
    cudaFuncSetAttribute((const void*)k_gemm<64, 32, true, true, false>,
                         cudaFuncAttributeMaxDynamicSharedMemorySize, SM_E);

    // ---- CSR build + degrees ----
    k_zero_deg<<<(n + 255) / 256, 256>>>(n);
    k_count<<<(e + 255) / 256, 256>>>(dst, e);
    k_dinv<<<(n + 255) / 256, 256>>>(n);
    k_scan<<<1, 1024>>>(n);
    k_fill<<<(e + 255) / 256, 256>>>(src, dst, e);

    // ---- embedding: h0 = relu(x @ emb_w^T + emb_b) ----
    k_gemm<128, 64, true, true, false><<<(n + 31) / 32, 256, SM_A>>>(x, emb_w, emb_b, d_h0, n);

    // ---- GCN layer 1 ----
    k_gemm<64, 128, false, false, true><<<(n + 15) / 16, 256, SM_B>>>(d_h0, c1_w, nullptr, d_lin, n);
    k_agg<<<(n + 7) / 8, 256>>>(d_lin, c1_b, d_h, n);

    // ---- GCN layer 2 ----
    k_gemm<128, 128, false, false, true><<<(n + 15) / 16, 256, SM_C>>>(d_h, c2_w, nullptr, d_lin, n);
    k_agg<<<(n + 7) / 8, 256>>>(d_lin, c2_b, d_h, n);

    // ---- bond projection: g = h @ bond_w1^T + bond_b1 (bias folds: 0.5(g_s+g_d) = ef@W1^T + b1) ----
    k_gemm<128, 64, true, false, false><<<(n + 31) / 32, 256, SM_A>>>(d_h, bw1, bb1, d_g, n);

    // ---- tm MLPs (layers 1-2 as GEMMs) ----
    k_gemm<128, 64, true, true, false><<<(n + 31) / 32, 256, SM_A>>>(d_h, hw1, hb1, d_t1, n);
    k_gemm<64, 32, true, true, false><<<(n + 63) / 64, 256, SM_E>>>(d_t1, hw2, hb2, d_t2h, n);
    k_gemm<128, 64, true, true, false><<<(n + 31) / 32, 256, SM_A>>>(d_h, ew1, eb1, d_t1, n);
    k_gemm<64, 32, true, true, false><<<(n + 63) / 64, 256, SM_E>>>(d_t1, ew2, eb2, d_t2e, n);

    // ---- reductions ----
    int nb_tm = (n + 7) / 8;
    k_tm<<<nb_tm, 256>>>(hw3, hb3, ew3, eb3, n);
    int nb_bond = (e + 31) / 32;
    k_bond<<<nb_bond, 256>>>(src, dst, pos, bw2, bb2, e);
    k_final<<<1, 256>>>(out, nb_bond, nb_tm, n);
}

// round 3
// speedup vs baseline: 1.0501x; 1.0501x over previous
#include <cuda_runtime.h>
#include <math.h>

#define NMAX 50000
#define EMAX 1600000
#define BOND_BLKS ((EMAX + 31) / 32)
#define TM_BLKS ((NMAX + 7) / 8)

// ---------------- scratch (device globals; no allocation allowed) ----------------
__device__ float d_h0 [(size_t)NMAX * 64];
__device__ float d_lin[(size_t)NMAX * 128];
__device__ float d_h  [(size_t)NMAX * 128];
__device__ float d_g  [(size_t)NMAX * 64];
__device__ float d_t1 [(size_t)NMAX * 64];
__device__ float d_t2h[(size_t)NMAX * 32];
__device__ float d_t2e[(size_t)NMAX * 32];
__device__ float d_dinv[NMAX];
__device__ int   d_deg[NMAX];
__device__ int   d_off[NMAX + 1];
__device__ int   d_cur[NMAX];
__device__ int   d_srcs[EMAX];
__device__ double d_pbond[BOND_BLKS];
__device__ double d_ptm[TM_BLKS];

// ---------------- degree / CSR build ----------------
__global__ void k_zero_deg(int n) {
    int i = blockIdx.x * blockDim.x + threadIdx.x;
    if (i < n) d_deg[i] = 0;
}

__global__ void k_count(const int* __restrict__ dst, int e) {
    int i = blockIdx.x * blockDim.x + threadIdx.x;
    if (i < e) atomicAdd(&d_deg[dst[i]], 1);
}

// single-block scan over deg -> exclusive offsets (+ cursor copy + dinv), 4 elems/thread
__global__ void k_scan(int n) {
    __shared__ int wsum[32];
    __shared__ int carry;
    int tid = threadIdx.x, lane = tid & 31, wid = tid >> 5;
    if (tid == 0) carry = 0;
    __syncthreads();
    for (int base = 0; base < n; base += 4096) {
        int i0 = base + tid * 4;
        int v0 = (i0 + 0 < n) ? d_deg[i0 + 0] : 0;
        int v1 = (i0 + 1 < n) ? d_deg[i0 + 1] : 0;
        int v2 = (i0 + 2 < n) ? d_deg[i0 + 2] : 0;
        int v3 = (i0 + 3 < n) ? d_deg[i0 + 3] : 0;
        int tsum = v0 + v1 + v2 + v3;
        int sc = tsum;
        #pragma unroll
        for (int st = 1; st < 32; st <<= 1) {
            int t = __shfl_up_sync(0xffffffffu, sc, st);
            if (lane >= st) sc += t;
        }
        if (lane == 31) wsum[wid] = sc;
        __syncthreads();
        if (wid == 0) {
            int s = wsum[lane];
            #pragma unroll
            for (int st = 1; st < 32; st <<= 1) {
                int t = __shfl_up_sync(0xffffffffu, s, st);
                if (lane >= st) s += t;
            }
            wsum[lane] = s;
        }
        __syncthreads();
        int excl = carry + (wid ? wsum[wid - 1] : 0) + sc - tsum;
        int ev[4];
        ev[0] = excl;
        ev[1] = ev[0] + v0;
        ev[2] = ev[1] + v1;
        ev[3] = ev[2] + v2;
        int dv[4] = {v0, v1, v2, v3};
        #pragma unroll
        for (int j = 0; j < 4; j++) {
            int i = i0 + j;
            if (i < n) {
                d_off[i] = ev[j];
                d_cur[i] = ev[j];
                d_dinv[i] = rsqrtf((float)(dv[j] + 1));   // +1: self loop
            }
        }
        __syncthreads();
        if (tid == 0) carry += wsum[31];
        __syncthreads();
    }
    if (threadIdx.x == 0) d_off[n] = carry;
}

__global__ void k_fill(const int* __restrict__ src, const int* __restrict__ dst, int e) {
    int i = blockIdx.x * blockDim.x + threadIdx.x;
    if (i < e) {
        int d = dst[i];
        int p = atomicAdd(&d_cur[d], 1);
        d_srcs[p] = src[i];
    }
}

// ---------------- generic small GEMM: out[n,DOUT] = act((in[n,K] @ W[DOUT,K]^T + bias) * scale) --------
template <int K, int DOUT, bool BIAS, bool RELU, bool SCALE>
__global__ __launch_bounds__(256) void k_gemm(const float* __restrict__ in,
                                              const float* __restrict__ W,
                                              const float* __restrict__ bias,
                                              float* __restrict__ out, int n) {
    const int NPB = 2048 / DOUT;      // nodes per block (threads=256, 8 outputs/thread)
    const int XSTR = K + 4;           // padded x stride (bank-conflict break)
    extern __shared__ float sm[];
    float* sWt = sm;                  // [K][DOUT] transposed weights
    float* sX  = sm + K * DOUT;       // [NPB][XSTR]

    for (int idx = threadIdx.x; idx < K * DOUT; idx += 256) {
        int k = idx / DOUT, o = idx % DOUT;
        sWt[idx] = W[o * K + k];
    }
    int base = blockIdx.x * NPB;
    for (int idx = threadIdx.x; idx < NPB * K; idx += 256) {
        int nn = idx / K, k = idx % K;
        sX[nn * XSTR + k] = (base + nn < n) ? in[(size_t)(base + nn) * K + k] : 0.f;
    }
    __syncthreads();

    const int OG = DOUT / 8;
    int node = threadIdx.x / OG;
    int o0 = (threadIdx.x % OG) * 8;
    if (base + node >= n) return;

    float acc[8];
    #pragma unroll
    for (int j = 0; j < 8; j++) acc[j] = BIAS ? bias[o0 + j] : 0.f;

    const float* xr = sX + node * XSTR;
    #pragma unroll 4
    for (int k = 0; k < K; k++) {
        float xv = xr[k];
        float4 w0 = *(const float4*)(sWt + k * DOUT + o0);
        float4 w1 = *(const float4*)(sWt + k * DOUT + o0 + 4);
        acc[0] += xv * w0.x; acc[1] += xv * w0.y; acc[2] += xv * w0.z; acc[3] += xv * w0.w;
        acc[4] += xv * w1.x; acc[5] += xv * w1.y; acc[6] += xv * w1.z; acc[7] += xv * w1.w;
    }
    float s = SCALE ? d_dinv[base + node] : 1.f;
    float r[8];
    #pragma unroll
    for (int j = 0; j < 8; j++) {
        float v = acc[j] * s;
        r[j] = RELU ? fmaxf(v, 0.f) : v;
    }
    float* op = out + (size_t)(base + node) * DOUT + o0;
    *(float4*)(op)     = make_float4(r[0], r[1], r[2], r[3]);
    *(float4*)(op + 4) = make_float4(r[4], r[5], r[6], r[7]);
}

// ---------------- GCN aggregation: out_i = relu(dinv_i*(sum_in hs_j + hs_i) + b) -----------
// hs = (h @ W^T) * dinv (precomputed). One warp per node, lane owns 4 floats of the 128-row.
__global__ __launch_bounds__(512) void k_agg(const float* __restrict__ hs,
                                             const float* __restrict__ bias,
                                             float* __restrict__ out, int n) {
    int w = (blockIdx.x * blockDim.x + threadIdx.x) >> 5;
    int lane = threadIdx.x & 31;
    if (w >= n) return;
    int c = lane * 4;
    float4 acc = *(const float4*)(hs + (size_t)w * 128 + c);   // self term
    int j0 = d_off[w], j1 = d_off[w + 1];
    int j = j0;
    for (; j + 3 < j1; j += 4) {
        int s0 = d_srcs[j], s1 = d_srcs[j + 1], s2 = d_srcs[j + 2], s3 = d_srcs[j + 3];
        float4 v0 = *(const float4*)(hs + (size_t)s0 * 128 + c);
        float4 v1 = *(const float4*)(hs + (size_t)s1 * 128 + c);
        float4 v2 = *(const float4*)(hs + (size_t)s2 * 128 + c);
        float4 v3 = *(const float4*)(hs + (size_t)s3 * 128 + c);
        acc.x += (v0.x + v1.x) + (v2.x + v3.x);
        acc.y += (v0.y + v1.y) + (v2.y + v3.y);
        acc.z += (v0.z + v1.z) + (v2.z + v3.z);
        acc.w += (v0.w + v1.w) + (v2.w + v3.w);
    }
    for (; j < j1; j++) {
        int s0 = d_srcs[j];
        float4 v0 = *(const float4*)(hs + (size_t)s0 * 128 + c);
        acc.x += v0.x; acc.y += v0.y; acc.z += v0.z; acc.w += v0.w;
    }
    float dv = d_dinv[w];
    float4 b = *(const float4*)(bias + c);
    float4 o;
    o.x = fmaxf(acc.x * dv + b.x, 0.f);
    o.y = fmaxf(acc.y * dv + b.y, 0.f);
    o.z = fmaxf(acc.z * dv + b.z, 0.f);
    o.w = fmaxf(acc.w * dv + b.w, 0.f);
    *(float4*)(out + (size_t)w * 128 + c) = o;
}

// ---------------- bond energy over edges (8 threads/edge, float shuffle reduction) ----------------
__global__ __launch_bounds__(256) void k_bond(const int* __restrict__ src,
                                              const int* __restrict__ dst,
                                              const float* __restrict__ pos,
                                              const float* __restrict__ w2,
                                              const float* __restrict__ b2p, int e) {
    __shared__ float wpart[8];
    int tid = threadIdx.x;
    int lane = tid & 31, wid = tid >> 5;
    int eid = blockIdx.x * 32 + (tid >> 3);
    int sub = tid & 7;
    int eidc = eid < e ? eid : e - 1;
    int s = src[eidc], d = dst[eidc];
    const float* gs = d_g + (size_t)s * 64 + sub * 8;
    const float* gd = d_g + (size_t)d * 64 + sub * 8;
    float4 a0 = *(const float4*)(gs), a1 = *(const float4*)(gs + 4);
    float4 b0 = *(const float4*)(gd), b1 = *(const float4*)(gd + 4);
    const float* w = w2 + sub * 8;
    float p = 0.f;
    p += fmaxf(0.5f * (a0.x + b0.x), 0.f) * w[0];
    p += fmaxf(0.5f * (a0.y + b0.y), 0.f) * w[1];
    p += fmaxf(0.5f * (a0.z + b0.z), 0.f) * w[2];
    p += fmaxf(0.5f * (a0.w + b0.w), 0.f) * w[3];
    p += fmaxf(0.5f * (a1.x + b1.x), 0.f) * w[4];
    p += fmaxf(0.5f * (a1.y + b1.y), 0.f) * w[5];
    p += fmaxf(0.5f * (a1.z + b1.z), 0.f) * w[6];
    p += fmaxf(0.5f * (a1.w + b1.w), 0.f) * w[7];
    p += __shfl_down_sync(0xffffffffu, p, 4, 8);
    p += __shfl_down_sync(0xffffffffu, p, 2, 8);
    p += __shfl_down_sync(0xffffffffu, p, 1, 8);
    float term = 0.f;
    if (sub == 0 && eid < e) {
        float dx = pos[d * 3 + 0] - pos[s * 3 + 0];
        float dy = pos[d * 3 + 1] - pos[s * 3 + 1];
        float dz = pos[d * 3 + 2] - pos[s * 3 + 2];
        float L = sqrtf(dx * dx + dy * dy + dz * dz);
        float t = L - 1.5f;
        term = p + b2p[0] + 1000.f * t * t;
    }
    // term nonzero only on lanes 0,8,16,24 -> two shuffle steps to lane 0
    term += __shfl_down_sync(0xffffffffu, term, 16);
    term += __shfl_down_sync(0xffffffffu, term, 8);
    if (lane == 0) wpart[wid] = term;
    __syncthreads();
    if (tid < 8) {
        float v = wpart[tid];
        v += __shfl_down_sync(0x000000ffu, v, 4, 8);
        v += __shfl_down_sync(0x000000ffu, v, 2, 8);
        v += __shfl_down_sync(0x000000ffu, v, 1, 8);
        if (tid == 0) d_pbond[blockIdx.x] = (double)v;
    }
}

// ---------------- tm final layer (warp per node, float shuffle reduction) ----------------
__global__ __launch_bounds__(256) void k_tm(const float* __restrict__ w3h, const float* __restrict__ b3h,
                                            const float* __restrict__ w3e, const float* __restrict__ b3e,
                                            int n) {
    __shared__ float wpart[8];
    int tid = threadIdx.x;
    int w = (blockIdx.x * 256 + tid) >> 5;
    int lane = tid & 31, wid = tid >> 5;
    int wn = w < n ? w : n - 1;
    float ph = d_t2h[(size_t)wn * 32 + lane] * w3h[lane];
    float pe = d_t2e[(size_t)wn * 32 + lane] * w3e[lane];
    #pragma unroll
    for (int st = 16; st > 0; st >>= 1) {
        ph += __shfl_down_sync(0xffffffffu, ph, st);
        pe += __shfl_down_sync(0xffffffffu, pe, st);
    }
    float v = 0.f;
    if (lane == 0 && w < n) {
        float sh = 1.f / (1.f + expf(-(ph + b3h[0])));
        float se = 1.f / (1.f + expf(-(pe + b3e[0])));
        v = 0.5f * (sh + se);
    }
    if (lane == 0) wpart[wid] = v;
    __syncthreads();
    if (tid < 8) {
        float s = wpart[tid];
        s += __shfl_down_sync(0x000000ffu, s, 4, 8);
        s += __shfl_down_sync(0x000000ffu, s, 2, 8);
        s += __shfl_down_sync(0x000000ffu, s, 1, 8);
        if (tid == 0) d_ptm[blockIdx.x] = (double)s;
    }
}

// ---------------- final scalar assembly ----------------
__global__ void k_final(float* __restrict__ out, int nb_bond, int nb_tm, int n) {
    __shared__ double sr[256];
    int tid = threadIdx.x;
    double s = 0.0;
    for (int i = tid; i < nb_bond; i += 256) s += d_pbond[i];
    sr[tid] = s;
    __syncthreads();
    for (int st = 128; st > 0; st >>= 1) { if (tid < st) sr[tid] += sr[tid + st]; __syncthreads(); }
    double ebond = sr[0];
    __syncthreads();
    s = 0.0;
    for (int i = tid; i < nb_tm; i += 256) s += d_ptm[i];
    sr[tid] = s;
    __syncthreads();
    for (int st = 128; st > 0; st >>= 1) { if (tid < st) sr[tid] += sr[tid + st]; __syncthreads(); }
    if (tid == 0) {
        double tm = sr[0] / (double)n;
        double et = ebond + 3.0;
        if (tm < 0.5) et += (1.0 - tm) * 10.0;
        out[0] = (float)ebond;
        out[1] = 1.0f; out[2] = 1.0f; out[3] = 1.0f;
        out[4] = (float)et;
        out[5] = (float)tm;
    }
}

// ---------------- host launcher ----------------
extern "C" void kernel_launch(void* const* d_in, const int* in_sizes, int n_in,
                              void* d_out, int out_size) {
    const float* x     = (const float*)d_in[0];
    const int*   ei    = (const int*)  d_in[1];
    const float* pos   = (const float*)d_in[2];
    /* d_in[3] = batch (unused) */
    const float* emb_w = (const float*)d_in[4];
    const float* emb_b = (const float*)d_in[5];
    const float* c1_w  = (const float*)d_in[6];
    const float* c1_b  = (const float*)d_in[7];
    const float* c2_w  = (const float*)d_in[8];
    const float* c2_b  = (const float*)d_in[9];
    const float* bw1   = (const float*)d_in[10];
    const float* bb1   = (const float*)d_in[11];
    const float* bw2   = (const float*)d_in[12];
    const float* bb2   = (const float*)d_in[13];
    const float* hw1   = (const float*)d_in[14];
    const float* hb1   = (const float*)d_in[15];
    const float* hw2   = (const float*)d_in[16];
    const float* hb2   = (const float*)d_in[17];
    const float* hw3   = (const float*)d_in[18];
    const float* hb3   = (const float*)d_in[19];
    const float* ew1   = (const float*)d_in[20];
    const float* eb1   = (const float*)d_in[21];
    const float* ew2   = (const float*)d_in[22];
    const float* eb2   = (const float*)d_in[23];
    const float* ew3   = (const float*)d_in[24];
    const float* eb3   = (const float*)d_in[25];

    int n = in_sizes[0] / 128;
    int e = in_sizes[1] / 2;
    const int* src = ei;
    const int* dst = ei + e;
    float* out = (float*)d_out;

    // dynamic smem sizes per instantiation
    const int SM_A = (128 * 64 + 32 * 132) * 4;   // K=128,DOUT=64  -> 49664
    const int SM_B = (64 * 128 + 16 * 68) * 4;    // K=64, DOUT=128 -> 37120
    const int SM_C = (128 * 128 + 16 * 132) * 4;  // K=128,DOUT=128 -> 73984
    const int SM_E = (64 * 32 + 64 * 68) * 4;     // K=64, DOUT=32  -> 25600

    cudaFuncSetAttribute((const void*)k_gemm<128, 64, true, true, false>,
                         cudaFuncAttributeMaxDynamicSharedMemorySize, SM_A);
    cudaFuncSetAttribute((const void*)k_gemm<128, 64, true, false, false>,
                         cudaFuncAttributeMaxDynamicSharedMemorySize, SM_A);
    cudaFuncSetAttribute((const void*)k_gemm<64, 128, false, false, true>,
                         cudaFuncAttributeMaxDynamicSharedMemorySize, SM_B);
    cudaFuncSetAttribute((const void*)k_gemm<128, 128, false, false, true>,
                         cudaFuncAttributeMaxDynamicSharedMemorySize, SM_C);
    cudaFuncSetAttribute((const void*)k_gemm<64, 32, true, true, false>,
                         cudaFuncAttributeMaxDynamicSharedMemorySize, SM_E);

    // ---- launch #1-#3: degrees + scan(+dinv) ----
    k_zero_deg<<<(n + 255) / 256, 256>>>(n);
    k_count<<<(e + 255) / 256, 256>>>(dst, e);
    k_scan<<<1, 1024>>>(n);

    // ---- launch #4 (profiled by ncu): embedding GEMM ----
    k_gemm<128, 64, true, true, false><<<(n + 31) / 32, 256, SM_A>>>(x, emb_w, emb_b, d_h0, n);

    // ---- CSR fill ----
    k_fill<<<(e + 255) / 256, 256>>>(src, dst, e);

    // ---- GCN layer 1 ----
    k_gemm<64, 128, false, false, true><<<(n + 15) / 16, 256, SM_B>>>(d_h0, c1_w, nullptr, d_lin, n);
    k_agg<<<(n + 15) / 16, 512>>>(d_lin, c1_b, d_h, n);

    // ---- GCN layer 2 ----
    k_gemm<128, 128, false, false, true><<<(n + 15) / 16, 256, SM_C>>>(d_h, c2_w, nullptr, d_lin, n);
    k_agg<<<(n + 15) / 16, 512>>>(d_lin, c2_b, d_h, n);

    // ---- bond projection: g = h @ bond_w1^T + bond_b1 ----
    k_gemm<128, 64, true, false, false><<<(n + 31) / 32, 256, SM_A>>>(d_h, bw1, bb1, d_g, n);

    // ---- tm MLPs (layers 1-2 as GEMMs) ----
    k_gemm<128, 64, true, true, false><<<(n + 31) / 32, 256, SM_A>>>(d_h, hw1, hb1, d_t1, n);
    k_gemm<64, 32, true, true, false><<<(n + 63) / 64, 256, SM_E>>>(d_t1, hw2, hb2, d_t2h, n);
    k_gemm<128, 64, true, true, false><<<(n + 31) / 32, 256, SM_A>>>(d_h, ew1, eb1, d_t1, n);
    k_gemm<64, 32, true, true, false><<<(n + 63) / 64, 256, SM_E>>>(d_t1, ew2, eb2, d_t2e, n);

    // ---- reductions ----
    int nb_tm = (n + 7) / 8;
    k_tm<<<nb_tm, 256>>>(hw3, hb3, ew3, eb3, n);
    int nb_bond = (e + 31) / 32;
    k_bond<<<nb_bond, 256>>>(src, dst, pos, bw2, bb2, e);
    k_final<<<1, 256>>>(out, nb_bond, nb_tm, n);
}

// round 5
// speedup vs baseline: 1.3452x; 1.2810x over previous
#include <cuda_runtime.h>
#include <math.h>

#define NMAX 50000
#define EMAX 1600000
#define BOND_BLKS 1184
#define TM_BLKS ((NMAX + 7) / 8)

// ---------------- scratch (device globals; no allocation allowed) ----------------
__device__ float d_h0 [(size_t)NMAX * 64];   // emb output, pre-scaled by dinv
__device__ float d_a0 [(size_t)NMAX * 64];   // aggregated 64-dim
__device__ float d_lin[(size_t)NMAX * 128];  // layer1 out (scaled) / final features
__device__ float d_h  [(size_t)NMAX * 128];  // aggregated 128-dim
__device__ float d_g  [(size_t)NMAX * 64];
__device__ float d_t1 [(size_t)NMAX * 64];
__device__ float d_t2h[(size_t)NMAX * 32];
__device__ float d_t2e[(size_t)NMAX * 32];
__device__ float d_dinv[NMAX];
__device__ int   d_deg[NMAX];
__device__ int   d_off[NMAX + 1];
__device__ int   d_cur[NMAX];
__device__ int   d_srcs[EMAX];
__device__ double d_pbond[BOND_BLKS];
__device__ double d_ptm[TM_BLKS];

// ---------------- degree / CSR build ----------------
__global__ void k_zero_deg(int n) {
    int i = blockIdx.x * blockDim.x + threadIdx.x;
    if (i < n) d_deg[i] = 0;
}

__global__ void k_count(const int* __restrict__ dst, int e) {
    int i = blockIdx.x * blockDim.x + threadIdx.x;
    if (i < e) atomicAdd(&d_deg[dst[i]], 1);
}

// single-block scan over deg -> exclusive offsets (+ cursor copy + dinv), 4 elems/thread
__global__ void k_scan(int n) {
    __shared__ int wsum[32];
    __shared__ int carry;
    int tid = threadIdx.x, lane = tid & 31, wid = tid >> 5;
    if (tid == 0) carry = 0;
    __syncthreads();
    for (int base = 0; base < n; base += 4096) {
        int i0 = base + tid * 4;
        int v0 = (i0 + 0 < n) ? d_deg[i0 + 0] : 0;
        int v1 = (i0 + 1 < n) ? d_deg[i0 + 1] : 0;
        int v2 = (i0 + 2 < n) ? d_deg[i0 + 2] : 0;
        int v3 = (i0 + 3 < n) ? d_deg[i0 + 3] : 0;
        int tsum = v0 + v1 + v2 + v3;
        int sc = tsum;
        #pragma unroll
        for (int st = 1; st < 32; st <<= 1) {
            int t = __shfl_up_sync(0xffffffffu, sc, st);
            if (lane >= st) sc += t;
        }
        if (lane == 31) wsum[wid] = sc;
        __syncthreads();
        if (wid == 0) {
            int s = wsum[lane];
            #pragma unroll
            for (int st = 1; st < 32; st <<= 1) {
                int t = __shfl_up_sync(0xffffffffu, s, st);
                if (lane >= st) s += t;
            }
            wsum[lane] = s;
        }
        __syncthreads();
        int excl = carry + (wid ? wsum[wid - 1] : 0) + sc - tsum;
        int ev[4];
        ev[0] = excl;
        ev[1] = ev[0] + v0;
        ev[2] = ev[1] + v1;
        ev[3] = ev[2] + v2;
        int dv[4] = {v0, v1, v2, v3};
        #pragma unroll
        for (int j = 0; j < 4; j++) {
            int i = i0 + j;
            if (i < n) {
                d_off[i] = ev[j];
                d_cur[i] = ev[j];
                d_dinv[i] = rsqrtf((float)(dv[j] + 1));   // +1: self loop
            }
        }
        __syncthreads();
        if (tid == 0) carry += wsum[31];
        __syncthreads();
    }
    if (threadIdx.x == 0) d_off[n] = carry;
}

__global__ void k_fill(const int* __restrict__ src, const int* __restrict__ dst, int e) {
    int i = blockIdx.x * blockDim.x + threadIdx.x;
    if (i < e) {
        int d = dst[i];
        int p = atomicAdd(&d_cur[d], 1);
        d_srcs[p] = src[i];
    }
}

// ---------------- register-tiled GEMM ----------------
// out[n,DOUT] = act(in[n,K] @ W[DOUT,K]^T + bias) [* dinv]
// 256 threads, tile = NT nodes x DOUT outs, thread = 4 nodes x 8 outs.
// X staged transposed in smem [k][node] so one LDS.128 feeds 4 nodes.
template <int K, int DOUT, bool RELU, bool SCALE>
__global__ __launch_bounds__(256) void k_gemm(const float* __restrict__ in,
                                              const float* __restrict__ W,
                                              const float* __restrict__ bias,
                                              float* __restrict__ out, int n) {
    const int NT = 8192 / DOUT;       // nodes per block
    const int XS = NT + 4;            // padded node stride
    extern __shared__ float sm[];
    float* sW = sm;                   // [K][DOUT]
    float* sX = sm + K * DOUT;        // [K][XS]

    for (int idx = threadIdx.x; idx < K * DOUT; idx += 256) {
        int k = idx / DOUT, o = idx % DOUT;
        sW[idx] = W[o * K + k];
    }
    int base = blockIdx.x * NT;
    for (int idx = threadIdx.x; idx < NT * K; idx += 256) {
        int nn = idx / K, k = idx % K;   // coalesced over k
        sX[k * XS + nn] = (base + nn < n) ? in[(size_t)(base + nn) * K + k] : 0.f;
    }
    __syncthreads();

    const int OG = DOUT / 8;
    int o0 = (threadIdx.x % OG) * 8;
    int n0 = (threadIdx.x / OG) * 4;

    float acc[4][8];
    #pragma unroll
    for (int i = 0; i < 8; i++) {
        float b = bias[o0 + i];
        acc[0][i] = b; acc[1][i] = b; acc[2][i] = b; acc[3][i] = b;
    }

    #pragma unroll 4
    for (int k = 0; k < K; k++) {
        float4 xv = *(const float4*)(sX + k * XS + n0);
        float4 w0 = *(const float4*)(sW + k * DOUT + o0);
        float4 w1 = *(const float4*)(sW + k * DOUT + o0 + 4);
        float wr[8] = {w0.x, w0.y, w0.z, w0.w, w1.x, w1.y, w1.z, w1.w};
        float xr[4] = {xv.x, xv.y, xv.z, xv.w};
        #pragma unroll
        for (int j = 0; j < 4; j++)
            #pragma unroll
            for (int i = 0; i < 8; i++)
                acc[j][i] += xr[j] * wr[i];
    }

    #pragma unroll
    for (int j = 0; j < 4; j++) {
        int node = base + n0 + j;
        if (node >= n) break;
        float s = SCALE ? d_dinv[node] : 1.f;
        float r[8];
        #pragma unroll
        for (int i = 0; i < 8; i++) {
            float v = acc[j][i];
            if (RELU) v = fmaxf(v, 0.f);
            r[i] = v * s;
        }
        float* op = out + (size_t)node * DOUT + o0;
        *(float4*)(op)     = make_float4(r[0], r[1], r[2], r[3]);
        *(float4*)(op + 4) = make_float4(r[4], r[5], r[6], r[7]);
    }
}

// ---------------- GCN aggregation (pre-GEMM): a_i = dinv_i*(sum_in hs_j + hs_i) -----------
// hs rows pre-scaled by dinv_j. D=128: warp/node; D=64: half-warp/node.
template <int D>
__global__ __launch_bounds__(512) void k_agg(const float* __restrict__ hs,
                                             float* __restrict__ out, int n) {
    const int LPN = D / 4;            // lanes per node
    const int NPW = 32 / LPN;         // nodes per warp
    int gw = (blockIdx.x * blockDim.x + threadIdx.x) >> 5;
    int lane = threadIdx.x & 31;
    int node = gw * NPW + lane / LPN;
    if (node >= n) return;
    int c = (lane % LPN) * 4;
    float4 acc = *(const float4*)(hs + (size_t)node * D + c);   // self term
    int j0 = d_off[node], j1 = d_off[node + 1];
    int j = j0;
    for (; j + 3 < j1; j += 4) {
        int s0 = d_srcs[j], s1 = d_srcs[j + 1], s2 = d_srcs[j + 2], s3 = d_srcs[j + 3];
        float4 v0 = *(const float4*)(hs + (size_t)s0 * D + c);
        float4 v1 = *(const float4*)(hs + (size_t)s1 * D + c);
        float4 v2 = *(const float4*)(hs + (size_t)s2 * D + c);
        float4 v3 = *(const float4*)(hs + (size_t)s3 * D + c);
        acc.x += (v0.x + v1.x) + (v2.x + v3.x);
        acc.y += (v0.y + v1.y) + (v2.y + v3.y);
        acc.z += (v0.z + v1.z) + (v2.z + v3.z);
        acc.w += (v0.w + v1.w) + (v2.w + v3.w);
    }
    for (; j < j1; j++) {
        int s0 = d_srcs[j];
        float4 v0 = *(const float4*)(hs + (size_t)s0 * D + c);
        acc.x += v0.x; acc.y += v0.y; acc.z += v0.z; acc.w += v0.w;
    }
    float dv = d_dinv[node];
    float4 o;
    o.x = acc.x * dv; o.y = acc.y * dv; o.z = acc.z * dv; o.w = acc.w * dv;
    *(float4*)(out + (size_t)node * D + c) = o;
}

// ---------------- bond energy (8 threads/edge, grid-stride, w2 in regs) ----------------
__global__ __launch_bounds__(256) void k_bond(const int* __restrict__ src,
                                              const int* __restrict__ dst,
                                              const float* __restrict__ pos,
                                              const float* __restrict__ w2,
                                              const float* __restrict__ b2p,
                                              int e, int total_groups) {
    __shared__ float wpart[8];
    int tid = threadIdx.x;
    int sub = tid & 7;
    int lane = tid & 31, wid = tid >> 5;
    float wreg[8];
    #pragma unroll
    for (int j = 0; j < 8; j++) wreg[j] = w2[sub * 8 + j];
    float b2 = b2p[0];

    int g0 = (blockIdx.x * 256 + tid) >> 3;
    float accq = 0.f;
    int cnt = 0;
    for (int eid = g0; eid < e; eid += total_groups) {
        int s = src[eid], d = dst[eid];
        const float* gs = d_g + (size_t)s * 64 + sub * 8;
        const float* gd = d_g + (size_t)d * 64 + sub * 8;
        float4 a0 = *(const float4*)(gs), a1 = *(const float4*)(gs + 4);
        float4 b0 = *(const float4*)(gd), b1 = *(const float4*)(gd + 4);
        float p = 0.f;
        p += fmaxf(0.5f * (a0.x + b0.x), 0.f) * wreg[0];
        p += fmaxf(0.5f * (a0.y + b0.y), 0.f) * wreg[1];
        p += fmaxf(0.5f * (a0.z + b0.z), 0.f) * wreg[2];
        p += fmaxf(0.5f * (a0.w + b0.w), 0.f) * wreg[3];
        p += fmaxf(0.5f * (a1.x + b1.x), 0.f) * wreg[4];
        p += fmaxf(0.5f * (a1.y + b1.y), 0.f) * wreg[5];
        p += fmaxf(0.5f * (a1.z + b1.z), 0.f) * wreg[6];
        p += fmaxf(0.5f * (a1.w + b1.w), 0.f) * wreg[7];
        p += __shfl_down_sync(0xffffffffu, p, 4, 8);
        p += __shfl_down_sync(0xffffffffu, p, 2, 8);
        p += __shfl_down_sync(0xffffffffu, p, 1, 8);
        if (sub == 0) {
            float dx = pos[d * 3 + 0] - pos[s * 3 + 0];
            float dy = pos[d * 3 + 1] - pos[s * 3 + 1];
            float dz = pos[d * 3 + 2] - pos[s * 3 + 2];
            float L = sqrtf(dx * dx + dy * dy + dz * dz);
            float t = L - 1.5f;
            accq += p + 1000.f * t * t;
            cnt++;
        }
    }
    float v = accq + b2 * (float)cnt;   // nonzero only on sub==0 lanes
    #pragma unroll
    for (int st = 16; st > 0; st >>= 1) v += __shfl_down_sync(0xffffffffu, v, st);
    if (lane == 0) wpart[wid] = v;
    __syncthreads();
    if (tid < 8) {
        float s = wpart[tid];
        s += __shfl_down_sync(0x000000ffu, s, 4, 8);
        s += __shfl_down_sync(0x000000ffu, s, 2, 8);
        s += __shfl_down_sync(0x000000ffu, s, 1, 8);
        if (tid == 0) d_pbond[blockIdx.x] = (double)s;
    }
}

// ---------------- tm final layer (warp per node) ----------------
__global__ __launch_bounds__(256) void k_tm(const float* __restrict__ w3h, const float* __restrict__ b3h,
                                            const float* __restrict__ w3e, const float* __restrict__ b3e,
                                            int n) {
    __shared__ float wpart[8];
    int tid = threadIdx.x;
    int w = (blockIdx.x * 256 + tid) >> 5;
    int lane = tid & 31, wid = tid >> 5;
    int wn = w < n ? w : n - 1;
    float ph = d_t2h[(size_t)wn * 32 + lane] * w3h[lane];
    float pe = d_t2e[(size_t)wn * 32 + lane] * w3e[lane];
    #pragma unroll
    for (int st = 16; st > 0; st >>= 1) {
        ph += __shfl_down_sync(0xffffffffu, ph, st);
        pe += __shfl_down_sync(0xffffffffu, pe, st);
    }
    float v = 0.f;
    if (lane == 0 && w < n) {
        float sh = 1.f / (1.f + expf(-(ph + b3h[0])));
        float se = 1.f / (1.f + expf(-(pe + b3e[0])));
        v = 0.5f * (sh + se);
    }
    if (lane == 0) wpart[wid] = v;
    __syncthreads();
    if (tid < 8) {
        float s = wpart[tid];
        s += __shfl_down_sync(0x000000ffu, s, 4, 8);
        s += __shfl_down_sync(0x000000ffu, s, 2, 8);
        s += __shfl_down_sync(0x000000ffu, s, 1, 8);
        if (tid == 0) d_ptm[blockIdx.x] = (double)s;
    }
}

// ---------------- final scalar assembly ----------------
__global__ void k_final(float* __restrict__ out, int nb_bond, int nb_tm, int n) {
    __shared__ double sr[256];
    int tid = threadIdx.x;
    double s = 0.0;
    for (int i = tid; i < nb_bond; i += 256) s += d_pbond[i];
    sr[tid] = s;
    __syncthreads();
    for (int st = 128; st > 0; st >>= 1) { if (tid < st) sr[tid] += sr[tid + st]; __syncthreads(); }
    double ebond = sr[0];
    __syncthreads();
    s = 0.0;
    for (int i = tid; i < nb_tm; i += 256) s += d_ptm[i];
    sr[tid] = s;
    __syncthreads();
    for (int st = 128; st > 0; st >>= 1) { if (tid < st) sr[tid] += sr[tid + st]; __syncthreads(); }
    if (tid == 0) {
        double tm = sr[0] / (double)n;
        double et = ebond + 3.0;
        if (tm < 0.5) et += (1.0 - tm) * 10.0;
        out[0] = (float)ebond;
        out[1] = 1.0f; out[2] = 1.0f; out[3] = 1.0f;
        out[4] = (float)et;
        out[5] = (float)tm;
    }
}

// ---------------- host launcher ----------------
extern "C" void kernel_launch(void* const* d_in, const int* in_sizes, int n_in,
                              void* d_out, int out_size) {
    const float* x     = (const float*)d_in[0];
    const int*   ei    = (const int*)  d_in[1];
    const float* pos   = (const float*)d_in[2];
    /* d_in[3] = batch (unused) */
    const float* emb_w = (const float*)d_in[4];
    const float* emb_b = (const float*)d_in[5];
    const float* c1_w  = (const float*)d_in[6];
    const float* c1_b  = (const float*)d_in[7];
    const float* c2_w  = (const float*)d_in[8];
    const float* c2_b  = (const float*)d_in[9];
    const float* bw1   = (const float*)d_in[10];
    const float* bb1   = (const float*)d_in[11];
    const float* bw2   = (const float*)d_in[12];
    const float* bb2   = (const float*)d_in[13];
    const float* hw1   = (const float*)d_in[14];
    const float* hb1   = (const float*)d_in[15];
    const float* hw2   = (const float*)d_in[16];
    const float* hb2   = (const float*)d_in[17];
    const float* hw3   = (const float*)d_in[18];
    const float* hb3   = (const float*)d_in[19];
    const float* ew1   = (const float*)d_in[20];
    const float* eb1   = (const float*)d_in[21];
    const float* ew2   = (const float*)d_in[22];
    const float* eb2   = (const float*)d_in[23];
    const float* ew3   = (const float*)d_in[24];
    const float* eb3   = (const float*)d_in[25];

    int n = in_sizes[0] / 128;
    int e = in_sizes[1] / 2;
    const int* src = ei;
    const int* dst = ei + e;
    float* out = (float*)d_out;

    // smem bytes per instantiation: (K*DOUT + K*(NT+4)) * 4, NT = 8192/DOUT
    const int SM_12864 = (128 * 64 + 128 * 132) * 4;   // 100,352
    const int SM_64128 = (64 * 128 + 64 * 68) * 4;     //  50,176
    const int SM_128128 = (128 * 128 + 128 * 68) * 4;  // 100,352
    const int SM_6432 = (64 * 32 + 64 * 260) * 4;      //  74,752

    cudaFuncSetAttribute((const void*)k_gemm<128, 64, true, true>,
                         cudaFuncAttributeMaxDynamicSharedMemorySize, SM_12864);
    cudaFuncSetAttribute((const void*)k_gemm<128, 64, true, false>,
                         cudaFuncAttributeMaxDynamicSharedMemorySize, SM_12864);
    cudaFuncSetAttribute((const void*)k_gemm<128, 64, false, false>,
                         cudaFuncAttributeMaxDynamicSharedMemorySize, SM_12864);
    cudaFuncSetAttribute((const void*)k_gemm<64, 128, true, true>,
                         cudaFuncAttributeMaxDynamicSharedMemorySize, SM_64128);
    cudaFuncSetAttribute((const void*)k_gemm<128, 128, true, false>,
                         cudaFuncAttributeMaxDynamicSharedMemorySize, SM_128128);
    cudaFuncSetAttribute((const void*)k_gemm<64, 32, true, false>,
                         cudaFuncAttributeMaxDynamicSharedMemorySize, SM_6432);

    // ---- CSR build (deg zeroed by kernel — device symbols can't be memset from host) ----
    k_zero_deg<<<(n + 255) / 256, 256>>>(n);                          // launch 1
    k_count<<<(e + 255) / 256, 256>>>(dst, e);                        // launch 2
    k_scan<<<1, 1024>>>(n);                                           // launch 3

    // ---- embedding: h0s = relu(x @ emb_w^T + emb_b) * dinv  (launch 4, profiled) ----
    k_gemm<128, 64, true, true><<<(n + 127) / 128, 256, SM_12864>>>(x, emb_w, emb_b, d_h0, n);

    // ---- CSR fill (independent of emb GEMM) ----
    k_fill<<<(e + 255) / 256, 256>>>(src, dst, e);

    // ---- GCN layer 1: aggregate (64-dim) then GEMM; output pre-scaled for layer 2 ----
    {
        int warps = (n + 1) / 2;                       // 2 nodes per warp (D=64)
        k_agg<64><<<(warps * 32 + 511) / 512, 512>>>(d_h0, d_a0, n);
    }
    k_gemm<64, 128, true, true><<<(n + 63) / 64, 256, SM_64128>>>(d_a0, c1_w, c1_b, d_lin, n);

    // ---- GCN layer 2: aggregate (128-dim) then GEMM ----
    k_agg<128><<<(n * 32 + 511) / 512, 512>>>(d_lin, d_h, n);
    k_gemm<128, 128, true, false><<<(n + 63) / 64, 256, SM_128128>>>(d_h, c2_w, c2_b, d_lin, n);
    float* h = d_lin;                                                 // final node features

    // ---- bond projection: g = h @ bond_w1^T + bond_b1 ----
    k_gemm<128, 64, false, false><<<(n + 127) / 128, 256, SM_12864>>>(h, bw1, bb1, d_g, n);

    // ---- tm MLPs ----
    k_gemm<128, 64, true, false><<<(n + 127) / 128, 256, SM_12864>>>(h, hw1, hb1, d_t1, n);
    k_gemm<64, 32, true, false><<<(n + 255) / 256, 256, SM_6432>>>(d_t1, hw2, hb2, d_t2h, n);
    k_gemm<128, 64, true, false><<<(n + 127) / 128, 256, SM_12864>>>(h, ew1, eb1, d_t1, n);
    k_gemm<64, 32, true, false><<<(n + 255) / 256, 256, SM_6432>>>(d_t1, ew2, eb2, d_t2e, n);

    // ---- reductions ----
    int nb_tm = (n + 7) / 8;
    k_tm<<<nb_tm, 256>>>(hw3, hb3, ew3, eb3, n);
    int total_groups = BOND_BLKS * 32;
    k_bond<<<BOND_BLKS, 256>>>(src, dst, pos, bw2, bb2, e, total_groups);
    k_final<<<1, 256>>>(out, BOND_BLKS, nb_tm, n);
}

// round 6
// speedup vs baseline: 1.4613x; 1.0863x over previous
#include <cuda_runtime.h>
#include <math.h>

#define NMAX 50000
#define EMAX 1600000
#define BOND_BLKS 1184
#define TMF_BLKS 592

// ---------------- scratch (device globals; no allocation allowed) ----------------
__device__ float d_h0 [(size_t)NMAX * 64];   // emb output, pre-scaled by dinv
__device__ float d_a0 [(size_t)NMAX * 64];   // aggregated 64-dim
__device__ float d_lin[(size_t)NMAX * 128];  // layer1 out (scaled) / final features
__device__ float d_h  [(size_t)NMAX * 128];  // aggregated 128-dim
__device__ float d_g  [(size_t)NMAX * 64];
__device__ float d_t1h[(size_t)NMAX * 64];
__device__ float d_t1e[(size_t)NMAX * 64];
__device__ float d_dinv[NMAX];
__device__ int   d_deg[NMAX];
__device__ int   d_off[NMAX + 1];
__device__ int   d_cur[NMAX];
__device__ int   d_srcs[EMAX];
__device__ double d_pbond[BOND_BLKS];
__device__ double d_ptm[TMF_BLKS];

// ---------------- degree / CSR build ----------------
__global__ void k_zero_deg(int n) {
    int i = blockIdx.x * blockDim.x + threadIdx.x;
    if (i < n) d_deg[i] = 0;
}

__global__ void k_count(const int* __restrict__ dst, int e) {
    int i = blockIdx.x * blockDim.x + threadIdx.x;
    if (i < e) atomicAdd(&d_deg[dst[i]], 1);
}

// single-block scan over deg -> exclusive offsets (+ cursor copy + dinv), 4 elems/thread
__global__ void k_scan(int n) {
    __shared__ int wsum[32];
    __shared__ int carry;
    int tid = threadIdx.x, lane = tid & 31, wid = tid >> 5;
    if (tid == 0) carry = 0;
    __syncthreads();
    for (int base = 0; base < n; base += 4096) {
        int i0 = base + tid * 4;
        int v0 = (i0 + 0 < n) ? d_deg[i0 + 0] : 0;
        int v1 = (i0 + 1 < n) ? d_deg[i0 + 1] : 0;
        int v2 = (i0 + 2 < n) ? d_deg[i0 + 2] : 0;
        int v3 = (i0 + 3 < n) ? d_deg[i0 + 3] : 0;
        int tsum = v0 + v1 + v2 + v3;
        int sc = tsum;
        #pragma unroll
        for (int st = 1; st < 32; st <<= 1) {
            int t = __shfl_up_sync(0xffffffffu, sc, st);
            if (lane >= st) sc += t;
        }
        if (lane == 31) wsum[wid] = sc;
        __syncthreads();
        if (wid == 0) {
            int s = wsum[lane];
            #pragma unroll
            for (int st = 1; st < 32; st <<= 1) {
                int t = __shfl_up_sync(0xffffffffu, s, st);
                if (lane >= st) s += t;
            }
            wsum[lane] = s;
        }
        __syncthreads();
        int excl = carry + (wid ? wsum[wid - 1] : 0) + sc - tsum;
        int ev[4];
        ev[0] = excl;
        ev[1] = ev[0] + v0;
        ev[2] = ev[1] + v1;
        ev[3] = ev[2] + v2;
        int dv[4] = {v0, v1, v2, v3};
        #pragma unroll
        for (int j = 0; j < 4; j++) {
            int i = i0 + j;
            if (i < n) {
                d_off[i] = ev[j];
                d_cur[i] = ev[j];
                d_dinv[i] = rsqrtf((float)(dv[j] + 1));   // +1: self loop
            }
        }
        __syncthreads();
        if (tid == 0) carry += wsum[31];
        __syncthreads();
    }
    if (threadIdx.x == 0) d_off[n] = carry;
}

__global__ void k_fill(const int* __restrict__ src, const int* __restrict__ dst, int e) {
    int i = blockIdx.x * blockDim.x + threadIdx.x;
    if (i < e) {
        int d = dst[i];
        int p = atomicAdd(&d_cur[d], 1);
        d_srcs[p] = src[i];
    }
}

// ---------------- register-tiled GEMM, 64-output tile per grid.y ----------------
// out[node][y*64 + o] = act(in[node][0..K) @ W[y*64+o][0..K)^T + bias[y*64+o]) [* dinv]
// 256 threads, NT=64 nodes, thread = 2 nodes x 8 outs. Both W and X staged with
// stride 68 (coalesced gmem reads; <=4-way smem write conflicts; 16B-aligned reads).
template <int K, bool RELU, bool SCALE>
__global__ __launch_bounds__(256) void k_gemm64(const float* __restrict__ in,
                                                const float* __restrict__ W,
                                                const float* __restrict__ bias,
                                                float* __restrict__ out,
                                                int n, int ostride) {
    const int NT = 64, STR = 68;
    extern __shared__ float sm[];
    float* sW = sm;                   // [K][STR], cols 0..63 used
    float* sX = sm + K * STR;         // [K][STR], cols 0..63 = nodes

    int tid = threadIdx.x;
    int y = blockIdx.y;
    const float* Wy = W + (size_t)y * 64 * K;

    for (int idx = tid; idx < 64 * K; idx += 256) {
        int o = idx / K, k = idx % K;           // consecutive tid -> consecutive k (coalesced)
        sW[k * STR + o] = Wy[idx];
    }
    int base = blockIdx.x * NT;
    for (int idx = tid; idx < NT * K; idx += 256) {
        int nn = idx / K, k = idx % K;          // coalesced over k
        sX[k * STR + nn] = (base + nn < n) ? in[(size_t)(base + nn) * K + k] : 0.f;
    }
    __syncthreads();

    int o0 = (tid & 7) * 8;
    int n0 = (tid >> 3) * 2;

    float acc[2][8];
    #pragma unroll
    for (int i = 0; i < 8; i++) {
        float b = bias[y * 64 + o0 + i];
        acc[0][i] = b; acc[1][i] = b;
    }

    #pragma unroll 4
    for (int k = 0; k < K; k++) {
        float2 xv = *(const float2*)(sX + k * STR + n0);
        float4 w0 = *(const float4*)(sW + k * STR + o0);
        float4 w1 = *(const float4*)(sW + k * STR + o0 + 4);
        float wr[8] = {w0.x, w0.y, w0.z, w0.w, w1.x, w1.y, w1.z, w1.w};
        #pragma unroll
        for (int i = 0; i < 8; i++) {
            acc[0][i] += xv.x * wr[i];
            acc[1][i] += xv.y * wr[i];
        }
    }

    #pragma unroll
    for (int j = 0; j < 2; j++) {
        int node = base + n0 + j;
        if (node >= n) break;
        float s = SCALE ? d_dinv[node] : 1.f;
        float r[8];
        #pragma unroll
        for (int i = 0; i < 8; i++) {
            float v = acc[j][i];
            if (RELU) v = fmaxf(v, 0.f);
            r[i] = v * s;
        }
        float* op = out + (size_t)node * ostride + y * 64 + o0;
        *(float4*)(op)     = make_float4(r[0], r[1], r[2], r[3]);
        *(float4*)(op + 4) = make_float4(r[4], r[5], r[6], r[7]);
    }
}

// ---------------- fused tail GEMM: 3 projections of h (K=128 -> 64) in one launch ----
// y=0: g   = h @ bw1^T + bb1          (no relu)
// y=1: t1h = relu(h @ hw1^T + hb1)
// y=2: t1e = relu(h @ ew1^T + eb1)
__global__ __launch_bounds__(256) void k_tail(const float* __restrict__ in,
                                              const float* __restrict__ bw1, const float* __restrict__ bb1,
                                              const float* __restrict__ hw1, const float* __restrict__ hb1,
                                              const float* __restrict__ ew1, const float* __restrict__ eb1,
                                              int n) {
    const int K = 128, NT = 64, STR = 68;
    extern __shared__ float sm[];
    float* sW = sm;
    float* sX = sm + K * STR;

    int tid = threadIdx.x;
    int y = blockIdx.y;
    const float* W = (y == 0) ? bw1 : ((y == 1) ? hw1 : ew1);
    const float* b = (y == 0) ? bb1 : ((y == 1) ? hb1 : eb1);
    float* out = (y == 0) ? d_g : ((y == 1) ? d_t1h : d_t1e);
    bool relu = (y != 0);

    for (int idx = tid; idx < 64 * K; idx += 256) {
        int o = idx / K, k = idx % K;
        sW[k * STR + o] = W[idx];
    }
    int base = blockIdx.x * NT;
    for (int idx = tid; idx < NT * K; idx += 256) {
        int nn = idx / K, k = idx % K;
        sX[k * STR + nn] = (base + nn < n) ? in[(size_t)(base + nn) * K + k] : 0.f;
    }
    __syncthreads();

    int o0 = (tid & 7) * 8;
    int n0 = (tid >> 3) * 2;

    float acc[2][8];
    #pragma unroll
    for (int i = 0; i < 8; i++) {
        float bb = b[o0 + i];
        acc[0][i] = bb; acc[1][i] = bb;
    }

    #pragma unroll 4
    for (int k = 0; k < K; k++) {
        float2 xv = *(const float2*)(sX + k * STR + n0);
        float4 w0 = *(const float4*)(sW + k * STR + o0);
        float4 w1 = *(const float4*)(sW + k * STR + o0 + 4);
        float wr[8] = {w0.x, w0.y, w0.z, w0.w, w1.x, w1.y, w1.z, w1.w};
        #pragma unroll
        for (int i = 0; i < 8; i++) {
            acc[0][i] += xv.x * wr[i];
            acc[1][i] += xv.y * wr[i];
        }
    }

    #pragma unroll
    for (int j = 0; j < 2; j++) {
        int node = base + n0 + j;
        if (node >= n) break;
        float r[8];
        #pragma unroll
        for (int i = 0; i < 8; i++) {
            float v = acc[j][i];
            r[i] = relu ? fmaxf(v, 0.f) : v;
        }
        float* op = out + (size_t)node * 64 + o0;
        *(float4*)(op)     = make_float4(r[0], r[1], r[2], r[3]);
        *(float4*)(op + 4) = make_float4(r[4], r[5], r[6], r[7]);
    }
}

// ---------------- GCN aggregation (pre-GEMM): a_i = dinv_i*(sum_in hs_j + hs_i) -----------
// hs rows pre-scaled by dinv_j. D=128: warp/node; D=64: half-warp/node.
template <int D>
__global__ __launch_bounds__(512) void k_agg(const float* __restrict__ hs,
                                             float* __restrict__ out, int n) {
    const int LPN = D / 4;            // lanes per node
    const int NPW = 32 / LPN;         // nodes per warp
    int gw = (blockIdx.x * blockDim.x + threadIdx.x) >> 5;
    int lane = threadIdx.x & 31;
    int node = gw * NPW + lane / LPN;
    if (node >= n) return;
    int c = (lane % LPN) * 4;
    float4 acc = *(const float4*)(hs + (size_t)node * D + c);   // self term
    int j0 = d_off[node], j1 = d_off[node + 1];
    int j = j0;
    for (; j + 3 < j1; j += 4) {
        int s0 = d_srcs[j], s1 = d_srcs[j + 1], s2 = d_srcs[j + 2], s3 = d_srcs[j + 3];
        float4 v0 = *(const float4*)(hs + (size_t)s0 * D + c);
        float4 v1 = *(const float4*)(hs + (size_t)s1 * D + c);
        float4 v2 = *(const float4*)(hs + (size_t)s2 * D + c);
        float4 v3 = *(const float4*)(hs + (size_t)s3 * D + c);
        acc.x += (v0.x + v1.x) + (v2.x + v3.x);
        acc.y += (v0.y + v1.y) + (v2.y + v3.y);
        acc.z += (v0.z + v1.z) + (v2.z + v3.z);
        acc.w += (v0.w + v1.w) + (v2.w + v3.w);
    }
    for (; j < j1; j++) {
        int s0 = d_srcs[j];
        float4 v0 = *(const float4*)(hs + (size_t)s0 * D + c);
        acc.x += v0.x; acc.y += v0.y; acc.z += v0.z; acc.w += v0.w;
    }
    float dv = d_dinv[node];
    float4 o;
    o.x = acc.x * dv; o.y = acc.y * dv; o.z = acc.z * dv; o.w = acc.w * dv;
    *(float4*)(out + (size_t)node * D + c) = o;
}

// ---------------- bond energy (8 threads/edge, grid-stride, w2 in regs) ----------------
__global__ __launch_bounds__(256) void k_bond(const int* __restrict__ src,
                                              const int* __restrict__ dst,
                                              const float* __restrict__ pos,
                                              const float* __restrict__ w2,
                                              const float* __restrict__ b2p,
                                              int e, int total_groups) {
    __shared__ float wpart[8];
    int tid = threadIdx.x;
    int sub = tid & 7;
    int lane = tid & 31, wid = tid >> 5;
    float wreg[8];
    #pragma unroll
    for (int j = 0; j < 8; j++) wreg[j] = w2[sub * 8 + j];
    float b2 = b2p[0];

    int g0 = (blockIdx.x * 256 + tid) >> 3;
    float accq = 0.f;
    int cnt = 0;
    for (int eid = g0; eid < e; eid += total_groups) {
        int s = src[eid], d = dst[eid];
        const float* gs = d_g + (size_t)s * 64 + sub * 8;
        const float* gd = d_g + (size_t)d * 64 + sub * 8;
        float4 a0 = *(const float4*)(gs), a1 = *(const float4*)(gs + 4);
        float4 b0 = *(const float4*)(gd), b1 = *(const float4*)(gd + 4);
        float p = 0.f;
        p += fmaxf(0.5f * (a0.x + b0.x), 0.f) * wreg[0];
        p += fmaxf(0.5f * (a0.y + b0.y), 0.f) * wreg[1];
        p += fmaxf(0.5f * (a0.z + b0.z), 0.f) * wreg[2];
        p += fmaxf(0.5f * (a0.w + b0.w), 0.f) * wreg[3];
        p += fmaxf(0.5f * (a1.x + b1.x), 0.f) * wreg[4];
        p += fmaxf(0.5f * (a1.y + b1.y), 0.f) * wreg[5];
        p += fmaxf(0.5f * (a1.z + b1.z), 0.f) * wreg[6];
        p += fmaxf(0.5f * (a1.w + b1.w), 0.f) * wreg[7];
        p += __shfl_down_sync(0xffffffffu, p, 4, 8);
        p += __shfl_down_sync(0xffffffffu, p, 2, 8);
        p += __shfl_down_sync(0xffffffffu, p, 1, 8);
        if (sub == 0) {
            float dx = pos[d * 3 + 0] - pos[s * 3 + 0];
            float dy = pos[d * 3 + 1] - pos[s * 3 + 1];
            float dz = pos[d * 3 + 2] - pos[s * 3 + 2];
            float L = sqrtf(dx * dx + dy * dy + dz * dz);
            float t = L - 1.5f;
            accq += p + 1000.f * t * t;
            cnt++;
        }
    }
    float v = accq + b2 * (float)cnt;   // nonzero only on sub==0 lanes
    #pragma unroll
    for (int st = 16; st > 0; st >>= 1) v += __shfl_down_sync(0xffffffffu, v, st);
    if (lane == 0) wpart[wid] = v;
    __syncthreads();
    if (tid < 8) {
        float s = wpart[tid];
        s += __shfl_down_sync(0x000000ffu, s, 4, 8);
        s += __shfl_down_sync(0x000000ffu, s, 2, 8);
        s += __shfl_down_sync(0x000000ffu, s, 1, 8);
        if (tid == 0) d_pbond[blockIdx.x] = (double)s;
    }
}

// ---------------- fused tm: t1 -> relu(t1@w2^T+b2) -> sigmoid(.@w3^T+b3), mean partials ----
__global__ __launch_bounds__(256) void k_tmf(const float* __restrict__ w2h, const float* __restrict__ b2h,
                                             const float* __restrict__ w3h, const float* __restrict__ b3h,
                                             const float* __restrict__ w2e, const float* __restrict__ b2e,
                                             const float* __restrict__ w3e, const float* __restrict__ b3e,
                                             int n) {
    __shared__ float sw2h[64 * 33];   // [k][o], pad 33
    __shared__ float sw2e[64 * 33];
    __shared__ float sx[8 * 128];
    __shared__ float s3h[32], s3e[32];
    __shared__ float wpart[8];
    int tid = threadIdx.x, lane = tid & 31, wid = tid >> 5;

    for (int idx = tid; idx < 2048; idx += 256) {
        int o = idx >> 6, k = idx & 63;         // consecutive tid -> consecutive k (coalesced)
        sw2h[k * 33 + o] = w2h[idx];
        sw2e[k * 33 + o] = w2e[idx];
    }
    if (tid < 32) s3h[tid] = w3h[tid];
    else if (tid < 64) s3e[tid - 32] = w3e[tid - 32];
    __syncthreads();

    float bh = b2h[lane], be = b2e[lane];
    float b3hv = b3h[0], b3ev = b3e[0];
    float accv = 0.f;

    for (int node = blockIdx.x * 8 + wid; node < n; node += TMF_BLKS * 8) {
        float xh0 = d_t1h[(size_t)node * 64 + lane];
        float xh1 = d_t1h[(size_t)node * 64 + 32 + lane];
        float xe0 = d_t1e[(size_t)node * 64 + lane];
        float xe1 = d_t1e[(size_t)node * 64 + 32 + lane];
        sx[wid * 128 + lane]      = xh0;
        sx[wid * 128 + 32 + lane] = xh1;
        sx[wid * 128 + 64 + lane] = xe0;
        sx[wid * 128 + 96 + lane] = xe1;
        __syncwarp();
        float ah = bh, ae = be;
        #pragma unroll 8
        for (int k = 0; k < 64; k++) {
            float xk  = sx[wid * 128 + k];
            float xke = sx[wid * 128 + 64 + k];
            ah += xk  * sw2h[k * 33 + lane];
            ae += xke * sw2e[k * 33 + lane];
        }
        ah = fmaxf(ah, 0.f) * s3h[lane];
        ae = fmaxf(ae, 0.f) * s3e[lane];
        #pragma unroll
        for (int st = 16; st > 0; st >>= 1) {
            ah += __shfl_down_sync(0xffffffffu, ah, st);
            ae += __shfl_down_sync(0xffffffffu, ae, st);
        }
        if (lane == 0) {
            float sh = 1.f / (1.f + expf(-(ah + b3hv)));
            float se = 1.f / (1.f + expf(-(ae + b3ev)));
            accv += 0.5f * (sh + se);
        }
        __syncwarp();
    }
    if (lane == 0) wpart[wid] = accv;
    __syncthreads();
    if (tid < 8) {
        float s = wpart[tid];
        s += __shfl_down_sync(0x000000ffu, s, 4, 8);
        s += __shfl_down_sync(0x000000ffu, s, 2, 8);
        s += __shfl_down_sync(0x000000ffu, s, 1, 8);
        if (tid == 0) d_ptm[blockIdx.x] = (double)s;
    }
}

// ---------------- final scalar assembly ----------------
__global__ void k_final(float* __restrict__ out, int nb_bond, int nb_tm, int n) {
    __shared__ double sr[256];
    int tid = threadIdx.x;
    double s = 0.0;
    for (int i = tid; i < nb_bond; i += 256) s += d_pbond[i];
    sr[tid] = s;
    __syncthreads();
    for (int st = 128; st > 0; st >>= 1) { if (tid < st) sr[tid] += sr[tid + st]; __syncthreads(); }
    double ebond = sr[0];
    __syncthreads();
    s = 0.0;
    for (int i = tid; i < nb_tm; i += 256) s += d_ptm[i];
    sr[tid] = s;
    __syncthreads();
    for (int st = 128; st > 0; st >>= 1) { if (tid < st) sr[tid] += sr[tid + st]; __syncthreads(); }
    if (tid == 0) {
        double tm = sr[0] / (double)n;
        double et = ebond + 3.0;
        if (tm < 0.5) et += (1.0 - tm) * 10.0;
        out[0] = (float)ebond;
        out[1] = 1.0f; out[2] = 1.0f; out[3] = 1.0f;
        out[4] = (float)et;
        out[5] = (float)tm;
    }
}

// ---------------- host launcher ----------------
extern "C" void kernel_launch(void* const* d_in, const int* in_sizes, int n_in,
                              void* d_out, int out_size) {
    const float* x     = (const float*)d_in[0];
    const int*   ei    = (const int*)  d_in[1];
    const float* pos   = (const float*)d_in[2];
    /* d_in[3] = batch (unused) */
    const float* emb_w = (const float*)d_in[4];
    const float* emb_b = (const float*)d_in[5];
    const float* c1_w  = (const float*)d_in[6];
    const float* c1_b  = (const float*)d_in[7];
    const float* c2_w  = (const float*)d_in[8];
    const float* c2_b  = (const float*)d_in[9];
    const float* bw1   = (const float*)d_in[10];
    const float* bb1   = (const float*)d_in[11];
    const float* bw2   = (const float*)d_in[12];
    const float* bb2   = (const float*)d_in[13];
    const float* hw1   = (const float*)d_in[14];
    const float* hb1   = (const float*)d_in[15];
    const float* hw2   = (const float*)d_in[16];
    const float* hb2   = (const float*)d_in[17];
    const float* hw3   = (const float*)d_in[18];
    const float* hb3   = (const float*)d_in[19];
    const float* ew1   = (const float*)d_in[20];
    const float* eb1   = (const float*)d_in[21];
    const float* ew2   = (const float*)d_in[22];
    const float* eb2   = (const float*)d_in[23];
    const float* ew3   = (const float*)d_in[24];
    const float* eb3   = (const float*)d_in[25];

    int n = in_sizes[0] / 128;
    int e = in_sizes[1] / 2;
    const int* src = ei;
    const int* dst = ei + e;
    float* out = (float*)d_out;

    // dynamic smem: 2 * K * 68 floats
    const int SM_K128 = 2 * 128 * 68 * 4;   // 69,632 -> 3 blocks/SM
    const int SM_K64  = 2 * 64 * 68 * 4;    // 34,816 -> 6 blocks/SM

    cudaFuncSetAttribute((const void*)k_gemm64<128, true, true>,
                         cudaFuncAttributeMaxDynamicSharedMemorySize, SM_K128);
    cudaFuncSetAttribute((const void*)k_gemm64<128, true, false>,
                         cudaFuncAttributeMaxDynamicSharedMemorySize, SM_K128);
    cudaFuncSetAttribute((const void*)k_gemm64<64, true, true>,
                         cudaFuncAttributeMaxDynamicSharedMemorySize, SM_K64);
    cudaFuncSetAttribute((const void*)k_tail,
                         cudaFuncAttributeMaxDynamicSharedMemorySize, SM_K128);

    int gx = (n + 63) / 64;   // 782

    // ---- CSR build ----
    k_zero_deg<<<(n + 255) / 256, 256>>>(n);                          // launch 1
    k_count<<<(e + 255) / 256, 256>>>(dst, e);                        // launch 2
    k_scan<<<1, 1024>>>(n);                                           // launch 3

    // ---- embedding: h0s = relu(x @ emb_w^T + emb_b) * dinv  (launch 4, profiled) ----
    k_gemm64<128, true, true><<<dim3(gx, 1), 256, SM_K128>>>(x, emb_w, emb_b, d_h0, n, 64);

    // ---- CSR fill (independent of emb GEMM) ----
    k_fill<<<(e + 255) / 256, 256>>>(src, dst, e);

    // ---- GCN layer 1: aggregate (64-dim) then GEMM; output pre-scaled for layer 2 ----
    {
        int warps = (n + 1) / 2;                       // 2 nodes per warp (D=64)
        k_agg<64><<<(warps * 32 + 511) / 512, 512>>>(d_h0, d_a0, n);
    }
    k_gemm64<64, true, true><<<dim3(gx, 2), 256, SM_K64>>>(d_a0, c1_w, c1_b, d_lin, n, 128);

    // ---- GCN layer 2: aggregate (128-dim) then GEMM ----
    k_agg<128><<<(n * 32 + 511) / 512, 512>>>(d_lin, d_h, n);
    k_gemm64<128, true, false><<<dim3(gx, 2), 256, SM_K128>>>(d_h, c2_w, c2_b, d_lin, n, 128);
    const float* h = d_lin;                                            // final node features

    // ---- fused tail projections: g / t1h / t1e ----
    k_tail<<<dim3(gx, 3), 256, SM_K128>>>(h, bw1, bb1, hw1, hb1, ew1, eb1, n);

    // ---- fused tm second+third layers + mean partials ----
    k_tmf<<<TMF_BLKS, 256>>>(hw2, hb2, hw3, hb3, ew2, eb2, ew3, eb3, n);

    // ---- bond energy partials ----
    int total_groups = BOND_BLKS * 32;
    k_bond<<<BOND_BLKS, 256>>>(src, dst, pos, bw2, bb2, e, total_groups);

    // ---- final scalars ----
    k_final<<<1, 256>>>(out, BOND_BLKS, TMF_BLKS, n);
}

// round 7
// speedup vs baseline: 19.2760x; 13.1910x over previous
#include <cuda_runtime.h>
#include <math.h>

#define NB 148
#define NT 1024
#define NMAX 50000
#define EMAX 1600000

typedef unsigned long long u64;

// ---------------- scratch (device globals) ----------------
__device__ float d_h0 [(size_t)NMAX * 64];   // emb out (pre-scaled by dinv)
__device__ float d_a0 [(size_t)NMAX * 64];   // aggregated 64
__device__ float d_l1 [(size_t)NMAX * 128];  // c1 out (pre-scaled)
__device__ float d_ag [(size_t)NMAX * 128];  // aggregated 128
__device__ float d_l2 [(size_t)NMAX * 128];  // c2 out = final features (own buffer: avoids L1 staleness)
__device__ float d_g  [(size_t)NMAX * 64];
__device__ float d_t1h[(size_t)NMAX * 64];
__device__ float d_t1e[(size_t)NMAX * 64];
__device__ float d_dinv[NMAX];
__device__ int   d_deg[NMAX];
__device__ int   d_off[NMAX + 1];
__device__ int   d_cur[NMAX];
__device__ int   d_srcs[EMAX];
__device__ int   d_bsum[NB];
__device__ double d_pb[NB];
__device__ double d_pt[NB];
__device__ unsigned int g_bar;               // monotonic across replays

// ---------------- grid barrier (all NB blocks resident by construction) ----------------
__device__ __forceinline__ void gbar() {
    __syncthreads();
    if (threadIdx.x == 0) {
        __threadfence();
        unsigned int old = atomicAdd(&g_bar, 1u);
        unsigned int target = (old / NB + 1u) * NB;   // counter always NB-aligned between barriers
        while (*((volatile unsigned int*)&g_bar) < target) { }
        __threadfence();
    }
    __syncthreads();
}

// ---------------- packed f32x2 helpers ----------------
__device__ __forceinline__ u64 pack2(float lo, float hi) {
    u64 r; asm("mov.b64 %0, {%1, %2};" : "=l"(r) : "f"(lo), "f"(hi)); return r;
}
__device__ __forceinline__ u64 ffma2(u64 a, u64 b, u64 c) {
    u64 r; asm("fma.rn.f32x2 %0, %1, %2, %3;" : "=l"(r) : "l"(a), "l"(b), "l"(c)); return r;
}
__device__ __forceinline__ float2 unpk2(u64 v) {
    float2 f; asm("mov.b64 {%0, %1}, %2;" : "=f"(f.x), "=f"(f.y) : "l"(v)); return f;
}

// ---------------- in-kernel GEMM stage: out[:, y*64..] = act(in @ W^T + b) [*dinv] ----------------
// NT=1024 threads, tile = 128 nodes x 64 outs, thread = 2 nodes x 4 outs (f32x2-packed over outs).
template <int K>
__device__ void gemm_stage(const float* __restrict__ in, const float* __restrict__ W,
                           const float* __restrict__ bias, float* __restrict__ out,
                           int n, int youts, int ostride, bool relu, bool scale,
                           float* sW, float* sX) {
    int tid = threadIdx.x;
    int ntiles = (n + 127) >> 7;
    int o0 = (tid & 15) * 4;
    int n0 = (tid >> 4) * 2;
    for (int t = blockIdx.x; t < ntiles * youts; t += NB) {
        int y = t / ntiles, tile = t - y * ntiles;
        const float* Wy = W + (size_t)y * 64 * K;
        __syncthreads();                                  // protect smem from prior iter readers
        for (int idx = tid; idx < 64 * K; idx += NT) {
            int o = idx / K, k = idx - o * K;             // coalesced over k
            sW[k * 68 + o] = Wy[idx];
        }
        int base = tile << 7;
        int nn_max = n - base; if (nn_max > 128) nn_max = 128;
        for (int idx = tid; idx < 128 * K; idx += NT) {
            int nn = idx / K, k = idx - nn * K;
            sX[k * 132 + nn] = (nn < nn_max) ? in[(size_t)(base + nn) * K + k] : 0.f;
        }
        __syncthreads();

        float b0 = bias[y * 64 + o0 + 0], b1 = bias[y * 64 + o0 + 1];
        float b2 = bias[y * 64 + o0 + 2], b3 = bias[y * 64 + o0 + 3];
        u64 a00 = pack2(b0, b1), a01 = pack2(b2, b3);
        u64 a10 = a00, a11 = a01;

        #pragma unroll 4
        for (int k = 0; k < K; k++) {
            float2 xv = *(const float2*)(sX + k * 132 + n0);
            u64 xx0 = pack2(xv.x, xv.x);
            u64 xx1 = pack2(xv.y, xv.y);
            longlong2 wv = *(const longlong2*)(sW + k * 68 + o0);   // 16B aligned
            a00 = ffma2(xx0, (u64)wv.x, a00); a01 = ffma2(xx0, (u64)wv.y, a01);
            a10 = ffma2(xx1, (u64)wv.x, a10); a11 = ffma2(xx1, (u64)wv.y, a11);
        }

        #pragma unroll
        for (int j = 0; j < 2; j++) {
            if (n0 + j < nn_max) {
                int node = base + n0 + j;
                float2 p0 = unpk2(j ? a10 : a00);
                float2 p1 = unpk2(j ? a11 : a01);
                float r0 = p0.x, r1 = p0.y, r2 = p1.x, r3 = p1.y;
                if (relu) { r0 = fmaxf(r0, 0.f); r1 = fmaxf(r1, 0.f); r2 = fmaxf(r2, 0.f); r3 = fmaxf(r3, 0.f); }
                if (scale) { float s = d_dinv[node]; r0 *= s; r1 *= s; r2 *= s; r3 *= s; }
                *(float4*)(out + (size_t)node * ostride + y * 64 + o0) = make_float4(r0, r1, r2, r3);
            }
        }
    }
}

// ---------------- in-kernel GCN aggregation: a_i = dinv_i*(sum_in hs_j + hs_i) ----------------
template <int D>
__device__ void agg_stage(const float* __restrict__ hs, float* __restrict__ out, int n) {
    const int LPN = D / 4, NPW = 32 / LPN;
    int lane = threadIdx.x & 31;
    int gw = (blockIdx.x * NT + threadIdx.x) >> 5;
    const int TOTW = NB * (NT / 32);
    int sub = lane / LPN;
    int c = (lane % LPN) * 4;
    for (int b = gw; b * NPW < n; b += TOTW) {
        int node = b * NPW + sub;
        if (node < n) {
            float4 acc = *(const float4*)(hs + (size_t)node * D + c);   // self
            int j0 = d_off[node], j1 = d_off[node + 1];
            int j = j0;
            for (; j + 3 < j1; j += 4) {
                int s0 = d_srcs[j], s1 = d_srcs[j + 1], s2 = d_srcs[j + 2], s3 = d_srcs[j + 3];
                float4 v0 = *(const float4*)(hs + (size_t)s0 * D + c);
                float4 v1 = *(const float4*)(hs + (size_t)s1 * D + c);
                float4 v2 = *(const float4*)(hs + (size_t)s2 * D + c);
                float4 v3 = *(const float4*)(hs + (size_t)s3 * D + c);
                acc.x += (v0.x + v1.x) + (v2.x + v3.x);
                acc.y += (v0.y + v1.y) + (v2.y + v3.y);
                acc.z += (v0.z + v1.z) + (v2.z + v3.z);
                acc.w += (v0.w + v1.w) + (v2.w + v3.w);
            }
            for (; j < j1; j++) {
                int s0 = d_srcs[j];
                float4 v0 = *(const float4*)(hs + (size_t)s0 * D + c);
                acc.x += v0.x; acc.y += v0.y; acc.z += v0.z; acc.w += v0.w;
            }
            float dv = d_dinv[node];
            float4 o;
            o.x = acc.x * dv; o.y = acc.y * dv; o.z = acc.z * dv; o.w = acc.w * dv;
            *(float4*)(out + (size_t)node * D + c) = o;
        }
    }
}

// ---------------- the megakernel ----------------
extern __shared__ float smem_buf[];

__global__ __launch_bounds__(NT, 1) void mega(
    const float* __restrict__ x, const int* __restrict__ src, const int* __restrict__ dst,
    const float* __restrict__ pos,
    const float* __restrict__ emb_w, const float* __restrict__ emb_b,
    const float* __restrict__ c1_w, const float* __restrict__ c1_b,
    const float* __restrict__ c2_w, const float* __restrict__ c2_b,
    const float* __restrict__ bw1, const float* __restrict__ bb1,
    const float* __restrict__ bw2, const float* __restrict__ bb2,
    const float* __restrict__ hw1, const float* __restrict__ hb1,
    const float* __restrict__ hw2, const float* __restrict__ hb2,
    const float* __restrict__ hw3, const float* __restrict__ hb3,
    const float* __restrict__ ew1, const float* __restrict__ eb1,
    const float* __restrict__ ew2, const float* __restrict__ eb2,
    const float* __restrict__ ew3, const float* __restrict__ eb3,
    float* __restrict__ out, int n, int e) {

    __shared__ float s_red[32];
    __shared__ int   s_ired[32];
    __shared__ int   s_all[NB];
    __shared__ int   s_base;

    int tid = threadIdx.x, bid = blockIdx.x;
    int lane = tid & 31, wid = tid >> 5;
    int gt = bid * NT + tid;
    const int GSTR = NB * NT;
    float* sW = smem_buf;                 // [K][68]
    float* sX = smem_buf + 128 * 68;      // [K][132]

    // ---- S0: zero degrees ----
    for (int i = gt; i < n; i += GSTR) d_deg[i] = 0;
    gbar();

    // ---- S1: count in-degrees ----
    for (int i = gt; i < e; i += GSTR) atomicAdd(&d_deg[dst[i]], 1);
    gbar();

    // ---- S2a: per-block chunk sums ----
    int chunk = (n + NB - 1) / NB;        // 338 for n=50000 (requires chunk <= NT)
    int lo = bid * chunk;
    int len = n - lo; if (len < 0) len = 0; if (len > chunk) len = chunk;
    int v = (tid < len) ? d_deg[lo + tid] : 0;
    {
        int wv = v;
        #pragma unroll
        for (int st = 16; st > 0; st >>= 1) wv += __shfl_down_sync(0xffffffffu, wv, st);
        if (lane == 0) s_ired[wid] = wv;
        __syncthreads();
        if (tid < 32) {
            int s = s_ired[tid];
            #pragma unroll
            for (int st = 16; st > 0; st >>= 1) s += __shfl_down_sync(0xffffffffu, s, st);
            if (tid == 0) d_bsum[bid] = s;
        }
    }
    gbar();

    // ---- S2c: base + local exclusive scan -> off/cur/dinv ----
    if (tid < NB) s_all[tid] = d_bsum[tid];
    __syncthreads();
    if (tid == 0) {
        int b = 0;
        for (int j = 0; j < bid; j++) b += s_all[j];
        s_base = b;
        if (bid == NB - 1) d_off[n] = b + s_all[NB - 1];
    }
    {
        int* a = (int*)smem_buf;
        a[tid] = v;
        __syncthreads();
        for (int st = 1; st < NT; st <<= 1) {
            int t = (tid >= st) ? a[tid - st] : 0;
            __syncthreads();
            a[tid] += t;
            __syncthreads();
        }
        int excl = a[tid] - v;
        if (tid < len) {
            int o = s_base + excl;
            d_off[lo + tid] = o;
            d_cur[lo + tid] = o;
            d_dinv[lo + tid] = rsqrtf((float)(v + 1));   // +1 self loop
        }
    }
    gbar();

    // ---- S3: CSR fill + embedding GEMM ----
    for (int i = gt; i < e; i += GSTR) {
        int dd = dst[i];
        int p = atomicAdd(&d_cur[dd], 1);
        d_srcs[p] = src[i];
    }
    gemm_stage<128>(x, emb_w, emb_b, d_h0, n, 1, 64, true, true, sW, sX);
    gbar();

    // ---- S4: aggregate 64 ----
    agg_stage<64>(d_h0, d_a0, n);
    gbar();

    // ---- S5: GCN1 GEMM (64->128, relu, pre-scale) ----
    gemm_stage<64>(d_a0, c1_w, c1_b, d_l1, n, 2, 128, true, true, sW, sX);
    gbar();

    // ---- S6: aggregate 128 ----
    agg_stage<128>(d_l1, d_ag, n);
    gbar();

    // ---- S7: GCN2 GEMM (128->128, relu) ----
    gemm_stage<128>(d_ag, c2_w, c2_b, d_l2, n, 2, 128, true, false, sW, sX);
    gbar();

    // ---- S8: tail projections ----
    gemm_stage<128>(d_l2, bw1, bb1, d_g,   n, 1, 64, false, false, sW, sX);
    gemm_stage<128>(d_l2, hw1, hb1, d_t1h, n, 1, 64, true,  false, sW, sX);
    gemm_stage<128>(d_l2, ew1, eb1, d_t1e, n, 1, 64, true,  false, sW, sX);
    gbar();

    // ---- S9a: tm MLP tail (warp per node) ----
    {
        float* F = smem_buf;
        float* sw2h = F;              // 64*33
        float* sw2e = F + 2112;       // 64*33
        float* s3h  = F + 4224;
        float* s3e  = F + 4256;
        float* sx   = F + 4288;       // 32*128
        for (int idx = tid; idx < 2048; idx += NT) {
            int o = idx >> 6, k = idx & 63;
            sw2h[k * 33 + o] = hw2[idx];
            sw2e[k * 33 + o] = ew2[idx];
        }
        if (tid < 32) s3h[tid] = hw3[tid];
        else if (tid < 64) s3e[tid - 32] = ew3[tid - 32];
        __syncthreads();
        float bh = hb2[lane], be = eb2[lane];
        float b3hv = hb3[0], b3ev = eb3[0];
        float accv = 0.f;
        float* sxw = sx + wid * 128;
        for (int node = bid * 32 + wid; node < n; node += NB * 32) {
            sxw[lane]      = d_t1h[(size_t)node * 64 + lane];
            sxw[32 + lane] = d_t1h[(size_t)node * 64 + 32 + lane];
            sxw[64 + lane] = d_t1e[(size_t)node * 64 + lane];
            sxw[96 + lane] = d_t1e[(size_t)node * 64 + 32 + lane];
            __syncwarp();
            float ah = bh, ae = be;
            #pragma unroll 8
            for (int k = 0; k < 64; k++) {
                ah += sxw[k]      * sw2h[k * 33 + lane];
                ae += sxw[64 + k] * sw2e[k * 33 + lane];
            }
            ah = fmaxf(ah, 0.f) * s3h[lane];
            ae = fmaxf(ae, 0.f) * s3e[lane];
            #pragma unroll
            for (int st = 16; st > 0; st >>= 1) {
                ah += __shfl_down_sync(0xffffffffu, ah, st);
                ae += __shfl_down_sync(0xffffffffu, ae, st);
            }
            if (lane == 0)
                accv += 0.5f * (1.f / (1.f + expf(-(ah + b3hv))) + 1.f / (1.f + expf(-(ae + b3ev))));
            __syncwarp();
        }
        if (lane == 0) s_red[wid] = accv;
        __syncthreads();
        if (tid < 32) {
            float s = s_red[tid];
            #pragma unroll
            for (int st = 16; st > 0; st >>= 1) s += __shfl_down_sync(0xffffffffu, s, st);
            if (tid == 0) d_pt[bid] = (double)s;
        }
        __syncthreads();
    }

    // ---- S9b: bond energy (8 threads/edge, grid-stride) ----
    {
        int sub = tid & 7;
        float wreg[8];
        #pragma unroll
        for (int j = 0; j < 8; j++) wreg[j] = bw2[sub * 8 + j];
        float b2v = bb2[0];
        const int GROUPS = NB * (NT / 8);
        int g0 = (bid * NT + tid) >> 3;
        float accq = 0.f;
        int cnt = 0;
        for (int eid = g0; eid < e; eid += GROUPS) {
            int s = src[eid], d = dst[eid];
            const float* gs = d_g + (size_t)s * 64 + sub * 8;
            const float* gd = d_g + (size_t)d * 64 + sub * 8;
            float4 a0 = *(const float4*)(gs), a1 = *(const float4*)(gs + 4);
            float4 b0 = *(const float4*)(gd), b1 = *(const float4*)(gd + 4);
            float p = 0.f;
            p += fmaxf(0.5f * (a0.x + b0.x), 0.f) * wreg[0];
            p += fmaxf(0.5f * (a0.y + b0.y), 0.f) * wreg[1];
            p += fmaxf(0.5f * (a0.z + b0.z), 0.f) * wreg[2];
            p += fmaxf(0.5f * (a0.w + b0.w), 0.f) * wreg[3];
            p += fmaxf(0.5f * (a1.x + b1.x), 0.f) * wreg[4];
            p += fmaxf(0.5f * (a1.y + b1.y), 0.f) * wreg[5];
            p += fmaxf(0.5f * (a1.z + b1.z), 0.f) * wreg[6];
            p += fmaxf(0.5f * (a1.w + b1.w), 0.f) * wreg[7];
            p += __shfl_down_sync(0xffffffffu, p, 4, 8);
            p += __shfl_down_sync(0xffffffffu, p, 2, 8);
            p += __shfl_down_sync(0xffffffffu, p, 1, 8);
            if (sub == 0) {
                float dx = pos[d * 3 + 0] - pos[s * 3 + 0];
                float dy = pos[d * 3 + 1] - pos[s * 3 + 1];
                float dz = pos[d * 3 + 2] - pos[s * 3 + 2];
                float L = sqrtf(dx * dx + dy * dy + dz * dz);
                float t = L - 1.5f;
                accq += p + 1000.f * t * t;
                cnt++;
            }
        }
        float vv = accq + b2v * (float)cnt;   // nonzero only on sub==0 lanes
        vv += __shfl_down_sync(0xffffffffu, vv, 16);
        vv += __shfl_down_sync(0xffffffffu, vv, 8);
        if (lane == 0) s_red[wid] = vv;
        __syncthreads();
        if (tid < 32) {
            float s = s_red[tid];
            #pragma unroll
            for (int st = 16; st > 0; st >>= 1) s += __shfl_down_sync(0xffffffffu, s, st);
            if (tid == 0) d_pb[bid] = (double)s;
        }
    }
    gbar();

    // ---- S10: final scalars (block 0) ----
    if (bid == 0) {
        double* db = (double*)smem_buf;
        if (tid < NB) { db[tid] = d_pb[tid]; db[NB + tid] = d_pt[tid]; }
        __syncthreads();
        if (tid == 0) {
            double eb = 0.0, tm = 0.0;
            for (int i = 0; i < NB; i++) { eb += db[i]; tm += db[NB + i]; }
            tm /= (double)n;
            double et = eb + 3.0;
            if (tm < 0.5) et += (1.0 - tm) * 10.0;
            out[0] = (float)eb;
            out[1] = 1.0f; out[2] = 1.0f; out[3] = 1.0f;
            out[4] = (float)et;
            out[5] = (float)tm;
        }
    }
}

// ---------------- host launcher: ONE kernel launch ----------------
extern "C" void kernel_launch(void* const* d_in, const int* in_sizes, int n_in,
                              void* d_out, int out_size) {
    const float* x     = (const float*)d_in[0];
    const int*   ei    = (const int*)  d_in[1];
    const float* pos   = (const float*)d_in[2];
    /* d_in[3] = batch (unused) */
    const float* emb_w = (const float*)d_in[4];
    const float* emb_b = (const float*)d_in[5];
    const float* c1_w  = (const float*)d_in[6];
    const float* c1_b  = (const float*)d_in[7];
    const float* c2_w  = (const float*)d_in[8];
    const float* c2_b  = (const float*)d_in[9];
    const float* bw1   = (const float*)d_in[10];
    const float* bb1   = (const float*)d_in[11];
    const float* bw2   = (const float*)d_in[12];
    const float* bb2   = (const float*)d_in[13];
    const float* hw1   = (const float*)d_in[14];
    const float* hb1   = (const float*)d_in[15];
    const float* hw2   = (const float*)d_in[16];
    const float* hb2   = (const float*)d_in[17];
    const float* hw3   = (const float*)d_in[18];
    const float* hb3   = (const float*)d_in[19];
    const float* ew1   = (const float*)d_in[20];
    const float* eb1   = (const float*)d_in[21];
    const float* ew2   = (const float*)d_in[22];
    const float* eb2   = (const float*)d_in[23];
    const float* ew3   = (const float*)d_in[24];
    const float* eb3   = (const float*)d_in[25];

    int n = in_sizes[0] / 128;
    int e = in_sizes[1] / 2;
    const int* src = ei;
    const int* dst = ei + e;
    float* out = (float*)d_out;

    const int SMEM = (128 * 68 + 128 * 132) * 4;   // 102,400 B
    cudaFuncSetAttribute((const void*)mega, cudaFuncAttributeMaxDynamicSharedMemorySize, SMEM);

    mega<<<NB, NT, SMEM>>>(x, src, dst, pos,
                           emb_w, emb_b, c1_w, c1_b, c2_w, c2_b,
                           bw1, bb1, bw2, bb2,
                           hw1, hb1, hw2, hb2, hw3, hb3,
                           ew1, eb1, ew2, eb2, ew3, eb3,
                           out, n, e);
}

// round 8
// speedup vs baseline: 20.7259x; 1.0752x over previous
#include <cuda_runtime.h>
#include <cuda_fp16.h>
#include <math.h>

#define NB 148
#define NT 1024
#define NMAX 50000
#define EMAX 1600000

typedef unsigned long long u64;

// ---------------- scratch (device globals) ----------------
__device__ __half d_h0h[(size_t)NMAX * 64];   // emb out (pre-scaled by dinv), fp16 gather table
__device__ float  d_a0 [(size_t)NMAX * 64];   // aggregated 64 (fp32 stream)
__device__ __half d_l1h[(size_t)NMAX * 128];  // c1 out (pre-scaled), fp16 gather table
__device__ float  d_ag [(size_t)NMAX * 128];  // aggregated 128 (fp32 stream)
__device__ float  d_l2 [(size_t)NMAX * 128];  // c2 out = final features (fp32)
__device__ __half d_gh [(size_t)NMAX * 64];   // bond projection, fp16 gather table
__device__ float  d_t1h[(size_t)NMAX * 64];
__device__ float  d_t1e[(size_t)NMAX * 64];
__device__ float  d_dinv[NMAX];
__device__ int    d_deg[NMAX];
__device__ int    d_off[NMAX + 1];
__device__ int    d_cur[NMAX];
__device__ int    d_srcs[EMAX];
__device__ int    d_bsum[NB];
__device__ double d_pb[NB];
__device__ double d_pt[NB];
__device__ unsigned int g_bar;               // monotonic across replays

// ---------------- grid barrier (all NB blocks resident by construction) ----------------
__device__ __forceinline__ void gbar() {
    __syncthreads();
    if (threadIdx.x == 0) {
        __threadfence();
        unsigned int old = atomicAdd(&g_bar, 1u);
        unsigned int target = (old / NB + 1u) * NB;   // counter always NB-aligned between barriers
        while (*((volatile unsigned int*)&g_bar) < target) { }
        __threadfence();
    }
    __syncthreads();
}

// ---------------- packed f32x2 helpers ----------------
__device__ __forceinline__ u64 pack2(float lo, float hi) {
    u64 r; asm("mov.b64 %0, {%1, %2};" : "=l"(r) : "f"(lo), "f"(hi)); return r;
}
__device__ __forceinline__ u64 ffma2(u64 a, u64 b, u64 c) {
    u64 r; asm("fma.rn.f32x2 %0, %1, %2, %3;" : "=l"(r) : "l"(a), "l"(b), "l"(c)); return r;
}
__device__ __forceinline__ float2 unpk2(u64 v) {
    float2 f; asm("mov.b64 {%0, %1}, %2;" : "=f"(f.x), "=f"(f.y) : "l"(v)); return f;
}

// ---------------- in-kernel GEMM stage: out[:, y*64..] = act(in @ W^T + b) [*dinv] ----------------
// NT=1024 threads, tile = 128 nodes x 64 outs, thread = 2 nodes x 4 outs (f32x2-packed).
// OUTH: write fp16 (gather tables) instead of fp32.
template <int K, bool OUTH>
__device__ void gemm_stage(const float* __restrict__ in, const float* __restrict__ W,
                           const float* __restrict__ bias, void* __restrict__ outp,
                           int n, int youts, int ostride, bool relu, bool scale,
                           float* sW, float* sX) {
    int tid = threadIdx.x;
    int ntiles = (n + 127) >> 7;
    int o0 = (tid & 15) * 4;
    int n0 = (tid >> 4) * 2;
    for (int t = blockIdx.x; t < ntiles * youts; t += NB) {
        int y = t / ntiles, tile = t - y * ntiles;
        const float* Wy = W + (size_t)y * 64 * K;
        __syncthreads();                                  // protect smem from prior iter readers
        for (int idx = tid; idx < 64 * K; idx += NT) {
            int o = idx / K, k = idx - o * K;             // coalesced over k
            sW[k * 68 + o] = Wy[idx];
        }
        int base = tile << 7;
        int nn_max = n - base; if (nn_max > 128) nn_max = 128;
        for (int idx = tid; idx < 128 * K; idx += NT) {
            int nn = idx / K, k = idx - nn * K;
            sX[k * 132 + nn] = (nn < nn_max) ? in[(size_t)(base + nn) * K + k] : 0.f;
        }
        __syncthreads();

        float b0 = bias[y * 64 + o0 + 0], b1 = bias[y * 64 + o0 + 1];
        float b2 = bias[y * 64 + o0 + 2], b3 = bias[y * 64 + o0 + 3];
        u64 a00 = pack2(b0, b1), a01 = pack2(b2, b3);
        u64 a10 = a00, a11 = a01;

        #pragma unroll 4
        for (int k = 0; k < K; k++) {
            float2 xv = *(const float2*)(sX + k * 132 + n0);
            u64 xx0 = pack2(xv.x, xv.x);
            u64 xx1 = pack2(xv.y, xv.y);
            longlong2 wv = *(const longlong2*)(sW + k * 68 + o0);   // 16B aligned
            a00 = ffma2(xx0, (u64)wv.x, a00); a01 = ffma2(xx0, (u64)wv.y, a01);
            a10 = ffma2(xx1, (u64)wv.x, a10); a11 = ffma2(xx1, (u64)wv.y, a11);
        }

        #pragma unroll
        for (int j = 0; j < 2; j++) {
            if (n0 + j < nn_max) {
                int node = base + n0 + j;
                float2 p0 = unpk2(j ? a10 : a00);
                float2 p1 = unpk2(j ? a11 : a01);
                float r0 = p0.x, r1 = p0.y, r2 = p1.x, r3 = p1.y;
                if (relu) { r0 = fmaxf(r0, 0.f); r1 = fmaxf(r1, 0.f); r2 = fmaxf(r2, 0.f); r3 = fmaxf(r3, 0.f); }
                if (scale) { float s = d_dinv[node]; r0 *= s; r1 *= s; r2 *= s; r3 *= s; }
                if (OUTH) {
                    __half2 ha = __floats2half2_rn(r0, r1);
                    __half2 hb = __floats2half2_rn(r2, r3);
                    uint2 u;
                    u.x = *reinterpret_cast<unsigned*>(&ha);
                    u.y = *reinterpret_cast<unsigned*>(&hb);
                    *(uint2*)((__half*)outp + (size_t)node * ostride + y * 64 + o0) = u;
                } else {
                    *(float4*)((float*)outp + (size_t)node * ostride + y * 64 + o0) =
                        make_float4(r0, r1, r2, r3);
                }
            }
        }
    }
}

// ---------------- in-kernel GCN aggregation from fp16 table: a_i = dinv_i*(sum hs_j + hs_i) ----
template <int D>
__device__ void agg_stage(const __half* __restrict__ hs, float* __restrict__ out, int n) {
    const int LPN = D / 4, NPW = 32 / LPN;
    int lane = threadIdx.x & 31;
    int gw = (blockIdx.x * NT + threadIdx.x) >> 5;
    const int TOTW = NB * (NT / 32);
    int sub = lane / LPN;
    int c = (lane % LPN) * 4;
    for (int b = gw; b * NPW < n; b += TOTW) {
        int node = b * NPW + sub;
        if (node < n) {
            uint2 us = *(const uint2*)(hs + (size_t)node * D + c);   // self (4 halves)
            __half2 s0h = *reinterpret_cast<__half2*>(&us.x);
            __half2 s1h = *reinterpret_cast<__half2*>(&us.y);
            float2 f0 = __half22float2(s0h), f1 = __half22float2(s1h);
            float4 acc = make_float4(f0.x, f0.y, f1.x, f1.y);
            int j0 = d_off[node], j1 = d_off[node + 1];
            int j = j0;
            for (; j + 3 < j1; j += 4) {
                int i0 = d_srcs[j], i1 = d_srcs[j + 1], i2 = d_srcs[j + 2], i3 = d_srcs[j + 3];
                uint2 u0 = *(const uint2*)(hs + (size_t)i0 * D + c);
                uint2 u1 = *(const uint2*)(hs + (size_t)i1 * D + c);
                uint2 u2 = *(const uint2*)(hs + (size_t)i2 * D + c);
                uint2 u3 = *(const uint2*)(hs + (size_t)i3 * D + c);
                float2 a0 = __half22float2(*reinterpret_cast<__half2*>(&u0.x));
                float2 a1 = __half22float2(*reinterpret_cast<__half2*>(&u0.y));
                float2 b0 = __half22float2(*reinterpret_cast<__half2*>(&u1.x));
                float2 b1 = __half22float2(*reinterpret_cast<__half2*>(&u1.y));
                float2 c0 = __half22float2(*reinterpret_cast<__half2*>(&u2.x));
                float2 c1 = __half22float2(*reinterpret_cast<__half2*>(&u2.y));
                float2 e0 = __half22float2(*reinterpret_cast<__half2*>(&u3.x));
                float2 e1 = __half22float2(*reinterpret_cast<__half2*>(&u3.y));
                acc.x += (a0.x + b0.x) + (c0.x + e0.x);
                acc.y += (a0.y + b0.y) + (c0.y + e0.y);
                acc.z += (a1.x + b1.x) + (c1.x + e1.x);
                acc.w += (a1.y + b1.y) + (c1.y + e1.y);
            }
            for (; j < j1; j++) {
                int i0 = d_srcs[j];
                uint2 u0 = *(const uint2*)(hs + (size_t)i0 * D + c);
                float2 a0 = __half22float2(*reinterpret_cast<__half2*>(&u0.x));
                float2 a1 = __half22float2(*reinterpret_cast<__half2*>(&u0.y));
                acc.x += a0.x; acc.y += a0.y; acc.z += a1.x; acc.w += a1.y;
            }
            float dv = d_dinv[node];
            float4 o;
            o.x = acc.x * dv; o.y = acc.y * dv; o.z = acc.z * dv; o.w = acc.w * dv;
            *(float4*)(out + (size_t)node * D + c) = o;
        }
    }
}

// ---------------- the megakernel ----------------
extern __shared__ float smem_buf[];

__global__ __launch_bounds__(NT, 1) void mega(
    const float* __restrict__ x, const int* __restrict__ src, const int* __restrict__ dst,
    const float* __restrict__ pos,
    const float* __restrict__ emb_w, const float* __restrict__ emb_b,
    const float* __restrict__ c1_w, const float* __restrict__ c1_b,
    const float* __restrict__ c2_w, const float* __restrict__ c2_b,
    const float* __restrict__ bw1, const float* __restrict__ bb1,
    const float* __restrict__ bw2, const float* __restrict__ bb2,
    const float* __restrict__ hw1, const float* __restrict__ hb1,
    const float* __restrict__ hw2, const float* __restrict__ hb2,
    const float* __restrict__ hw3, const float* __restrict__ hb3,
    const float* __restrict__ ew1, const float* __restrict__ eb1,
    const float* __restrict__ ew2, const float* __restrict__ eb2,
    const float* __restrict__ ew3, const float* __restrict__ eb3,
    float* __restrict__ out, int n, int e) {

    __shared__ float s_red[32];
    __shared__ int   s_ired[32];
    __shared__ int   s_all[NB];
    __shared__ int   s_base;

    int tid = threadIdx.x, bid = blockIdx.x;
    int lane = tid & 31, wid = tid >> 5;
    int gt = bid * NT + tid;
    const int GSTR = NB * NT;
    float* sW = smem_buf;                 // [K][68]
    float* sX = smem_buf + 128 * 68;      // [K][132]

    // ---- S0: zero degrees ----
    for (int i = gt; i < n; i += GSTR) d_deg[i] = 0;
    gbar();

    // ---- S1: count in-degrees ----
    for (int i = gt; i < e; i += GSTR) atomicAdd(&d_deg[dst[i]], 1);
    gbar();

    // ---- S2a: per-block chunk sums ----
    int chunk = (n + NB - 1) / NB;        // 338 for n=50000 (requires chunk <= NT)
    int lo = bid * chunk;
    int len = n - lo; if (len < 0) len = 0; if (len > chunk) len = chunk;
    int v = (tid < len) ? d_deg[lo + tid] : 0;
    {
        int wv = v;
        #pragma unroll
        for (int st = 16; st > 0; st >>= 1) wv += __shfl_down_sync(0xffffffffu, wv, st);
        if (lane == 0) s_ired[wid] = wv;
        __syncthreads();
        if (tid < 32) {
            int s = s_ired[tid];
            #pragma unroll
            for (int st = 16; st > 0; st >>= 1) s += __shfl_down_sync(0xffffffffu, s, st);
            if (tid == 0) d_bsum[bid] = s;
        }
    }
    gbar();

    // ---- S2c: base + local exclusive scan -> off/cur/dinv ----
    if (tid < NB) s_all[tid] = d_bsum[tid];
    __syncthreads();
    if (tid == 0) {
        int b = 0;
        for (int j = 0; j < bid; j++) b += s_all[j];
        s_base = b;
        if (bid == NB - 1) d_off[n] = b + s_all[NB - 1];
    }
    {
        int* a = (int*)smem_buf;
        a[tid] = v;
        __syncthreads();
        for (int st = 1; st < NT; st <<= 1) {
            int t = (tid >= st) ? a[tid - st] : 0;
            __syncthreads();
            a[tid] += t;
            __syncthreads();
        }
        int excl = a[tid] - v;
        if (tid < len) {
            int o = s_base + excl;
            d_off[lo + tid] = o;
            d_cur[lo + tid] = o;
            d_dinv[lo + tid] = rsqrtf((float)(v + 1));   // +1 self loop
        }
    }
    gbar();

    // ---- S3: CSR fill + embedding GEMM (fp16 out) ----
    for (int i = gt; i < e; i += GSTR) {
        int dd = dst[i];
        int p = atomicAdd(&d_cur[dd], 1);
        d_srcs[p] = src[i];
    }
    gemm_stage<128, true>(x, emb_w, emb_b, d_h0h, n, 1, 64, true, true, sW, sX);
    gbar();

    // ---- S4: aggregate 64 (fp16 gathers) ----
    agg_stage<64>(d_h0h, d_a0, n);
    gbar();

    // ---- S5: GCN1 GEMM (64->128, relu, pre-scale, fp16 out) ----
    gemm_stage<64, true>(d_a0, c1_w, c1_b, d_l1h, n, 2, 128, true, true, sW, sX);
    gbar();

    // ---- S6: aggregate 128 (fp16 gathers) ----
    agg_stage<128>(d_l1h, d_ag, n);
    gbar();

    // ---- S7: GCN2 GEMM (128->128, relu, fp32 out) ----
    gemm_stage<128, false>(d_ag, c2_w, c2_b, d_l2, n, 2, 128, true, false, sW, sX);
    gbar();

    // ---- S8: tail projections (g in fp16; t1h/t1e fp32 streams) ----
    gemm_stage<128, true >(d_l2, bw1, bb1, d_gh,  n, 1, 64, false, false, sW, sX);
    gemm_stage<128, false>(d_l2, hw1, hb1, d_t1h, n, 1, 64, true,  false, sW, sX);
    gemm_stage<128, false>(d_l2, ew1, eb1, d_t1e, n, 1, 64, true,  false, sW, sX);
    gbar();

    // ---- S9a: tm MLP tail (warp per node) ----
    {
        float* F = smem_buf;
        float* sw2h = F;              // 64*33
        float* sw2e = F + 2112;       // 64*33
        float* s3h  = F + 4224;
        float* s3e  = F + 4256;
        float* sx   = F + 4288;       // 32*128
        for (int idx = tid; idx < 2048; idx += NT) {
            int o = idx >> 6, k = idx & 63;
            sw2h[k * 33 + o] = hw2[idx];
            sw2e[k * 33 + o] = ew2[idx];
        }
        if (tid < 32) s3h[tid] = hw3[tid];
        else if (tid < 64) s3e[tid - 32] = ew3[tid - 32];
        __syncthreads();
        float bh = hb2[lane], be = eb2[lane];
        float b3hv = hb3[0], b3ev = eb3[0];
        float accv = 0.f;
        float* sxw = sx + wid * 128;
        for (int node = bid * 32 + wid; node < n; node += NB * 32) {
            sxw[lane]      = d_t1h[(size_t)node * 64 + lane];
            sxw[32 + lane] = d_t1h[(size_t)node * 64 + 32 + lane];
            sxw[64 + lane] = d_t1e[(size_t)node * 64 + lane];
            sxw[96 + lane] = d_t1e[(size_t)node * 64 + 32 + lane];
            __syncwarp();
            float ah = bh, ae = be;
            #pragma unroll 8
            for (int k = 0; k < 64; k++) {
                ah += sxw[k]      * sw2h[k * 33 + lane];
                ae += sxw[64 + k] * sw2e[k * 33 + lane];
            }
            ah = fmaxf(ah, 0.f) * s3h[lane];
            ae = fmaxf(ae, 0.f) * s3e[lane];
            #pragma unroll
            for (int st = 16; st > 0; st >>= 1) {
                ah += __shfl_down_sync(0xffffffffu, ah, st);
                ae += __shfl_down_sync(0xffffffffu, ae, st);
            }
            if (lane == 0)
                accv += 0.5f * (1.f / (1.f + expf(-(ah + b3hv))) + 1.f / (1.f + expf(-(ae + b3ev))));
            __syncwarp();
        }
        if (lane == 0) s_red[wid] = accv;
        __syncthreads();
        if (tid < 32) {
            float s = s_red[tid];
            #pragma unroll
            for (int st = 16; st > 0; st >>= 1) s += __shfl_down_sync(0xffffffffu, s, st);
            if (tid == 0) d_pt[bid] = (double)s;
        }
        __syncthreads();
    }

    // ---- S9b: bond energy (8 threads/edge, fp16 gathers of g) ----
    {
        int sub = tid & 7;
        float wreg[8];
        #pragma unroll
        for (int j = 0; j < 8; j++) wreg[j] = bw2[sub * 8 + j];
        float b2v = bb2[0];
        const int GROUPS = NB * (NT / 8);
        int g0 = (bid * NT + tid) >> 3;
        float accq = 0.f;
        int cnt = 0;
        for (int eid = g0; eid < e; eid += GROUPS) {
            int s = src[eid], d = dst[eid];
            uint4 us = *(const uint4*)(d_gh + (size_t)s * 64 + sub * 8);   // 8 halves
            uint4 ud = *(const uint4*)(d_gh + (size_t)d * 64 + sub * 8);
            float2 s0 = __half22float2(*reinterpret_cast<__half2*>(&us.x));
            float2 s1 = __half22float2(*reinterpret_cast<__half2*>(&us.y));
            float2 s2 = __half22float2(*reinterpret_cast<__half2*>(&us.z));
            float2 s3 = __half22float2(*reinterpret_cast<__half2*>(&us.w));
            float2 t0 = __half22float2(*reinterpret_cast<__half2*>(&ud.x));
            float2 t1 = __half22float2(*reinterpret_cast<__half2*>(&ud.y));
            float2 t2 = __half22float2(*reinterpret_cast<__half2*>(&ud.z));
            float2 t3 = __half22float2(*reinterpret_cast<__half2*>(&ud.w));
            float p = 0.f;
            p += fmaxf(0.5f * (s0.x + t0.x), 0.f) * wreg[0];
            p += fmaxf(0.5f * (s0.y + t0.y), 0.f) * wreg[1];
            p += fmaxf(0.5f * (s1.x + t1.x), 0.f) * wreg[2];
            p += fmaxf(0.5f * (s1.y + t1.y), 0.f) * wreg[3];
            p += fmaxf(0.5f * (s2.x + t2.x), 0.f) * wreg[4];
            p += fmaxf(0.5f * (s2.y + t2.y), 0.f) * wreg[5];
            p += fmaxf(0.5f * (s3.x + t3.x), 0.f) * wreg[6];
            p += fmaxf(0.5f * (s3.y + t3.y), 0.f) * wreg[7];
            p += __shfl_down_sync(0xffffffffu, p, 4, 8);
            p += __shfl_down_sync(0xffffffffu, p, 2, 8);
            p += __shfl_down_sync(0xffffffffu, p, 1, 8);
            if (sub == 0) {
                float dx = pos[d * 3 + 0] - pos[s * 3 + 0];
                float dy = pos[d * 3 + 1] - pos[s * 3 + 1];
                float dz = pos[d * 3 + 2] - pos[s * 3 + 2];
                float L = sqrtf(dx * dx + dy * dy + dz * dz);
                float t = L - 1.5f;
                accq += p + 1000.f * t * t;
                cnt++;
            }
        }
        float vv = accq + b2v * (float)cnt;   // nonzero only on sub==0 lanes
        vv += __shfl_down_sync(0xffffffffu, vv, 16);
        vv += __shfl_down_sync(0xffffffffu, vv, 8);
        if (lane == 0) s_red[wid] = vv;
        __syncthreads();
        if (tid < 32) {
            float s = s_red[tid];
            #pragma unroll
            for (int st = 16; st > 0; st >>= 1) s += __shfl_down_sync(0xffffffffu, s, st);
            if (tid == 0) d_pb[bid] = (double)s;
        }
    }
    gbar();

    // ---- S10: final scalars (block 0) ----
    if (bid == 0) {
        double* db = (double*)smem_buf;
        if (tid < NB) { db[tid] = d_pb[tid]; db[NB + tid] = d_pt[tid]; }
        __syncthreads();
        if (tid == 0) {
            double eb = 0.0, tm = 0.0;
            for (int i = 0; i < NB; i++) { eb += db[i]; tm += db[NB + i]; }
            tm /= (double)n;
            double et = eb + 3.0;
            if (tm < 0.5) et += (1.0 - tm) * 10.0;
            out[0] = (float)eb;
            out[1] = 1.0f; out[2] = 1.0f; out[3] = 1.0f;
            out[4] = (float)et;
            out[5] = (float)tm;
        }
    }
}

// ---------------- host launcher: ONE kernel launch ----------------
extern "C" void kernel_launch(void* const* d_in, const int* in_sizes, int n_in,
                              void* d_out, int out_size) {
    const float* x     = (const float*)d_in[0];
    const int*   ei    = (const int*)  d_in[1];
    const float* pos   = (const float*)d_in[2];
    /* d_in[3] = batch (unused) */
    const float* emb_w = (const float*)d_in[4];
    const float* emb_b = (const float*)d_in[5];
    const float* c1_w  = (const float*)d_in[6];
    const float* c1_b  = (const float*)d_in[7];
    const float* c2_w  = (const float*)d_in[8];
    const float* c2_b  = (const float*)d_in[9];
    const float* bw1   = (const float*)d_in[10];
    const float* bb1   = (const float*)d_in[11];
    const float* bw2   = (const float*)d_in[12];
    const float* bb2   = (const float*)d_in[13];
    const float* hw1   = (const float*)d_in[14];
    const float* hb1   = (const float*)d_in[15];
    const float* hw2   = (const float*)d_in[16];
    const float* hb2   = (const float*)d_in[17];
    const float* hw3   = (const float*)d_in[18];
    const float* hb3   = (const float*)d_in[19];
    const float* ew1   = (const float*)d_in[20];
    const float* eb1   = (const float*)d_in[21];
    const float* ew2   = (const float*)d_in[22];
    const float* eb2   = (const float*)d_in[23];
    const float* ew3   = (const float*)d_in[24];
    const float* eb3   = (const float*)d_in[25];

    int n = in_sizes[0] / 128;
    int e = in_sizes[1] / 2;
    const int* src = ei;
    const int* dst = ei + e;
    float* out = (float*)d_out;

    const int SMEM = (128 * 68 + 128 * 132) * 4;   // 102,400 B
    cudaFuncSetAttribute((const void*)mega, cudaFuncAttributeMaxDynamicSharedMemorySize, SMEM);

    mega<<<NB, NT, SMEM>>>(x, src, dst, pos,
                           emb_w, emb_b, c1_w, c1_b, c2_w, c2_b,
                           bw1, bb1, bw2, bb2,
                           hw1, hb1, hw2, hb2, hw3, hb3,
                           ew1, eb1, ew2, eb2, ew3, eb3,
                           out, n, e);
}

// round 9
// speedup vs baseline: 22.1701x; 1.0697x over previous
#include <cuda_runtime.h>
#include <cuda_fp16.h>
#include <math.h>

#define NB 148
#define NT 1024
#define NMAX 50000
#define EMAX 1600000

typedef unsigned long long u64;

// ---------------- scratch (device globals) ----------------
__device__ __half d_h0h[(size_t)NMAX * 64];   // emb out (pre-scaled by dinv), fp16 gather table
__device__ float  d_a0 [(size_t)NMAX * 64];   // aggregated 64 (fp32 stream)
__device__ __half d_l1h[(size_t)NMAX * 128];  // c1 out (pre-scaled), fp16 gather table
__device__ float  d_ag [(size_t)NMAX * 128];  // aggregated 128 (fp32 stream)
__device__ float  d_l2 [(size_t)NMAX * 128];  // c2 out = final features (fp32)
__device__ __half d_gh [(size_t)NMAX * 64];   // bond projection, fp16 gather table
__device__ float  d_t1h[(size_t)NMAX * 64];
__device__ float  d_t1e[(size_t)NMAX * 64];
__device__ float  d_dinv[NMAX];
__device__ int    d_deg[NMAX];
__device__ int    d_off[NMAX + 1];
__device__ int    d_cur[NMAX];
__device__ int    d_srcs[EMAX];
__device__ int    d_bsum[NB];
__device__ double d_pb[NB];
__device__ double d_pt[NB];
__device__ unsigned int g_bar;               // monotonic across replays

// ---------------- grid barrier (all NB blocks resident by construction) ----------------
__device__ __forceinline__ void gbar() {
    __syncthreads();
    if (threadIdx.x == 0) {
        __threadfence();
        unsigned int old = atomicAdd(&g_bar, 1u);
        unsigned int target = (old / NB + 1u) * NB;   // counter always NB-aligned between barriers
        while (*((volatile unsigned int*)&g_bar) < target) { }
        __threadfence();
    }
    __syncthreads();
}

// ---------------- packed f32x2 helpers ----------------
__device__ __forceinline__ u64 pack2(float lo, float hi) {
    u64 r; asm("mov.b64 %0, {%1, %2};" : "=l"(r) : "f"(lo), "f"(hi)); return r;
}
__device__ __forceinline__ u64 ffma2(u64 a, u64 b, u64 c) {
    u64 r; asm("fma.rn.f32x2 %0, %1, %2, %3;" : "=l"(r) : "l"(a), "l"(b), "l"(c)); return r;
}
__device__ __forceinline__ u64 addf2(u64 a, u64 b) {
    u64 r; asm("add.rn.f32x2 %0, %1, %2;" : "=l"(r) : "l"(a), "l"(b)); return r;
}
__device__ __forceinline__ float2 unpk2(u64 v) {
    float2 f; asm("mov.b64 {%0, %1}, %2;" : "=f"(f.x), "=f"(f.y) : "l"(v)); return f;
}

// ---------------- in-kernel GEMM stage ----------------
// out[:, y*64..] = act(in @ W^T + b) [*dinv].  Tile = 128 nodes x 64 outs.
// Warp layout: all lanes share out-group (8 outs) + 32-node block;
// lane = kslice(2b) x nodesub(3b). Thread = 4 nodes x 8 outs over K/4 slice.
// X loads: 128B contiguous per kslice row; W loads: 32B broadcast (deduped).
// K-partials reduced with shfl_xor(8,16) on packed f32x2 accumulators.
template <int K, bool OUTH>
__device__ void gemm_stage(const float* __restrict__ in, const float* __restrict__ W,
                           const float* __restrict__ bias, void* __restrict__ outp,
                           int n, int youts, int ostride, bool relu, bool scale,
                           float* sW, float* sX) {
    const int KS = K / 4;
    int tid = threadIdx.x;
    int w = tid >> 5, lane = tid & 31;
    int o0 = (w & 7) * 8;                 // per-warp out-group
    int nloc = (w >> 3) * 32 + (lane & 7) * 4;   // local node 0..127
    int kslice = lane >> 3;
    int ntiles = (n + 127) >> 7;

    for (int t = blockIdx.x; t < ntiles * youts; t += NB) {
        int y = t / ntiles, tile = t - y * ntiles;
        const float* Wy = W + (size_t)y * 64 * K;
        __syncthreads();                                  // protect smem from prior iter readers
        for (int idx = tid; idx < 64 * K; idx += NT) {
            int o = idx / K, k = idx - o * K;             // coalesced over k
            sW[k * 68 + o] = Wy[idx];
        }
        int base = tile << 7;
        int nn_max = n - base; if (nn_max > 128) nn_max = 128;
        for (int idx = tid; idx < 128 * K; idx += NT) {
            int nn = idx / K, k = idx - nn * K;
            sX[k * 132 + nn] = (nn < nn_max) ? in[(size_t)(base + nn) * K + k] : 0.f;
        }
        __syncthreads();

        u64 acc[4][4];
        if (kslice == 0) {
            float b0 = bias[y * 64 + o0 + 0], b1 = bias[y * 64 + o0 + 1];
            float b2 = bias[y * 64 + o0 + 2], b3 = bias[y * 64 + o0 + 3];
            float b4 = bias[y * 64 + o0 + 4], b5 = bias[y * 64 + o0 + 5];
            float b6 = bias[y * 64 + o0 + 6], b7 = bias[y * 64 + o0 + 7];
            u64 i0 = pack2(b0, b1), i1 = pack2(b2, b3), i2 = pack2(b4, b5), i3 = pack2(b6, b7);
            #pragma unroll
            for (int j = 0; j < 4; j++) { acc[j][0] = i0; acc[j][1] = i1; acc[j][2] = i2; acc[j][3] = i3; }
        } else {
            #pragma unroll
            for (int j = 0; j < 4; j++)
                #pragma unroll
                for (int p = 0; p < 4; p++) acc[j][p] = 0ull;
        }

        const float* xp = sX + kslice * KS * 132 + nloc;
        const float* wp = sW + kslice * KS * 68 + o0;
        #pragma unroll 4
        for (int kk = 0; kk < KS; kk++) {
            float4 xv = *(const float4*)xp; xp += 132;
            longlong2 w01 = *(const longlong2*)wp;
            longlong2 w23 = *(const longlong2*)(wp + 4); wp += 68;
            u64 xx0 = pack2(xv.x, xv.x), xx1 = pack2(xv.y, xv.y);
            u64 xx2 = pack2(xv.z, xv.z), xx3 = pack2(xv.w, xv.w);
            acc[0][0] = ffma2(xx0, (u64)w01.x, acc[0][0]);
            acc[0][1] = ffma2(xx0, (u64)w01.y, acc[0][1]);
            acc[0][2] = ffma2(xx0, (u64)w23.x, acc[0][2]);
            acc[0][3] = ffma2(xx0, (u64)w23.y, acc[0][3]);
            acc[1][0] = ffma2(xx1, (u64)w01.x, acc[1][0]);
            acc[1][1] = ffma2(xx1, (u64)w01.y, acc[1][1]);
            acc[1][2] = ffma2(xx1, (u64)w23.x, acc[1][2]);
            acc[1][3] = ffma2(xx1, (u64)w23.y, acc[1][3]);
            acc[2][0] = ffma2(xx2, (u64)w01.x, acc[2][0]);
            acc[2][1] = ffma2(xx2, (u64)w01.y, acc[2][1]);
            acc[2][2] = ffma2(xx2, (u64)w23.x, acc[2][2]);
            acc[2][3] = ffma2(xx2, (u64)w23.y, acc[2][3]);
            acc[3][0] = ffma2(xx3, (u64)w01.x, acc[3][0]);
            acc[3][1] = ffma2(xx3, (u64)w01.y, acc[3][1]);
            acc[3][2] = ffma2(xx3, (u64)w23.x, acc[3][2]);
            acc[3][3] = ffma2(xx3, (u64)w23.y, acc[3][3]);
        }

        // reduce K-slices: lanes (l, l^8, l^16, l^24) hold partials of same (nodes, outs)
        #pragma unroll
        for (int j = 0; j < 4; j++) {
            #pragma unroll
            for (int p = 0; p < 4; p++) {
                u64 v = acc[j][p];
                v = addf2(v, __shfl_xor_sync(0xffffffffu, v, 8));
                v = addf2(v, __shfl_xor_sync(0xffffffffu, v, 16));
                acc[j][p] = v;
            }
        }

        if (kslice == 0) {
            #pragma unroll
            for (int j = 0; j < 4; j++) {
                int nl = nloc + j;
                if (nl < nn_max) {
                    int node = base + nl;
                    float2 p0 = unpk2(acc[j][0]), p1 = unpk2(acc[j][1]);
                    float2 p2 = unpk2(acc[j][2]), p3 = unpk2(acc[j][3]);
                    float r[8] = {p0.x, p0.y, p1.x, p1.y, p2.x, p2.y, p3.x, p3.y};
                    if (relu) {
                        #pragma unroll
                        for (int i = 0; i < 8; i++) r[i] = fmaxf(r[i], 0.f);
                    }
                    if (scale) {
                        float s = d_dinv[node];
                        #pragma unroll
                        for (int i = 0; i < 8; i++) r[i] *= s;
                    }
                    if (OUTH) {
                        __half2 h0 = __floats2half2_rn(r[0], r[1]);
                        __half2 h1 = __floats2half2_rn(r[2], r[3]);
                        __half2 h2 = __floats2half2_rn(r[4], r[5]);
                        __half2 h3 = __floats2half2_rn(r[6], r[7]);
                        uint4 u;
                        u.x = *reinterpret_cast<unsigned*>(&h0);
                        u.y = *reinterpret_cast<unsigned*>(&h1);
                        u.z = *reinterpret_cast<unsigned*>(&h2);
                        u.w = *reinterpret_cast<unsigned*>(&h3);
                        *(uint4*)((__half*)outp + (size_t)node * ostride + y * 64 + o0) = u;
                    } else {
                        float* op = (float*)outp + (size_t)node * ostride + y * 64 + o0;
                        *(float4*)(op)     = make_float4(r[0], r[1], r[2], r[3]);
                        *(float4*)(op + 4) = make_float4(r[4], r[5], r[6], r[7]);
                    }
                }
            }
        }
    }
}

// ---------------- in-kernel GCN aggregation from fp16 table: a_i = dinv_i*(sum hs_j + hs_i) ----
template <int D>
__device__ void agg_stage(const __half* __restrict__ hs, float* __restrict__ out, int n) {
    const int LPN = D / 4, NPW = 32 / LPN;
    int lane = threadIdx.x & 31;
    int gw = (blockIdx.x * NT + threadIdx.x) >> 5;
    const int TOTW = NB * (NT / 32);
    int sub = lane / LPN;
    int c = (lane % LPN) * 4;
    for (int b = gw; b * NPW < n; b += TOTW) {
        int node = b * NPW + sub;
        if (node < n) {
            uint2 us = *(const uint2*)(hs + (size_t)node * D + c);   // self (4 halves)
            float2 f0 = __half22float2(*reinterpret_cast<__half2*>(&us.x));
            float2 f1 = __half22float2(*reinterpret_cast<__half2*>(&us.y));
            float4 acc = make_float4(f0.x, f0.y, f1.x, f1.y);
            int j0 = d_off[node], j1 = d_off[node + 1];
            int j = j0;
            for (; j + 3 < j1; j += 4) {
                int i0 = d_srcs[j], i1 = d_srcs[j + 1], i2 = d_srcs[j + 2], i3 = d_srcs[j + 3];
                uint2 u0 = *(const uint2*)(hs + (size_t)i0 * D + c);
                uint2 u1 = *(const uint2*)(hs + (size_t)i1 * D + c);
                uint2 u2 = *(const uint2*)(hs + (size_t)i2 * D + c);
                uint2 u3 = *(const uint2*)(hs + (size_t)i3 * D + c);
                float2 a0 = __half22float2(*reinterpret_cast<__half2*>(&u0.x));
                float2 a1 = __half22float2(*reinterpret_cast<__half2*>(&u0.y));
                float2 b0 = __half22float2(*reinterpret_cast<__half2*>(&u1.x));
                float2 b1 = __half22float2(*reinterpret_cast<__half2*>(&u1.y));
                float2 c0 = __half22float2(*reinterpret_cast<__half2*>(&u2.x));
                float2 c1 = __half22float2(*reinterpret_cast<__half2*>(&u2.y));
                float2 e0 = __half22float2(*reinterpret_cast<__half2*>(&u3.x));
                float2 e1 = __half22float2(*reinterpret_cast<__half2*>(&u3.y));
                acc.x += (a0.x + b0.x) + (c0.x + e0.x);
                acc.y += (a0.y + b0.y) + (c0.y + e0.y);
                acc.z += (a1.x + b1.x) + (c1.x + e1.x);
                acc.w += (a1.y + b1.y) + (c1.y + e1.y);
            }
            for (; j < j1; j++) {
                int i0 = d_srcs[j];
                uint2 u0 = *(const uint2*)(hs + (size_t)i0 * D + c);
                float2 a0 = __half22float2(*reinterpret_cast<__half2*>(&u0.x));
                float2 a1 = __half22float2(*reinterpret_cast<__half2*>(&u0.y));
                acc.x += a0.x; acc.y += a0.y; acc.z += a1.x; acc.w += a1.y;
            }
            float dv = d_dinv[node];
            float4 o;
            o.x = acc.x * dv; o.y = acc.y * dv; o.z = acc.z * dv; o.w = acc.w * dv;
            *(float4*)(out + (size_t)node * D + c) = o;
        }
    }
}

// ---------------- the megakernel ----------------
extern __shared__ float smem_buf[];

__global__ __launch_bounds__(NT, 1) void mega(
    const float* __restrict__ x, const int* __restrict__ src, const int* __restrict__ dst,
    const float* __restrict__ pos,
    const float* __restrict__ emb_w, const float* __restrict__ emb_b,
    const float* __restrict__ c1_w, const float* __restrict__ c1_b,
    const float* __restrict__ c2_w, const float* __restrict__ c2_b,
    const float* __restrict__ bw1, const float* __restrict__ bb1,
    const float* __restrict__ bw2, const float* __restrict__ bb2,
    const float* __restrict__ hw1, const float* __restrict__ hb1,
    const float* __restrict__ hw2, const float* __restrict__ hb2,
    const float* __restrict__ hw3, const float* __restrict__ hb3,
    const float* __restrict__ ew1, const float* __restrict__ eb1,
    const float* __restrict__ ew2, const float* __restrict__ eb2,
    const float* __restrict__ ew3, const float* __restrict__ eb3,
    float* __restrict__ out, int n, int e) {

    __shared__ float s_red[32];
    __shared__ int   s_ired[32];
    __shared__ int   s_all[NB];
    __shared__ int   s_base;

    int tid = threadIdx.x, bid = blockIdx.x;
    int lane = tid & 31, wid = tid >> 5;
    int gt = bid * NT + tid;
    const int GSTR = NB * NT;
    float* sW = smem_buf;                 // [K][68]
    float* sX = smem_buf + 128 * 68;      // [K][132]

    // ---- S0: zero degrees ----
    for (int i = gt; i < n; i += GSTR) d_deg[i] = 0;
    gbar();

    // ---- S1: count in-degrees ----
    for (int i = gt; i < e; i += GSTR) atomicAdd(&d_deg[dst[i]], 1);
    gbar();

    // ---- S2a: per-block chunk sums ----
    int chunk = (n + NB - 1) / NB;        // 338 for n=50000 (requires chunk <= NT)
    int lo = bid * chunk;
    int len = n - lo; if (len < 0) len = 0; if (len > chunk) len = chunk;
    int v = (tid < len) ? d_deg[lo + tid] : 0;
    {
        int wv = v;
        #pragma unroll
        for (int st = 16; st > 0; st >>= 1) wv += __shfl_down_sync(0xffffffffu, wv, st);
        if (lane == 0) s_ired[wid] = wv;
        __syncthreads();
        if (tid < 32) {
            int s = s_ired[tid];
            #pragma unroll
            for (int st = 16; st > 0; st >>= 1) s += __shfl_down_sync(0xffffffffu, s, st);
            if (tid == 0) d_bsum[bid] = s;
        }
    }
    gbar();

    // ---- S2c: base + local exclusive scan -> off/cur/dinv ----
    if (tid < NB) s_all[tid] = d_bsum[tid];
    __syncthreads();
    if (tid == 0) {
        int b = 0;
        for (int j = 0; j < bid; j++) b += s_all[j];
        s_base = b;
        if (bid == NB - 1) d_off[n] = b + s_all[NB - 1];
    }
    {
        int* a = (int*)smem_buf;
        a[tid] = v;
        __syncthreads();
        for (int st = 1; st < NT; st <<= 1) {
            int t = (tid >= st) ? a[tid - st] : 0;
            __syncthreads();
            a[tid] += t;
            __syncthreads();
        }
        int excl = a[tid] - v;
        if (tid < len) {
            int o = s_base + excl;
            d_off[lo + tid] = o;
            d_cur[lo + tid] = o;
            d_dinv[lo + tid] = rsqrtf((float)(v + 1));   // +1 self loop
        }
    }
    gbar();

    // ---- S3: CSR fill + embedding GEMM (fp16 out) ----
    for (int i = gt; i < e; i += GSTR) {
        int dd = dst[i];
        int p = atomicAdd(&d_cur[dd], 1);
        d_srcs[p] = src[i];
    }
    gemm_stage<128, true>(x, emb_w, emb_b, d_h0h, n, 1, 64, true, true, sW, sX);
    gbar();

    // ---- S4: aggregate 64 (fp16 gathers) ----
    agg_stage<64>(d_h0h, d_a0, n);
    gbar();

    // ---- S5: GCN1 GEMM (64->128, relu, pre-scale, fp16 out) ----
    gemm_stage<64, true>(d_a0, c1_w, c1_b, d_l1h, n, 2, 128, true, true, sW, sX);
    gbar();

    // ---- S6: aggregate 128 (fp16 gathers) ----
    agg_stage<128>(d_l1h, d_ag, n);
    gbar();

    // ---- S7: GCN2 GEMM (128->128, relu, fp32 out) ----
    gemm_stage<128, false>(d_ag, c2_w, c2_b, d_l2, n, 2, 128, true, false, sW, sX);
    gbar();

    // ---- S8: tail projections (g in fp16; t1h/t1e fp32 streams) ----
    gemm_stage<128, true >(d_l2, bw1, bb1, d_gh,  n, 1, 64, false, false, sW, sX);
    gemm_stage<128, false>(d_l2, hw1, hb1, d_t1h, n, 1, 64, true,  false, sW, sX);
    gemm_stage<128, false>(d_l2, ew1, eb1, d_t1e, n, 1, 64, true,  false, sW, sX);
    gbar();

    // ---- S9a: tm MLP tail (warp per node) ----
    {
        float* F = smem_buf;
        float* sw2h = F;              // 64*33
        float* sw2e = F + 2112;       // 64*33
        float* s3h  = F + 4224;
        float* s3e  = F + 4256;
        float* sx   = F + 4288;       // 32*128
        for (int idx = tid; idx < 2048; idx += NT) {
            int o = idx >> 6, k = idx & 63;
            sw2h[k * 33 + o] = hw2[idx];
            sw2e[k * 33 + o] = ew2[idx];
        }
        if (tid < 32) s3h[tid] = hw3[tid];
        else if (tid < 64) s3e[tid - 32] = ew3[tid - 32];
        __syncthreads();
        float bh = hb2[lane], be = eb2[lane];
        float b3hv = hb3[0], b3ev = eb3[0];
        float accv = 0.f;
        float* sxw = sx + wid * 128;
        for (int node = bid * 32 + wid; node < n; node += NB * 32) {
            sxw[lane]      = d_t1h[(size_t)node * 64 + lane];
            sxw[32 + lane] = d_t1h[(size_t)node * 64 + 32 + lane];
            sxw[64 + lane] = d_t1e[(size_t)node * 64 + lane];
            sxw[96 + lane] = d_t1e[(size_t)node * 64 + 32 + lane];
            __syncwarp();
            float ah = bh, ae = be;
            #pragma unroll 8
            for (int k = 0; k < 64; k++) {
                ah += sxw[k]      * sw2h[k * 33 + lane];
                ae += sxw[64 + k] * sw2e[k * 33 + lane];
            }
            ah = fmaxf(ah, 0.f) * s3h[lane];
            ae = fmaxf(ae, 0.f) * s3e[lane];
            #pragma unroll
            for (int st = 16; st > 0; st >>= 1) {
                ah += __shfl_down_sync(0xffffffffu, ah, st);
                ae += __shfl_down_sync(0xffffffffu, ae, st);
            }
            if (lane == 0)
                accv += 0.5f * (1.f / (1.f + expf(-(ah + b3hv))) + 1.f / (1.f + expf(-(ae + b3ev))));
            __syncwarp();
        }
        if (lane == 0) s_red[wid] = accv;
        __syncthreads();
        if (tid < 32) {
            float s = s_red[tid];
            #pragma unroll
            for (int st = 16; st > 0; st >>= 1) s += __shfl_down_sync(0xffffffffu, s, st);
            if (tid == 0) d_pt[bid] = (double)s;
        }
        __syncthreads();
    }

    // ---- S9b: bond energy (8 threads/edge, fp16 gathers of g) ----
    {
        int sub = tid & 7;
        float wreg[8];
        #pragma unroll
        for (int j = 0; j < 8; j++) wreg[j] = bw2[sub * 8 + j];
        float b2v = bb2[0];
        const int GROUPS = NB * (NT / 8);
        int g0 = (bid * NT + tid) >> 3;
        float accq = 0.f;
        int cnt = 0;
        for (int eid = g0; eid < e; eid += GROUPS) {
            int s = src[eid], d = dst[eid];
            uint4 us = *(const uint4*)(d_gh + (size_t)s * 64 + sub * 8);   // 8 halves
            uint4 ud = *(const uint4*)(d_gh + (size_t)d * 64 + sub * 8);
            float2 s0 = __half22float2(*reinterpret_cast<__half2*>(&us.x));
            float2 s1 = __half22float2(*reinterpret_cast<__half2*>(&us.y));
            float2 s2 = __half22float2(*reinterpret_cast<__half2*>(&us.z));
            float2 s3 = __half22float2(*reinterpret_cast<__half2*>(&us.w));
            float2 t0 = __half22float2(*reinterpret_cast<__half2*>(&ud.x));
            float2 t1 = __half22float2(*reinterpret_cast<__half2*>(&ud.y));
            float2 t2 = __half22float2(*reinterpret_cast<__half2*>(&ud.z));
            float2 t3 = __half22float2(*reinterpret_cast<__half2*>(&ud.w));
            float p = 0.f;
            p += fmaxf(0.5f * (s0.x + t0.x), 0.f) * wreg[0];
            p += fmaxf(0.5f * (s0.y + t0.y), 0.f) * wreg[1];
            p += fmaxf(0.5f * (s1.x + t1.x), 0.f) * wreg[2];
            p += fmaxf(0.5f * (s1.y + t1.y), 0.f) * wreg[3];
            p += fmaxf(0.5f * (s2.x + t2.x), 0.f) * wreg[4];
            p += fmaxf(0.5f * (s2.y + t2.y), 0.f) * wreg[5];
            p += fmaxf(0.5f * (s3.x + t3.x), 0.f) * wreg[6];
            p += fmaxf(0.5f * (s3.y + t3.y), 0.f) * wreg[7];
            p += __shfl_down_sync(0xffffffffu, p, 4, 8);
            p += __shfl_down_sync(0xffffffffu, p, 2, 8);
            p += __shfl_down_sync(0xffffffffu, p, 1, 8);
            if (sub == 0) {
                float dx = pos[d * 3 + 0] - pos[s * 3 + 0];
                float dy = pos[d * 3 + 1] - pos[s * 3 + 1];
                float dz = pos[d * 3 + 2] - pos[s * 3 + 2];
                float L = sqrtf(dx * dx + dy * dy + dz * dz);
                float t = L - 1.5f;
                accq += p + 1000.f * t * t;
                cnt++;
            }
        }
        float vv = accq + b2v * (float)cnt;   // nonzero only on sub==0 lanes
        vv += __shfl_down_sync(0xffffffffu, vv, 16);
        vv += __shfl_down_sync(0xffffffffu, vv, 8);
        if (lane == 0) s_red[wid] = vv;
        __syncthreads();
        if (tid < 32) {
            float s = s_red[tid];
            #pragma unroll
            for (int st = 16; st > 0; st >>= 1) s += __shfl_down_sync(0xffffffffu, s, st);
            if (tid == 0) d_pb[bid] = (double)s;
        }
    }
    gbar();

    // ---- S10: final scalars (block 0) ----
    if (bid == 0) {
        double* db = (double*)smem_buf;
        if (tid < NB) { db[tid] = d_pb[tid]; db[NB + tid] = d_pt[tid]; }
        __syncthreads();
        if (tid == 0) {
            double eb = 0.0, tm = 0.0;
            for (int i = 0; i < NB; i++) { eb += db[i]; tm += db[NB + i]; }
            tm /= (double)n;
            double et = eb + 3.0;
            if (tm < 0.5) et += (1.0 - tm) * 10.0;
            out[0] = (float)eb;
            out[1] = 1.0f; out[2] = 1.0f; out[3] = 1.0f;
            out[4] = (float)et;
            out[5] = (float)tm;
        }
    }
}

// ---------------- host launcher: ONE kernel launch ----------------
extern "C" void kernel_launch(void* const* d_in, const int* in_sizes, int n_in,
                              void* d_out, int out_size) {
    const float* x     = (const float*)d_in[0];
    const int*   ei    = (const int*)  d_in[1];
    const float* pos   = (const float*)d_in[2];
    /* d_in[3] = batch (unused) */
    const float* emb_w = (const float*)d_in[4];
    const float* emb_b = (const float*)d_in[5];
    const float* c1_w  = (const float*)d_in[6];
    const float* c1_b  = (const float*)d_in[7];
    const float* c2_w  = (const float*)d_in[8];
    const float* c2_b  = (const float*)d_in[9];
    const float* bw1   = (const float*)d_in[10];
    const float* bb1   = (const float*)d_in[11];
    const float* bw2   = (const float*)d_in[12];
    const float* bb2   = (const float*)d_in[13];
    const float* hw1   = (const float*)d_in[14];
    const float* hb1   = (const float*)d_in[15];
    const float* hw2   = (const float*)d_in[16];
    const float* hb2   = (const float*)d_in[17];
    const float* hw3   = (const float*)d_in[18];
    const float* hb3   = (const float*)d_in[19];
    const float* ew1   = (const float*)d_in[20];
    const float* eb1   = (const float*)d_in[21];
    const float* ew2   = (const float*)d_in[22];
    const float* eb2   = (const float*)d_in[23];
    const float* ew3   = (const float*)d_in[24];
    const float* eb3   = (const float*)d_in[25];

    int n = in_sizes[0] / 128;
    int e = in_sizes[1] / 2;
    const int* src = ei;
    const int* dst = ei + e;
    float* out = (float*)d_out;

    const int SMEM = (128 * 68 + 128 * 132) * 4;   // 102,400 B
    cudaFuncSetAttribute((const void*)mega, cudaFuncAttributeMaxDynamicSharedMemorySize, SMEM);

    mega<<<NB, NT, SMEM>>>(x, src, dst, pos,
                           emb_w, emb_b, c1_w, c1_b, c2_w, c2_b,
                           bw1, bb1, bw2, bb2,
                           hw1, hb1, hw2, hb2, hw3, hb3,
                           ew1, eb1, ew2, eb2, ew3, eb3,
                           out, n, e);
}

// round 10
// speedup vs baseline: 23.6943x; 1.0687x over previous
#include <cuda_runtime.h>
#include <cuda_fp16.h>
#include <math.h>

#define NB 148
#define NT 1024
#define NMAX 50000
#define EMAX 1600000

typedef unsigned long long u64;

// ---------------- scratch (device globals) ----------------
__device__ __half d_h0h[(size_t)NMAX * 64];   // emb out (pre-scaled by dinv), fp16
__device__ __half d_a0h[(size_t)NMAX * 64];   // aggregated 64, fp16
__device__ __half d_l1h[(size_t)NMAX * 128];  // c1 out (pre-scaled), fp16
__device__ __half d_agh[(size_t)NMAX * 128];  // aggregated 128, fp16
__device__ __half d_l2h[(size_t)NMAX * 128];  // c2 out = final features, fp16
__device__ __half d_gh [(size_t)NMAX * 64];   // bond projection, fp16
__device__ float  d_t1h[(size_t)NMAX * 64];
__device__ float  d_t1e[(size_t)NMAX * 64];
__device__ float  d_dinv[NMAX];
__device__ int    d_deg[NMAX];
__device__ int    d_off[NMAX + 1];
__device__ int    d_cur[NMAX];
__device__ int    d_srcs[EMAX];
__device__ int    d_bsum[NB];
__device__ double d_pb[NB];
__device__ double d_pt[NB];
__device__ unsigned int g_bar;               // monotonic across replays

// ---------------- grid barrier ----------------
__device__ __forceinline__ void gbar() {
    __syncthreads();
    if (threadIdx.x == 0) {
        __threadfence();
        unsigned int old = atomicAdd(&g_bar, 1u);
        unsigned int target = (old / NB + 1u) * NB;
        while (*((volatile unsigned int*)&g_bar) < target) { }
        __threadfence();
    }
    __syncthreads();
}

// ---------------- packed f32x2 helpers ----------------
__device__ __forceinline__ u64 pack2(float lo, float hi) {
    u64 r; asm("mov.b64 %0, {%1, %2};" : "=l"(r) : "f"(lo), "f"(hi)); return r;
}
__device__ __forceinline__ u64 ffma2(u64 a, u64 b, u64 c) {
    u64 r; asm("fma.rn.f32x2 %0, %1, %2, %3;" : "=l"(r) : "l"(a), "l"(b), "l"(c)); return r;
}
__device__ __forceinline__ u64 addf2(u64 a, u64 b) {
    u64 r; asm("add.rn.f32x2 %0, %1, %2;" : "=l"(r) : "l"(a), "l"(b)); return r;
}
__device__ __forceinline__ float2 unpk2(u64 v) {
    float2 f; asm("mov.b64 {%0, %1}, %2;" : "=f"(f.x), "=f"(f.y) : "l"(v)); return f;
}
__device__ __forceinline__ float2 h22f2(unsigned u) {
    __half2 h = *reinterpret_cast<__half2*>(&u);
    return __half22float2(h);
}

// ---------------- multi-output GEMM: stage X once, loop weight specs ----------------
// X in fp16 (or fp32 converted at staging). smem X layout: word[k2*132 + node] = half2(x[node][2k2], x[node][2k2+1]).
// Warp: out-group o0 (8 outs), 32-node block, lane = kslice(2b) x nodesub(3b); thread = 4 nodes x 8 outs.
// flags: 1=relu, 2=scale(dinv), 4=fp16 out
template <int K, bool CVT, int NS>
__device__ __forceinline__ void gemm_multi(
    const void* xin,
    const float* const* Ws, const float* const* Bs,
    void* const* Os, const int* osts, const unsigned* flg,
    int n, float* sW, unsigned* sX) {

    const int K2 = K / 2, KS2 = K / 8;
    int tid = threadIdx.x;
    int w = tid >> 5, lane = tid & 31;
    int o0 = (w & 7) * 8;
    int nloc = (w >> 3) * 32 + (lane & 7) * 4;
    int kslice = lane >> 3;
    int ntiles = (n + 127) >> 7;

    for (int t = blockIdx.x; t < ntiles; t += NB) {
        int base = t << 7;
        int nn_max = n - base; if (nn_max > 128) nn_max = 128;
        __syncthreads();                              // protect smem from prior readers
        // ---- stage X (once per tile) ----
        if (CVT) {
            const float* xf = (const float*)xin;
            for (int idx = tid; idx < 128 * K2; idx += NT) {
                int nn = idx / K2, k2 = idx - nn * K2;
                float2 v = (nn < nn_max) ? *(const float2*)(xf + (size_t)(base + nn) * K + 2 * k2)
                                         : make_float2(0.f, 0.f);
                __half2 h = __floats2half2_rn(v.x, v.y);
                sX[k2 * 132 + nn] = *reinterpret_cast<unsigned*>(&h);
            }
        } else {
            const __half* xh = (const __half*)xin;
            for (int idx = tid; idx < 128 * K2; idx += NT) {
                int nn = idx / K2, k2 = idx - nn * K2;
                sX[k2 * 132 + nn] = (nn < nn_max)
                    ? *(const unsigned*)(xh + (size_t)(base + nn) * K + 2 * k2) : 0u;
            }
        }
        // ---- loop over output specs ----
        #pragma unroll
        for (int s = 0; s < NS; s++) {
            if (s > 0) __syncthreads();               // prev compute done before sW overwrite
            const float* Wp = Ws[s];
            for (int idx = tid; idx < 64 * K; idx += NT) {
                int o = idx / K, k = idx - o * K;     // coalesced over k
                sW[k * 68 + o] = Wp[idx];
            }
            __syncthreads();

            u64 acc[4][4];
            if (kslice == 0) {
                const float* Bp = Bs[s];
                u64 i0 = pack2(Bp[o0 + 0], Bp[o0 + 1]);
                u64 i1 = pack2(Bp[o0 + 2], Bp[o0 + 3]);
                u64 i2 = pack2(Bp[o0 + 4], Bp[o0 + 5]);
                u64 i3 = pack2(Bp[o0 + 6], Bp[o0 + 7]);
                #pragma unroll
                for (int j = 0; j < 4; j++) { acc[j][0] = i0; acc[j][1] = i1; acc[j][2] = i2; acc[j][3] = i3; }
            } else {
                #pragma unroll
                for (int j = 0; j < 4; j++)
                    #pragma unroll
                    for (int p = 0; p < 4; p++) acc[j][p] = 0ull;
            }

            const unsigned* xp = sX + (kslice * KS2) * 132 + nloc;
            const float* wp = sW + (kslice * KS2 * 2) * 68 + o0;
            #pragma unroll 2
            for (int kk = 0; kk < KS2; kk++) {
                uint4 xq = *(const uint4*)xp; xp += 132;
                // even k
                {
                    longlong2 w0 = *(const longlong2*)wp;
                    longlong2 w1 = *(const longlong2*)(wp + 4);
                    float2 f0 = h22f2(xq.x), f1 = h22f2(xq.y), f2 = h22f2(xq.z), f3 = h22f2(xq.w);
                    u64 x0 = pack2(f0.x, f0.x), x1 = pack2(f1.x, f1.x);
                    u64 x2 = pack2(f2.x, f2.x), x3 = pack2(f3.x, f3.x);
                    acc[0][0] = ffma2(x0, (u64)w0.x, acc[0][0]); acc[0][1] = ffma2(x0, (u64)w0.y, acc[0][1]);
                    acc[0][2] = ffma2(x0, (u64)w1.x, acc[0][2]); acc[0][3] = ffma2(x0, (u64)w1.y, acc[0][3]);
                    acc[1][0] = ffma2(x1, (u64)w0.x, acc[1][0]); acc[1][1] = ffma2(x1, (u64)w0.y, acc[1][1]);
                    acc[1][2] = ffma2(x1, (u64)w1.x, acc[1][2]); acc[1][3] = ffma2(x1, (u64)w1.y, acc[1][3]);
                    acc[2][0] = ffma2(x2, (u64)w0.x, acc[2][0]); acc[2][1] = ffma2(x2, (u64)w0.y, acc[2][1]);
                    acc[2][2] = ffma2(x2, (u64)w1.x, acc[2][2]); acc[2][3] = ffma2(x2, (u64)w1.y, acc[2][3]);
                    acc[3][0] = ffma2(x3, (u64)w0.x, acc[3][0]); acc[3][1] = ffma2(x3, (u64)w0.y, acc[3][1]);
                    acc[3][2] = ffma2(x3, (u64)w1.x, acc[3][2]); acc[3][3] = ffma2(x3, (u64)w1.y, acc[3][3]);
                }
                // odd k
                {
                    longlong2 w0 = *(const longlong2*)(wp + 68);
                    longlong2 w1 = *(const longlong2*)(wp + 72);
                    float2 f0 = h22f2(xq.x), f1 = h22f2(xq.y), f2 = h22f2(xq.z), f3 = h22f2(xq.w);
                    u64 x0 = pack2(f0.y, f0.y), x1 = pack2(f1.y, f1.y);
                    u64 x2 = pack2(f2.y, f2.y), x3 = pack2(f3.y, f3.y);
                    acc[0][0] = ffma2(x0, (u64)w0.x, acc[0][0]); acc[0][1] = ffma2(x0, (u64)w0.y, acc[0][1]);
                    acc[0][2] = ffma2(x0, (u64)w1.x, acc[0][2]); acc[0][3] = ffma2(x0, (u64)w1.y, acc[0][3]);
                    acc[1][0] = ffma2(x1, (u64)w0.x, acc[1][0]); acc[1][1] = ffma2(x1, (u64)w0.y, acc[1][1]);
                    acc[1][2] = ffma2(x1, (u64)w1.x, acc[1][2]); acc[1][3] = ffma2(x1, (u64)w1.y, acc[1][3]);
                    acc[2][0] = ffma2(x2, (u64)w0.x, acc[2][0]); acc[2][1] = ffma2(x2, (u64)w0.y, acc[2][1]);
                    acc[2][2] = ffma2(x2, (u64)w1.x, acc[2][2]); acc[2][3] = ffma2(x2, (u64)w1.y, acc[2][3]);
                    acc[3][0] = ffma2(x3, (u64)w0.x, acc[3][0]); acc[3][1] = ffma2(x3, (u64)w0.y, acc[3][1]);
                    acc[3][2] = ffma2(x3, (u64)w1.x, acc[3][2]); acc[3][3] = ffma2(x3, (u64)w1.y, acc[3][3]);
                }
                wp += 136;
            }

            // reduce K-slices across lanes (l, l^8, l^16, l^24)
            #pragma unroll
            for (int j = 0; j < 4; j++) {
                #pragma unroll
                for (int p = 0; p < 4; p++) {
                    u64 v = acc[j][p];
                    v = addf2(v, __shfl_xor_sync(0xffffffffu, v, 8));
                    v = addf2(v, __shfl_xor_sync(0xffffffffu, v, 16));
                    acc[j][p] = v;
                }
            }

            if (kslice == 0) {
                unsigned f = flg[s];
                int ost = osts[s];
                #pragma unroll
                for (int j = 0; j < 4; j++) {
                    int nl = nloc + j;
                    if (nl < nn_max) {
                        int node = base + nl;
                        float2 p0 = unpk2(acc[j][0]), p1 = unpk2(acc[j][1]);
                        float2 p2 = unpk2(acc[j][2]), p3 = unpk2(acc[j][3]);
                        float r[8] = {p0.x, p0.y, p1.x, p1.y, p2.x, p2.y, p3.x, p3.y};
                        if (f & 1u) {
                            #pragma unroll
                            for (int i = 0; i < 8; i++) r[i] = fmaxf(r[i], 0.f);
                        }
                        if (f & 2u) {
                            float sc = d_dinv[node];
                            #pragma unroll
                            for (int i = 0; i < 8; i++) r[i] *= sc;
                        }
                        if (f & 4u) {
                            __half2 h0 = __floats2half2_rn(r[0], r[1]);
                            __half2 h1 = __floats2half2_rn(r[2], r[3]);
                            __half2 h2 = __floats2half2_rn(r[4], r[5]);
                            __half2 h3 = __floats2half2_rn(r[6], r[7]);
                            uint4 u;
                            u.x = *reinterpret_cast<unsigned*>(&h0);
                            u.y = *reinterpret_cast<unsigned*>(&h1);
                            u.z = *reinterpret_cast<unsigned*>(&h2);
                            u.w = *reinterpret_cast<unsigned*>(&h3);
                            *(uint4*)((__half*)Os[s] + (size_t)node * ost + o0) = u;
                        } else {
                            float* op = (float*)Os[s] + (size_t)node * ost + o0;
                            *(float4*)(op)     = make_float4(r[0], r[1], r[2], r[3]);
                            *(float4*)(op + 4) = make_float4(r[4], r[5], r[6], r[7]);
                        }
                    }
                }
            }
        }
    }
}

// ---------------- GCN aggregation (fp16 in, fp16 out): a_i = dinv_i*(sum hs_j + hs_i) ----
template <int D>
__device__ void agg_stage(const __half* __restrict__ hs, __half* __restrict__ out, int n) {
    const int LPN = D / 4, NPW = 32 / LPN;
    int lane = threadIdx.x & 31;
    int gw = (blockIdx.x * NT + threadIdx.x) >> 5;
    const int TOTW = NB * (NT / 32);
    int sub = lane / LPN;
    int c = (lane % LPN) * 4;
    for (int b = gw; b * NPW < n; b += TOTW) {
        int node = b * NPW + sub;
        if (node < n) {
            uint2 us = *(const uint2*)(hs + (size_t)node * D + c);
            float2 f0 = h22f2(us.x), f1 = h22f2(us.y);
            float4 acc = make_float4(f0.x, f0.y, f1.x, f1.y);
            int j0 = d_off[node], j1 = d_off[node + 1];
            int j = j0;
            for (; j + 3 < j1; j += 4) {
                int i0 = d_srcs[j], i1 = d_srcs[j + 1], i2 = d_srcs[j + 2], i3 = d_srcs[j + 3];
                uint2 u0 = *(const uint2*)(hs + (size_t)i0 * D + c);
                uint2 u1 = *(const uint2*)(hs + (size_t)i1 * D + c);
                uint2 u2 = *(const uint2*)(hs + (size_t)i2 * D + c);
                uint2 u3 = *(const uint2*)(hs + (size_t)i3 * D + c);
                float2 a0 = h22f2(u0.x), a1 = h22f2(u0.y);
                float2 b0 = h22f2(u1.x), b1 = h22f2(u1.y);
                float2 c0 = h22f2(u2.x), c1 = h22f2(u2.y);
                float2 e0 = h22f2(u3.x), e1 = h22f2(u3.y);
                acc.x += (a0.x + b0.x) + (c0.x + e0.x);
                acc.y += (a0.y + b0.y) + (c0.y + e0.y);
                acc.z += (a1.x + b1.x) + (c1.x + e1.x);
                acc.w += (a1.y + b1.y) + (c1.y + e1.y);
            }
            for (; j < j1; j++) {
                int i0 = d_srcs[j];
                uint2 u0 = *(const uint2*)(hs + (size_t)i0 * D + c);
                float2 a0 = h22f2(u0.x), a1 = h22f2(u0.y);
                acc.x += a0.x; acc.y += a0.y; acc.z += a1.x; acc.w += a1.y;
            }
            float dv = d_dinv[node];
            __half2 o0 = __floats2half2_rn(acc.x * dv, acc.y * dv);
            __half2 o1 = __floats2half2_rn(acc.z * dv, acc.w * dv);
            uint2 u;
            u.x = *reinterpret_cast<unsigned*>(&o0);
            u.y = *reinterpret_cast<unsigned*>(&o1);
            *(uint2*)(out + (size_t)node * D + c) = u;
        }
    }
}

// ---------------- the megakernel ----------------
extern __shared__ float smem_buf[];

__global__ __launch_bounds__(NT, 1) void mega(
    const float* __restrict__ x, const int* __restrict__ src, const int* __restrict__ dst,
    const float* __restrict__ pos,
    const float* __restrict__ emb_w, const float* __restrict__ emb_b,
    const float* __restrict__ c1_w, const float* __restrict__ c1_b,
    const float* __restrict__ c2_w, const float* __restrict__ c2_b,
    const float* __restrict__ bw1, const float* __restrict__ bb1,
    const float* __restrict__ bw2, const float* __restrict__ bb2,
    const float* __restrict__ hw1, const float* __restrict__ hb1,
    const float* __restrict__ hw2, const float* __restrict__ hb2,
    const float* __restrict__ hw3, const float* __restrict__ hb3,
    const float* __restrict__ ew1, const float* __restrict__ eb1,
    const float* __restrict__ ew2, const float* __restrict__ eb2,
    const float* __restrict__ ew3, const float* __restrict__ eb3,
    float* __restrict__ out, int n, int e) {

    __shared__ float s_red[32];
    __shared__ int   s_ired[32];
    __shared__ int   s_all[NB];
    __shared__ int   s_base;

    int tid = threadIdx.x, bid = blockIdx.x;
    int lane = tid & 31, wid = tid >> 5;
    int gt = bid * NT + tid;
    const int GSTR = NB * NT;
    float* sW = smem_buf;                         // [K][68] fp32
    unsigned* sXu = (unsigned*)(smem_buf + 128 * 68);   // [K/2][132] half2 words

    // ---- S0: zero degrees ----
    for (int i = gt; i < n; i += GSTR) d_deg[i] = 0;
    gbar();

    // ---- S1: count in-degrees ----
    for (int i = gt; i < e; i += GSTR) atomicAdd(&d_deg[dst[i]], 1);
    gbar();

    // ---- S2a: per-block chunk sums ----
    int chunk = (n + NB - 1) / NB;
    int lo = bid * chunk;
    int len = n - lo; if (len < 0) len = 0; if (len > chunk) len = chunk;
    int v = (tid < len) ? d_deg[lo + tid] : 0;
    {
        int wv = v;
        #pragma unroll
        for (int st = 16; st > 0; st >>= 1) wv += __shfl_down_sync(0xffffffffu, wv, st);
        if (lane == 0) s_ired[wid] = wv;
        __syncthreads();
        if (tid < 32) {
            int s = s_ired[tid];
            #pragma unroll
            for (int st = 16; st > 0; st >>= 1) s += __shfl_down_sync(0xffffffffu, s, st);
            if (tid == 0) d_bsum[bid] = s;
        }
    }
    gbar();

    // ---- S2c: base + local exclusive scan -> off/cur/dinv ----
    if (tid < NB) s_all[tid] = d_bsum[tid];
    __syncthreads();
    if (tid == 0) {
        int b = 0;
        for (int j = 0; j < bid; j++) b += s_all[j];
        s_base = b;
        if (bid == NB - 1) d_off[n] = b + s_all[NB - 1];
    }
    {
        int* a = (int*)smem_buf;
        a[tid] = v;
        __syncthreads();
        for (int st = 1; st < NT; st <<= 1) {
            int t = (tid >= st) ? a[tid - st] : 0;
            __syncthreads();
            a[tid] += t;
            __syncthreads();
        }
        int excl = a[tid] - v;
        if (tid < len) {
            int o = s_base + excl;
            d_off[lo + tid] = o;
            d_cur[lo + tid] = o;
            d_dinv[lo + tid] = rsqrtf((float)(v + 1));
        }
    }
    gbar();

    // ---- S3: CSR fill + embedding GEMM (fp32 x converted at staging) ----
    for (int i = gt; i < e; i += GSTR) {
        int dd = dst[i];
        int p = atomicAdd(&d_cur[dd], 1);
        d_srcs[p] = src[i];
    }
    {
        const float* Ws[1] = {emb_w}; const float* Bs[1] = {emb_b};
        void* Os[1] = {(void*)d_h0h}; int ost[1] = {64}; unsigned fl[1] = {1u | 2u | 4u};
        gemm_multi<128, true, 1>(x, Ws, Bs, Os, ost, fl, n, sW, sXu);
    }
    gbar();

    // ---- S4: aggregate 64 ----
    agg_stage<64>(d_h0h, d_a0h, n);
    gbar();

    // ---- S5: GCN1 GEMM (64->128, relu, pre-scale) ----
    {
        const float* Ws[2] = {c1_w, c1_w + 64 * 64};
        const float* Bs[2] = {c1_b, c1_b + 64};
        void* Os[2] = {(void*)d_l1h, (void*)(d_l1h + 64)};
        int ost[2] = {128, 128}; unsigned fl[2] = {7u, 7u};
        gemm_multi<64, false, 2>(d_a0h, Ws, Bs, Os, ost, fl, n, sW, sXu);
    }
    gbar();

    // ---- S6: aggregate 128 ----
    agg_stage<128>(d_l1h, d_agh, n);
    gbar();

    // ---- S7: GCN2 GEMM (128->128, relu) ----
    {
        const float* Ws[2] = {c2_w, c2_w + 64 * 128};
        const float* Bs[2] = {c2_b, c2_b + 64};
        void* Os[2] = {(void*)d_l2h, (void*)(d_l2h + 64)};
        int ost[2] = {128, 128}; unsigned fl[2] = {1u | 4u, 1u | 4u};
        gemm_multi<128, false, 2>(d_agh, Ws, Bs, Os, ost, fl, n, sW, sXu);
    }
    gbar();

    // ---- S8: tail projections (X = l2 staged once, 3 weight sets) ----
    {
        const float* Ws[3] = {bw1, hw1, ew1};
        const float* Bs[3] = {bb1, hb1, eb1};
        void* Os[3] = {(void*)d_gh, (void*)d_t1h, (void*)d_t1e};
        int ost[3] = {64, 64, 64}; unsigned fl[3] = {4u, 1u, 1u};
        gemm_multi<128, false, 3>(d_l2h, Ws, Bs, Os, ost, fl, n, sW, sXu);
    }
    gbar();

    // ---- S9a: tm MLP tail (warp per node) ----
    {
        float* F = smem_buf;
        float* sw2h = F;              // 64*33
        float* sw2e = F + 2112;       // 64*33
        float* s3h  = F + 4224;
        float* s3e  = F + 4256;
        float* sx   = F + 4288;       // 32*128
        for (int idx = tid; idx < 2048; idx += NT) {
            int o = idx >> 6, k = idx & 63;
            sw2h[k * 33 + o] = hw2[idx];
            sw2e[k * 33 + o] = ew2[idx];
        }
        if (tid < 32) s3h[tid] = hw3[tid];
        else if (tid < 64) s3e[tid - 32] = ew3[tid - 32];
        __syncthreads();
        float bh = hb2[lane], be = eb2[lane];
        float b3hv = hb3[0], b3ev = eb3[0];
        float accv = 0.f;
        float* sxw = sx + wid * 128;
        for (int node = bid * 32 + wid; node < n; node += NB * 32) {
            sxw[lane]      = d_t1h[(size_t)node * 64 + lane];
            sxw[32 + lane] = d_t1h[(size_t)node * 64 + 32 + lane];
            sxw[64 + lane] = d_t1e[(size_t)node * 64 + lane];
            sxw[96 + lane] = d_t1e[(size_t)node * 64 + 32 + lane];
            __syncwarp();
            float ah = bh, ae = be;
            #pragma unroll 8
            for (int k = 0; k < 64; k++) {
                ah += sxw[k]      * sw2h[k * 33 + lane];
                ae += sxw[64 + k] * sw2e[k * 33 + lane];
            }
            ah = fmaxf(ah, 0.f) * s3h[lane];
            ae = fmaxf(ae, 0.f) * s3e[lane];
            #pragma unroll
            for (int st = 16; st > 0; st >>= 1) {
                ah += __shfl_down_sync(0xffffffffu, ah, st);
                ae += __shfl_down_sync(0xffffffffu, ae, st);
            }
            if (lane == 0)
                accv += 0.5f * (1.f / (1.f + expf(-(ah + b3hv))) + 1.f / (1.f + expf(-(ae + b3ev))));
            __syncwarp();
        }
        if (lane == 0) s_red[wid] = accv;
        __syncthreads();
        if (tid < 32) {
            float s = s_red[tid];
            #pragma unroll
            for (int st = 16; st > 0; st >>= 1) s += __shfl_down_sync(0xffffffffu, s, st);
            if (tid == 0) d_pt[bid] = (double)s;
        }
        __syncthreads();
    }

    // ---- S9b: bond energy (8 threads/edge, fp16 gathers of g) ----
    {
        int sub = tid & 7;
        float wreg[8];
        #pragma unroll
        for (int j = 0; j < 8; j++) wreg[j] = bw2[sub * 8 + j];
        float b2v = bb2[0];
        const int GROUPS = NB * (NT / 8);
        int g0 = (bid * NT + tid) >> 3;
        float accq = 0.f;
        int cnt = 0;
        for (int eid = g0; eid < e; eid += GROUPS) {
            int s = src[eid], d = dst[eid];
            uint4 us = *(const uint4*)(d_gh + (size_t)s * 64 + sub * 8);
            uint4 ud = *(const uint4*)(d_gh + (size_t)d * 64 + sub * 8);
            float2 s0 = h22f2(us.x), s1 = h22f2(us.y), s2 = h22f2(us.z), s3 = h22f2(us.w);
            float2 t0 = h22f2(ud.x), t1 = h22f2(ud.y), t2 = h22f2(ud.z), t3 = h22f2(ud.w);
            float p = 0.f;
            p += fmaxf(0.5f * (s0.x + t0.x), 0.f) * wreg[0];
            p += fmaxf(0.5f * (s0.y + t0.y), 0.f) * wreg[1];
            p += fmaxf(0.5f * (s1.x + t1.x), 0.f) * wreg[2];
            p += fmaxf(0.5f * (s1.y + t1.y), 0.f) * wreg[3];
            p += fmaxf(0.5f * (s2.x + t2.x), 0.f) * wreg[4];
            p += fmaxf(0.5f * (s2.y + t2.y), 0.f) * wreg[5];
            p += fmaxf(0.5f * (s3.x + t3.x), 0.f) * wreg[6];
            p += fmaxf(0.5f * (s3.y + t3.y), 0.f) * wreg[7];
            p += __shfl_down_sync(0xffffffffu, p, 4, 8);
            p += __shfl_down_sync(0xffffffffu, p, 2, 8);
            p += __shfl_down_sync(0xffffffffu, p, 1, 8);
            if (sub == 0) {
                float dx = pos[d * 3 + 0] - pos[s * 3 + 0];
                float dy = pos[d * 3 + 1] - pos[s * 3 + 1];
                float dz = pos[d * 3 + 2] - pos[s * 3 + 2];
                float L = sqrtf(dx * dx + dy * dy + dz * dz);
                float t = L - 1.5f;
                accq += p + 1000.f * t * t;
                cnt++;
            }
        }
        float vv = accq + b2v * (float)cnt;
        vv += __shfl_down_sync(0xffffffffu, vv, 16);
        vv += __shfl_down_sync(0xffffffffu, vv, 8);
        if (lane == 0) s_red[wid] = vv;
        __syncthreads();
        if (tid < 32) {
            float s = s_red[tid];
            #pragma unroll
            for (int st = 16; st > 0; st >>= 1) s += __shfl_down_sync(0xffffffffu, s, st);
            if (tid == 0) d_pb[bid] = (double)s;
        }
    }
    gbar();

    // ---- S10: final scalars (block 0) ----
    if (bid == 0) {
        double* db = (double*)smem_buf;
        if (tid < NB) { db[tid] = d_pb[tid]; db[NB + tid] = d_pt[tid]; }
        __syncthreads();
        if (tid == 0) {
            double eb = 0.0, tm = 0.0;
            for (int i = 0; i < NB; i++) { eb += db[i]; tm += db[NB + i]; }
            tm /= (double)n;
            double et = eb + 3.0;
            if (tm < 0.5) et += (1.0 - tm) * 10.0;
            out[0] = (float)eb;
            out[1] = 1.0f; out[2] = 1.0f; out[3] = 1.0f;
            out[4] = (float)et;
            out[5] = (float)tm;
        }
    }
}

// ---------------- host launcher: ONE kernel launch ----------------
extern "C" void kernel_launch(void* const* d_in, const int* in_sizes, int n_in,
                              void* d_out, int out_size) {
    const float* x     = (const float*)d_in[0];
    const int*   ei    = (const int*)  d_in[1];
    const float* pos   = (const float*)d_in[2];
    /* d_in[3] = batch (unused) */
    const float* emb_w = (const float*)d_in[4];
    const float* emb_b = (const float*)d_in[5];
    const float* c1_w  = (const float*)d_in[6];
    const float* c1_b  = (const float*)d_in[7];
    const float* c2_w  = (const float*)d_in[8];
    const float* c2_b  = (const float*)d_in[9];
    const float* bw1   = (const float*)d_in[10];
    const float* bb1   = (const float*)d_in[11];
    const float* bw2   = (const float*)d_in[12];
    const float* bb2   = (const float*)d_in[13];
    const float* hw1   = (const float*)d_in[14];
    const float* hb1   = (const float*)d_in[15];
    const float* hw2   = (const float*)d_in[16];
    const float* hb2   = (const float*)d_in[17];
    const float* hw3   = (const float*)d_in[18];
    const float* hb3   = (const float*)d_in[19];
    const float* ew1   = (const float*)d_in[20];
    const float* eb1   = (const float*)d_in[21];
    const float* ew2   = (const float*)d_in[22];
    const float* eb2   = (const float*)d_in[23];
    const float* ew3   = (const float*)d_in[24];
    const float* eb3   = (const float*)d_in[25];

    int n = in_sizes[0] / 128;
    int e = in_sizes[1] / 2;
    const int* src = ei;
    const int* dst = ei + e;
    float* out = (float*)d_out;

    const int SMEM = (128 * 68) * 4 + (64 * 132) * 4;   // sW fp32 + sX half2 words = 68,608 B
    cudaFuncSetAttribute((const void*)mega, cudaFuncAttributeMaxDynamicSharedMemorySize, SMEM);

    mega<<<NB, NT, SMEM>>>(x, src, dst, pos,
                           emb_w, emb_b, c1_w, c1_b, c2_w, c2_b,
                           bw1, bb1, bw2, bb2,
                           hw1, hb1, hw2, hb2, hw3, hb3,
                           ew1, eb1, ew2, eb2, ew3, eb3,
                           out, n, e);
}

// round 11
// speedup vs baseline: 33.6957x; 1.4221x over previous
#include <cuda_runtime.h>
#include <cuda_fp16.h>
#include <math.h>

#define NB 148
#define NT 1024
#define NMAX 50000
#define EMAX 1600000

typedef unsigned long long u64;

// ---------------- scratch (device globals) ----------------
__device__ __half d_h0h[(size_t)NMAX * 64];   // emb out (pre-scaled by dinv), fp16
__device__ __half d_a0h[(size_t)NMAX * 64];   // aggregated 64, fp16
__device__ __half d_l1h[(size_t)NMAX * 128];  // c1 out (pre-scaled), fp16
__device__ __half d_agh[(size_t)NMAX * 128];  // aggregated 128, fp16
__device__ __half d_l2h[(size_t)NMAX * 128];  // c2 out = final features, fp16
__device__ __half d_gh [(size_t)NMAX * 64];   // bond projection, fp16
__device__ float  d_t1h[(size_t)NMAX * 64];
__device__ float  d_t1e[(size_t)NMAX * 64];
__device__ float  d_dinv[NMAX];
__device__ int    d_deg[NMAX];
__device__ int    d_off[NMAX + 1];
__device__ int    d_cur[NMAX];
__device__ int    d_srcs[EMAX];
__device__ int    d_bsum[NB];
__device__ double d_pb[NB];
__device__ double d_pt[NB];
__device__ unsigned int g_bar;               // monotonic across replays

// ---------------- grid barrier ----------------
__device__ __forceinline__ void gbar() {
    __syncthreads();
    if (threadIdx.x == 0) {
        __threadfence();
        unsigned int old = atomicAdd(&g_bar, 1u);
        unsigned int target = (old / NB + 1u) * NB;
        while (*((volatile unsigned int*)&g_bar) < target) { }
        __threadfence();
    }
    __syncthreads();
}

__device__ __forceinline__ float2 h22f2(unsigned u) {
    __half2 h = *reinterpret_cast<__half2*>(&u);
    return __half22float2(h);
}

__device__ __forceinline__ unsigned smem_u32(const void* p) {
    return (unsigned)__cvta_generic_to_shared(p);
}

__device__ __forceinline__ void mma16816(float* d,
                                         unsigned a0, unsigned a1, unsigned a2, unsigned a3,
                                         unsigned b0, unsigned b1) {
    asm volatile(
        "mma.sync.aligned.m16n8k16.row.col.f32.f16.f16.f32 "
        "{%0,%1,%2,%3}, {%4,%5,%6,%7}, {%8,%9}, {%0,%1,%2,%3};"
        : "+f"(d[0]), "+f"(d[1]), "+f"(d[2]), "+f"(d[3])
        : "r"(a0), "r"(a1), "r"(a2), "r"(a3), "r"(b0), "r"(b1));
}

// ---------------- tensor-core multi-output GEMM: stage X once, loop weight specs ----------------
// out[:, 0..64) = act(in[:, 0..K) @ W[64,K]^T + bias) [*dinv], per spec.
// X in smem as [node][k] fp16 with 16B-chunk XOR swizzle (chunk ^= node&7) -> conflict-free ldmatrix.
// W in smem as [o][K+8] fp16 (direct convert of row-major W) -> conflict-free LDS.32 B-fragments.
// Warp tile: 16 nodes x 16 outs (2x m16n8k16 per k16 step). flags: 1=relu, 2=scale(dinv), 4=fp16 out.
template <int K, bool CVT, int NS>
__device__ __forceinline__ void gemm_multi(
    const void* xin,
    const float* const* Ws, const float* const* Bs,
    void* const* Os, const int* osts, const unsigned* flg,
    int n, __half* sWh, __half* sXh) {

    const int C = K / 8;          // 16B chunks per X row
    const int KP = K + 8;         // padded W row (halves)
    int tid = threadIdx.x;
    int w = tid >> 5, lane = tid & 31;
    int node0 = (w & 7) * 16;     // 8 node groups x 16
    int o0 = (w >> 3) * 16;       // 4 out groups x 16
    int g = lane >> 2, t = lane & 3;
    int ntiles = (n + 127) >> 7;
    unsigned sx_base = smem_u32(sXh);

    for (int tile = blockIdx.x; tile < ntiles; tile += NB) {
        int base = tile << 7;
        int nn_max = n - base; if (nn_max > 128) nn_max = 128;
        __syncthreads();                              // protect smem from prior readers
        // ---- stage X (once per tile) ----
        if (CVT) {
            const float* xf = (const float*)xin;
            for (int idx = tid; idx < 128 * C; idx += NT) {
                int nn = idx / C, c = idx - nn * C;
                uint4 q;
                if (nn < nn_max) {
                    const float* p = xf + (size_t)(base + nn) * K + c * 8;
                    float4 v0 = *(const float4*)p;
                    float4 v1 = *(const float4*)(p + 4);
                    __half2 h0 = __floats2half2_rn(v0.x, v0.y);
                    __half2 h1 = __floats2half2_rn(v0.z, v0.w);
                    __half2 h2 = __floats2half2_rn(v1.x, v1.y);
                    __half2 h3 = __floats2half2_rn(v1.z, v1.w);
                    q.x = *reinterpret_cast<unsigned*>(&h0);
                    q.y = *reinterpret_cast<unsigned*>(&h1);
                    q.z = *reinterpret_cast<unsigned*>(&h2);
                    q.w = *reinterpret_cast<unsigned*>(&h3);
                } else { q = make_uint4(0, 0, 0, 0); }
                *(uint4*)(sXh + nn * K + ((c ^ (nn & 7)) << 3)) = q;
            }
        } else {
            const __half* xh = (const __half*)xin;
            for (int idx = tid; idx < 128 * C; idx += NT) {
                int nn = idx / C, c = idx - nn * C;
                uint4 q = (nn < nn_max)
                    ? *(const uint4*)(xh + (size_t)(base + nn) * K + c * 8)
                    : make_uint4(0, 0, 0, 0);
                *(uint4*)(sXh + nn * K + ((c ^ (nn & 7)) << 3)) = q;
            }
        }
        // ---- loop over output specs ----
        #pragma unroll
        for (int s = 0; s < NS; s++) {
            if (s > 0) __syncthreads();               // prev compute done before sW overwrite
            const float* Wp = Ws[s];
            for (int idx = tid; idx < 64 * (K / 2); idx += NT) {
                int o = idx / (K / 2), k2 = idx - o * (K / 2);
                float2 wv = *(const float2*)(Wp + o * K + k2 * 2);
                __half2 h = __floats2half2_rn(wv.x, wv.y);
                *(unsigned*)(sWh + o * KP + k2 * 2) = *reinterpret_cast<unsigned*>(&h);
            }
            __syncthreads();

            const float* Bp = Bs[s];
            float ba0 = Bp[o0 + t * 2],     ba1 = Bp[o0 + t * 2 + 1];
            float bb0 = Bp[o0 + 8 + t * 2], bb1 = Bp[o0 + 8 + t * 2 + 1];
            float d0[4] = {ba0, ba1, ba0, ba1};
            float d1[4] = {bb0, bb1, bb0, bb1};

            int row = node0 + (lane & 15);
            #pragma unroll
            for (int ks = 0; ks < K / 16; ks++) {
                int chunk = ks * 2 + (lane >> 4);
                unsigned addr = sx_base + (unsigned)(row * (K * 2) + ((chunk ^ (row & 7)) << 4));
                unsigned a0, a1, a2, a3;
                asm volatile("ldmatrix.sync.aligned.m8n8.x4.shared.b16 {%0,%1,%2,%3}, [%4];"
                             : "=r"(a0), "=r"(a1), "=r"(a2), "=r"(a3) : "r"(addr));
                const __half* wb = sWh + ks * 16 + t * 2;
                unsigned b00 = *(const unsigned*)(wb + (o0 + g) * KP);
                unsigned b01 = *(const unsigned*)(wb + (o0 + g) * KP + 8);
                unsigned b10 = *(const unsigned*)(wb + (o0 + 8 + g) * KP);
                unsigned b11 = *(const unsigned*)(wb + (o0 + 8 + g) * KP + 8);
                mma16816(d0, a0, a1, a2, a3, b00, b01);
                mma16816(d1, a0, a1, a2, a3, b10, b11);
            }

            // ---- epilogue: D rows = node0+g, node0+8+g; cols = o0(+8)+t*2, +1 ----
            unsigned f = flg[s];
            int ost = osts[s];
            int nl0 = node0 + g, nl1 = nl0 + 8;
            #pragma unroll
            for (int half_ = 0; half_ < 2; half_++) {
                int nl = half_ ? nl1 : nl0;
                if (nl < nn_max) {
                    int node = base + nl;
                    float v0 = half_ ? d0[2] : d0[0];
                    float v1 = half_ ? d0[3] : d0[1];
                    float v2 = half_ ? d1[2] : d1[0];
                    float v3 = half_ ? d1[3] : d1[1];
                    if (f & 1u) {
                        v0 = fmaxf(v0, 0.f); v1 = fmaxf(v1, 0.f);
                        v2 = fmaxf(v2, 0.f); v3 = fmaxf(v3, 0.f);
                    }
                    if (f & 2u) {
                        float sc = d_dinv[node];
                        v0 *= sc; v1 *= sc; v2 *= sc; v3 *= sc;
                    }
                    if (f & 4u) {
                        __half* op = (__half*)Os[s] + (size_t)node * ost;
                        __half2 h0 = __floats2half2_rn(v0, v1);
                        __half2 h1 = __floats2half2_rn(v2, v3);
                        *(unsigned*)(op + o0 + t * 2)     = *reinterpret_cast<unsigned*>(&h0);
                        *(unsigned*)(op + o0 + 8 + t * 2) = *reinterpret_cast<unsigned*>(&h1);
                    } else {
                        float* op = (float*)Os[s] + (size_t)node * ost;
                        *(float2*)(op + o0 + t * 2)     = make_float2(v0, v1);
                        *(float2*)(op + o0 + 8 + t * 2) = make_float2(v2, v3);
                    }
                }
            }
        }
    }
}

// ---------------- GCN aggregation (fp16 in, fp16 out): a_i = dinv_i*(sum hs_j + hs_i) ----
template <int D>
__device__ void agg_stage(const __half* __restrict__ hs, __half* __restrict__ out, int n) {
    const int LPN = D / 4, NPW = 32 / LPN;
    int lane = threadIdx.x & 31;
    int gw = (blockIdx.x * NT + threadIdx.x) >> 5;
    const int TOTW = NB * (NT / 32);
    int sub = lane / LPN;
    int c = (lane % LPN) * 4;
    for (int b = gw; b * NPW < n; b += TOTW) {
        int node = b * NPW + sub;
        if (node < n) {
            uint2 us = *(const uint2*)(hs + (size_t)node * D + c);
            float2 f0 = h22f2(us.x), f1 = h22f2(us.y);
            float4 acc = make_float4(f0.x, f0.y, f1.x, f1.y);
            int j0 = d_off[node], j1 = d_off[node + 1];
            int j = j0;
            for (; j + 3 < j1; j += 4) {
                int i0 = d_srcs[j], i1 = d_srcs[j + 1], i2 = d_srcs[j + 2], i3 = d_srcs[j + 3];
                uint2 u0 = *(const uint2*)(hs + (size_t)i0 * D + c);
                uint2 u1 = *(const uint2*)(hs + (size_t)i1 * D + c);
                uint2 u2 = *(const uint2*)(hs + (size_t)i2 * D + c);
                uint2 u3 = *(const uint2*)(hs + (size_t)i3 * D + c);
                float2 a0 = h22f2(u0.x), a1 = h22f2(u0.y);
                float2 b0 = h22f2(u1.x), b1 = h22f2(u1.y);
                float2 c0 = h22f2(u2.x), c1 = h22f2(u2.y);
                float2 e0 = h22f2(u3.x), e1 = h22f2(u3.y);
                acc.x += (a0.x + b0.x) + (c0.x + e0.x);
                acc.y += (a0.y + b0.y) + (c0.y + e0.y);
                acc.z += (a1.x + b1.x) + (c1.x + e1.x);
                acc.w += (a1.y + b1.y) + (c1.y + e1.y);
            }
            for (; j < j1; j++) {
                int i0 = d_srcs[j];
                uint2 u0 = *(const uint2*)(hs + (size_t)i0 * D + c);
                float2 a0 = h22f2(u0.x), a1 = h22f2(u0.y);
                acc.x += a0.x; acc.y += a0.y; acc.z += a1.x; acc.w += a1.y;
            }
            float dv = d_dinv[node];
            __half2 o0 = __floats2half2_rn(acc.x * dv, acc.y * dv);
            __half2 o1 = __floats2half2_rn(acc.z * dv, acc.w * dv);
            uint2 u;
            u.x = *reinterpret_cast<unsigned*>(&o0);
            u.y = *reinterpret_cast<unsigned*>(&o1);
            *(uint2*)(out + (size_t)node * D + c) = u;
        }
    }
}

// ---------------- the megakernel ----------------
extern __shared__ float smem_buf[];

__global__ __launch_bounds__(NT, 1) void mega(
    const float* __restrict__ x, const int* __restrict__ src, const int* __restrict__ dst,
    const float* __restrict__ pos,
    const float* __restrict__ emb_w, const float* __restrict__ emb_b,
    const float* __restrict__ c1_w, const float* __restrict__ c1_b,
    const float* __restrict__ c2_w, const float* __restrict__ c2_b,
    const float* __restrict__ bw1, const float* __restrict__ bb1,
    const float* __restrict__ bw2, const float* __restrict__ bb2,
    const float* __restrict__ hw1, const float* __restrict__ hb1,
    const float* __restrict__ hw2, const float* __restrict__ hb2,
    const float* __restrict__ hw3, const float* __restrict__ hb3,
    const float* __restrict__ ew1, const float* __restrict__ eb1,
    const float* __restrict__ ew2, const float* __restrict__ eb2,
    const float* __restrict__ ew3, const float* __restrict__ eb3,
    float* __restrict__ out, int n, int e) {

    __shared__ float s_red[32];
    __shared__ int   s_ired[32];
    __shared__ int   s_all[NB];
    __shared__ int   s_base;

    int tid = threadIdx.x, bid = blockIdx.x;
    int lane = tid & 31, wid = tid >> 5;
    int gt = bid * NT + tid;
    const int GSTR = NB * NT;
    __half* sWh = (__half*)smem_buf;                    // [64][K+8] fp16 (<= 17,408 B)
    __half* sXh = (__half*)((char*)smem_buf + 17408);   // [128][K] fp16 swizzled (<= 32,768 B)

    // ---- S0: zero degrees ----
    for (int i = gt; i < n; i += GSTR) d_deg[i] = 0;
    gbar();

    // ---- S1: count in-degrees ----
    for (int i = gt; i < e; i += GSTR) atomicAdd(&d_deg[dst[i]], 1);
    gbar();

    // ---- S2a: per-block chunk sums ----
    int chunk = (n + NB - 1) / NB;
    int lo = bid * chunk;
    int len = n - lo; if (len < 0) len = 0; if (len > chunk) len = chunk;
    int v = (tid < len) ? d_deg[lo + tid] : 0;
    {
        int wv = v;
        #pragma unroll
        for (int st = 16; st > 0; st >>= 1) wv += __shfl_down_sync(0xffffffffu, wv, st);
        if (lane == 0) s_ired[wid] = wv;
        __syncthreads();
        if (tid < 32) {
            int s = s_ired[tid];
            #pragma unroll
            for (int st = 16; st > 0; st >>= 1) s += __shfl_down_sync(0xffffffffu, s, st);
            if (tid == 0) d_bsum[bid] = s;
        }
    }
    gbar();

    // ---- S2c: base + local exclusive scan -> off/cur/dinv ----
    if (tid < NB) s_all[tid] = d_bsum[tid];
    __syncthreads();
    if (tid == 0) {
        int b = 0;
        for (int j = 0; j < bid; j++) b += s_all[j];
        s_base = b;
        if (bid == NB - 1) d_off[n] = b + s_all[NB - 1];
    }
    {
        int* a = (int*)smem_buf;
        a[tid] = v;
        __syncthreads();
        for (int st = 1; st < NT; st <<= 1) {
            int t = (tid >= st) ? a[tid - st] : 0;
            __syncthreads();
            a[tid] += t;
            __syncthreads();
        }
        int excl = a[tid] - v;
        if (tid < len) {
            int o = s_base + excl;
            d_off[lo + tid] = o;
            d_cur[lo + tid] = o;
            d_dinv[lo + tid] = rsqrtf((float)(v + 1));
        }
    }
    gbar();

    // ---- S3: CSR fill + embedding GEMM (fp32 x converted at staging) ----
    for (int i = gt; i < e; i += GSTR) {
        int dd = dst[i];
        int p = atomicAdd(&d_cur[dd], 1);
        d_srcs[p] = src[i];
    }
    {
        const float* Ws[1] = {emb_w}; const float* Bs[1] = {emb_b};
        void* Os[1] = {(void*)d_h0h}; int ost[1] = {64}; unsigned fl[1] = {1u | 2u | 4u};
        gemm_multi<128, true, 1>(x, Ws, Bs, Os, ost, fl, n, sWh, sXh);
    }
    gbar();

    // ---- S4: aggregate 64 ----
    agg_stage<64>(d_h0h, d_a0h, n);
    gbar();

    // ---- S5: GCN1 GEMM (64->128, relu, pre-scale) ----
    {
        const float* Ws[2] = {c1_w, c1_w + 64 * 64};
        const float* Bs[2] = {c1_b, c1_b + 64};
        void* Os[2] = {(void*)d_l1h, (void*)(d_l1h + 64)};
        int ost[2] = {128, 128}; unsigned fl[2] = {7u, 7u};
        gemm_multi<64, false, 2>(d_a0h, Ws, Bs, Os, ost, fl, n, sWh, sXh);
    }
    gbar();

    // ---- S6: aggregate 128 ----
    agg_stage<128>(d_l1h, d_agh, n);
    gbar();

    // ---- S7: GCN2 GEMM (128->128, relu) ----
    {
        const float* Ws[2] = {c2_w, c2_w + 64 * 128};
        const float* Bs[2] = {c2_b, c2_b + 64};
        void* Os[2] = {(void*)d_l2h, (void*)(d_l2h + 64)};
        int ost[2] = {128, 128}; unsigned fl[2] = {1u | 4u, 1u | 4u};
        gemm_multi<128, false, 2>(d_agh, Ws, Bs, Os, ost, fl, n, sWh, sXh);
    }
    gbar();

    // ---- S8: tail projections (X = l2 staged once, 3 weight sets) ----
    {
        const float* Ws[3] = {bw1, hw1, ew1};
        const float* Bs[3] = {bb1, hb1, eb1};
        void* Os[3] = {(void*)d_gh, (void*)d_t1h, (void*)d_t1e};
        int ost[3] = {64, 64, 64}; unsigned fl[3] = {4u, 1u, 1u};
        gemm_multi<128, false, 3>(d_l2h, Ws, Bs, Os, ost, fl, n, sWh, sXh);
    }
    gbar();

    // ---- S9a: tm MLP tail (warp per node) ----
    {
        float* F = smem_buf;
        float* sw2h = F;              // 64*33
        float* sw2e = F + 2112;       // 64*33
        float* s3h  = F + 4224;
        float* s3e  = F + 4256;
        float* sx   = F + 4288;       // 32*128
        for (int idx = tid; idx < 2048; idx += NT) {
            int o = idx >> 6, k = idx & 63;
            sw2h[k * 33 + o] = hw2[idx];
            sw2e[k * 33 + o] = ew2[idx];
        }
        if (tid < 32) s3h[tid] = hw3[tid];
        else if (tid < 64) s3e[tid - 32] = ew3[tid - 32];
        __syncthreads();
        float bh = hb2[lane], be = eb2[lane];
        float b3hv = hb3[0], b3ev = eb3[0];
        float accv = 0.f;
        float* sxw = sx + wid * 128;
        for (int node = bid * 32 + wid; node < n; node += NB * 32) {
            sxw[lane]      = d_t1h[(size_t)node * 64 + lane];
            sxw[32 + lane] = d_t1h[(size_t)node * 64 + 32 + lane];
            sxw[64 + lane] = d_t1e[(size_t)node * 64 + lane];
            sxw[96 + lane] = d_t1e[(size_t)node * 64 + 32 + lane];
            __syncwarp();
            float ah = bh, ae = be;
            #pragma unroll 8
            for (int k = 0; k < 64; k++) {
                ah += sxw[k]      * sw2h[k * 33 + lane];
                ae += sxw[64 + k] * sw2e[k * 33 + lane];
            }
            ah = fmaxf(ah, 0.f) * s3h[lane];
            ae = fmaxf(ae, 0.f) * s3e[lane];
            #pragma unroll
            for (int st = 16; st > 0; st >>= 1) {
                ah += __shfl_down_sync(0xffffffffu, ah, st);
                ae += __shfl_down_sync(0xffffffffu, ae, st);
            }
            if (lane == 0)
                accv += 0.5f * (1.f / (1.f + expf(-(ah + b3hv))) + 1.f / (1.f + expf(-(ae + b3ev))));
            __syncwarp();
        }
        if (lane == 0) s_red[wid] = accv;
        __syncthreads();
        if (tid < 32) {
            float s = s_red[tid];
            #pragma unroll
            for (int st = 16; st > 0; st >>= 1) s += __shfl_down_sync(0xffffffffu, s, st);
            if (tid == 0) d_pt[bid] = (double)s;
        }
        __syncthreads();
    }

    // ---- S9b: bond energy (8 threads/edge, fp16 gathers of g) ----
    {
        int sub = tid & 7;
        float wreg[8];
        #pragma unroll
        for (int j = 0; j < 8; j++) wreg[j] = bw2[sub * 8 + j];
        float b2v = bb2[0];
        const int GROUPS = NB * (NT / 8);
        int g0 = (bid * NT + tid) >> 3;
        float accq = 0.f;
        int cnt = 0;
        for (int eid = g0; eid < e; eid += GROUPS) {
            int s = src[eid], d = dst[eid];
            uint4 us = *(const uint4*)(d_gh + (size_t)s * 64 + sub * 8);
            uint4 ud = *(const uint4*)(d_gh + (size_t)d * 64 + sub * 8);
            float2 s0 = h22f2(us.x), s1 = h22f2(us.y), s2 = h22f2(us.z), s3 = h22f2(us.w);
            float2 t0 = h22f2(ud.x), t1 = h22f2(ud.y), t2 = h22f2(ud.z), t3 = h22f2(ud.w);
            float p = 0.f;
            p += fmaxf(0.5f * (s0.x + t0.x), 0.f) * wreg[0];
            p += fmaxf(0.5f * (s0.y + t0.y), 0.f) * wreg[1];
            p += fmaxf(0.5f * (s1.x + t1.x), 0.f) * wreg[2];
            p += fmaxf(0.5f * (s1.y + t1.y), 0.f) * wreg[3];
            p += fmaxf(0.5f * (s2.x + t2.x), 0.f) * wreg[4];
            p += fmaxf(0.5f * (s2.y + t2.y), 0.f) * wreg[5];
            p += fmaxf(0.5f * (s3.x + t3.x), 0.f) * wreg[6];
            p += fmaxf(0.5f * (s3.y + t3.y), 0.f) * wreg[7];
            p += __shfl_down_sync(0xffffffffu, p, 4, 8);
            p += __shfl_down_sync(0xffffffffu, p, 2, 8);
            p += __shfl_down_sync(0xffffffffu, p, 1, 8);
            if (sub == 0) {
                float dx = pos[d * 3 + 0] - pos[s * 3 + 0];
                float dy = pos[d * 3 + 1] - pos[s * 3 + 1];
                float dz = pos[d * 3 + 2] - pos[s * 3 + 2];
                float L = sqrtf(dx * dx + dy * dy + dz * dz);
                float t = L - 1.5f;
                accq += p + 1000.f * t * t;
                cnt++;
            }
        }
        float vv = accq + b2v * (float)cnt;
        vv += __shfl_down_sync(0xffffffffu, vv, 16);
        vv += __shfl_down_sync(0xffffffffu, vv, 8);
        if (lane == 0) s_red[wid] = vv;
        __syncthreads();
        if (tid < 32) {
            float s = s_red[tid];
            #pragma unroll
            for (int st = 16; st > 0; st >>= 1) s += __shfl_down_sync(0xffffffffu, s, st);
            if (tid == 0) d_pb[bid] = (double)s;
        }
    }
    gbar();

    // ---- S10: final scalars (block 0) ----
    if (bid == 0) {
        double* db = (double*)smem_buf;
        if (tid < NB) { db[tid] = d_pb[tid]; db[NB + tid] = d_pt[tid]; }
        __syncthreads();
        if (tid == 0) {
            double eb = 0.0, tm = 0.0;
            for (int i = 0; i < NB; i++) { eb += db[i]; tm += db[NB + i]; }
            tm /= (double)n;
            double et = eb + 3.0;
            if (tm < 0.5) et += (1.0 - tm) * 10.0;
            out[0] = (float)eb;
            out[1] = 1.0f; out[2] = 1.0f; out[3] = 1.0f;
            out[4] = (float)et;
            out[5] = (float)tm;
        }
    }
}

// ---------------- host launcher: ONE kernel launch ----------------
extern "C" void kernel_launch(void* const* d_in, const int* in_sizes, int n_in,
                              void* d_out, int out_size) {
    const float* x     = (const float*)d_in[0];
    const int*   ei    = (const int*)  d_in[1];
    const float* pos   = (const float*)d_in[2];
    /* d_in[3] = batch (unused) */
    const float* emb_w = (const float*)d_in[4];
    const float* emb_b = (const float*)d_in[5];
    const float* c1_w  = (const float*)d_in[6];
    const float* c1_b  = (const float*)d_in[7];
    const float* c2_w  = (const float*)d_in[8];
    const float* c2_b  = (const float*)d_in[9];
    const float* bw1   = (const float*)d_in[10];
    const float* bb1   = (const float*)d_in[11];
    const float* bw2   = (const float*)d_in[12];
    const float* bb2   = (const float*)d_in[13];
    const float* hw1   = (const float*)d_in[14];
    const float* hb1   = (const float*)d_in[15];
    const float* hw2   = (const float*)d_in[16];
    const float* hb2   = (const float*)d_in[17];
    const float* hw3   = (const float*)d_in[18];
    const float* hb3   = (const float*)d_in[19];
    const float* ew1   = (const float*)d_in[20];
    const float* eb1   = (const float*)d_in[21];
    const float* ew2   = (const float*)d_in[22];
    const float* eb2   = (const float*)d_in[23];
    const float* ew3   = (const float*)d_in[24];
    const float* eb3   = (const float*)d_in[25];

    int n = in_sizes[0] / 128;
    int e = in_sizes[1] / 2;
    const int* src = ei;
    const int* dst = ei + e;
    float* out = (float*)d_out;

    const int SMEM = 17408 + 32768;   // sW fp16 [64][136] + sX fp16 [128][128] = 50,176 B
    cudaFuncSetAttribute((const void*)mega, cudaFuncAttributeMaxDynamicSharedMemorySize, SMEM);

    mega<<<NB, NT, SMEM>>>(x, src, dst, pos,
                           emb_w, emb_b, c1_w, c1_b, c2_w, c2_b,
                           bw1, bb1, bw2, bb2,
                           hw1, hb1, hw2, hb2, hw3, hb3,
                           ew1, eb1, ew2, eb2, ew3, eb3,
                           out, n, e);
}

// round 12
// speedup vs baseline: 36.2842x; 1.0768x over previous
#include <cuda_runtime.h>
#include <cuda_fp16.h>
#include <math.h>

#define NB 148
#define NT 1024
#define NMAX 50000
#define EMAX 1600000

typedef unsigned long long u64;

// ---------------- scratch (device globals) ----------------
__device__ __half d_h0h[(size_t)NMAX * 64];   // emb out (pre-scaled by dinv), fp16
__device__ __half d_a0h[(size_t)NMAX * 64];   // aggregated 64, fp16
__device__ __half d_l1h[(size_t)NMAX * 128];  // c1 out (pre-scaled), fp16
__device__ __half d_agh[(size_t)NMAX * 128];  // aggregated 128, fp16
__device__ __half d_l2h[(size_t)NMAX * 128];  // c2 out = final features, fp16
__device__ __half d_gh [(size_t)NMAX * 64];   // bond projection, fp16
__device__ __half d_t12h[(size_t)NMAX * 128]; // [t1h | t1e] fp16
__device__ __half d_t2x[(size_t)NMAX * 64];   // [t2h | t2e] fp16
__device__ float  d_b2c[64];                  // [hb2 | eb2]
__device__ float  d_dinv[NMAX];
__device__ int    d_deg[NMAX];
__device__ int    d_off[NMAX + 1];
__device__ int    d_cur[NMAX];
__device__ int    d_srcs[EMAX];
__device__ int    d_bsum[NB];
__device__ double d_pb[NB];
__device__ double d_pt[NB];
__device__ unsigned int g_bar;               // monotonic across replays

// ---------------- grid barrier ----------------
__device__ __forceinline__ void gbar() {
    __syncthreads();
    if (threadIdx.x == 0) {
        __threadfence();
        unsigned int old = atomicAdd(&g_bar, 1u);
        unsigned int target = (old / NB + 1u) * NB;
        while (*((volatile unsigned int*)&g_bar) < target) { }
        __threadfence();
    }
    __syncthreads();
}

__device__ __forceinline__ float2 h22f2(unsigned u) {
    __half2 h = *reinterpret_cast<__half2*>(&u);
    return __half22float2(h);
}

__device__ __forceinline__ unsigned smem_u32(const void* p) {
    return (unsigned)__cvta_generic_to_shared(p);
}

__device__ __forceinline__ void mma16816(float* d,
                                         unsigned a0, unsigned a1, unsigned a2, unsigned a3,
                                         unsigned b0, unsigned b1) {
    asm volatile(
        "mma.sync.aligned.m16n8k16.row.col.f32.f16.f16.f32 "
        "{%0,%1,%2,%3}, {%4,%5,%6,%7}, {%8,%9}, {%0,%1,%2,%3};"
        : "+f"(d[0]), "+f"(d[1]), "+f"(d[2]), "+f"(d[3])
        : "r"(a0), "r"(a1), "r"(a2), "r"(a3), "r"(b0), "r"(b1));
}

// ---------------- tensor-core multi-output GEMM: stage X once, loop weight specs ----------------
// flags: 1=relu, 2=scale(dinv), 4=fp16 out, 8=block-diag W (Ws=[32][64] upper-left, Ws2=[32][64] lower-right)
template <int K, bool CVT, int NS>
__device__ __forceinline__ void gemm_multi(
    const void* xin,
    const float* const* Ws, const float* const* Ws2, const float* const* Bs,
    void* const* Os, const int* osts, const unsigned* flg,
    int n, __half* sWh, __half* sXh) {

    const int C = K / 8;          // 16B chunks per X row
    const int KP = K + 8;         // padded W row (halves)
    int tid = threadIdx.x;
    int w = tid >> 5, lane = tid & 31;
    int node0 = (w & 7) * 16;     // 8 node groups x 16
    int o0 = (w >> 3) * 16;       // 4 out groups x 16
    int g = lane >> 2, t = lane & 3;
    int ntiles = (n + 127) >> 7;
    unsigned sx_base = smem_u32(sXh);

    for (int tile = blockIdx.x; tile < ntiles; tile += NB) {
        int base = tile << 7;
        int nn_max = n - base; if (nn_max > 128) nn_max = 128;
        __syncthreads();                              // protect smem from prior readers
        // ---- stage X (once per tile) ----
        if (CVT) {
            const float* xf = (const float*)xin;
            for (int idx = tid; idx < 128 * C; idx += NT) {
                int nn = idx / C, c = idx - nn * C;
                uint4 q;
                if (nn < nn_max) {
                    const float* p = xf + (size_t)(base + nn) * K + c * 8;
                    float4 v0 = *(const float4*)p;
                    float4 v1 = *(const float4*)(p + 4);
                    __half2 h0 = __floats2half2_rn(v0.x, v0.y);
                    __half2 h1 = __floats2half2_rn(v0.z, v0.w);
                    __half2 h2 = __floats2half2_rn(v1.x, v1.y);
                    __half2 h3 = __floats2half2_rn(v1.z, v1.w);
                    q.x = *reinterpret_cast<unsigned*>(&h0);
                    q.y = *reinterpret_cast<unsigned*>(&h1);
                    q.z = *reinterpret_cast<unsigned*>(&h2);
                    q.w = *reinterpret_cast<unsigned*>(&h3);
                } else { q = make_uint4(0, 0, 0, 0); }
                *(uint4*)(sXh + nn * K + ((c ^ (nn & 7)) << 3)) = q;
            }
        } else {
            const __half* xh = (const __half*)xin;
            for (int idx = tid; idx < 128 * C; idx += NT) {
                int nn = idx / C, c = idx - nn * C;
                uint4 q = (nn < nn_max)
                    ? *(const uint4*)(xh + (size_t)(base + nn) * K + c * 8)
                    : make_uint4(0, 0, 0, 0);
                *(uint4*)(sXh + nn * K + ((c ^ (nn & 7)) << 3)) = q;
            }
        }
        // ---- loop over output specs ----
        #pragma unroll
        for (int s = 0; s < NS; s++) {
            if (s > 0) __syncthreads();               // prev compute done before sW overwrite
            unsigned f = flg[s];
            if (f & 8u) {
                // block-diagonal: rows 0-31 = [Wh | 0], rows 32-63 = [0 | We]; each [32][64]
                const float* Wh = Ws[s];
                const float* We = Ws2[s];
                for (int idx = tid; idx < 64 * (KP / 2); idx += NT) {
                    int o = idx / (KP / 2), w2 = idx - o * (KP / 2);
                    unsigned val = 0u;
                    if (o < 32) {
                        if (w2 < 32) {
                            float2 v = *(const float2*)(Wh + o * 64 + w2 * 2);
                            __half2 h = __floats2half2_rn(v.x, v.y);
                            val = *reinterpret_cast<unsigned*>(&h);
                        }
                    } else {
                        if (w2 >= 32 && w2 < 64) {
                            float2 v = *(const float2*)(We + (o - 32) * 64 + (w2 - 32) * 2);
                            __half2 h = __floats2half2_rn(v.x, v.y);
                            val = *reinterpret_cast<unsigned*>(&h);
                        }
                    }
                    *(unsigned*)(sWh + o * KP + w2 * 2) = val;
                }
            } else {
                const float* Wp = Ws[s];
                for (int idx = tid; idx < 64 * (K / 2); idx += NT) {
                    int o = idx / (K / 2), k2 = idx - o * (K / 2);
                    float2 wv = *(const float2*)(Wp + o * K + k2 * 2);
                    __half2 h = __floats2half2_rn(wv.x, wv.y);
                    *(unsigned*)(sWh + o * KP + k2 * 2) = *reinterpret_cast<unsigned*>(&h);
                }
            }
            __syncthreads();

            const float* Bp = Bs[s];
            float ba0 = Bp[o0 + t * 2],     ba1 = Bp[o0 + t * 2 + 1];
            float bb0 = Bp[o0 + 8 + t * 2], bb1 = Bp[o0 + 8 + t * 2 + 1];
            float d0[4] = {ba0, ba1, ba0, ba1};
            float d1[4] = {bb0, bb1, bb0, bb1};

            int row = node0 + (lane & 15);
            #pragma unroll
            for (int ks = 0; ks < K / 16; ks++) {
                int chunk = ks * 2 + (lane >> 4);
                unsigned addr = sx_base + (unsigned)(row * (K * 2) + ((chunk ^ (row & 7)) << 4));
                unsigned a0, a1, a2, a3;
                asm volatile("ldmatrix.sync.aligned.m8n8.x4.shared.b16 {%0,%1,%2,%3}, [%4];"
                             : "=r"(a0), "=r"(a1), "=r"(a2), "=r"(a3) : "r"(addr));
                const __half* wb = sWh + ks * 16 + t * 2;
                unsigned b00 = *(const unsigned*)(wb + (o0 + g) * KP);
                unsigned b01 = *(const unsigned*)(wb + (o0 + g) * KP + 8);
                unsigned b10 = *(const unsigned*)(wb + (o0 + 8 + g) * KP);
                unsigned b11 = *(const unsigned*)(wb + (o0 + 8 + g) * KP + 8);
                mma16816(d0, a0, a1, a2, a3, b00, b01);
                mma16816(d1, a0, a1, a2, a3, b10, b11);
            }

            // ---- epilogue ----
            int ost = osts[s];
            int nl0 = node0 + g, nl1 = nl0 + 8;
            #pragma unroll
            for (int half_ = 0; half_ < 2; half_++) {
                int nl = half_ ? nl1 : nl0;
                if (nl < nn_max) {
                    int node = base + nl;
                    float v0 = half_ ? d0[2] : d0[0];
                    float v1 = half_ ? d0[3] : d0[1];
                    float v2 = half_ ? d1[2] : d1[0];
                    float v3 = half_ ? d1[3] : d1[1];
                    if (f & 1u) {
                        v0 = fmaxf(v0, 0.f); v1 = fmaxf(v1, 0.f);
                        v2 = fmaxf(v2, 0.f); v3 = fmaxf(v3, 0.f);
                    }
                    if (f & 2u) {
                        float sc = d_dinv[node];
                        v0 *= sc; v1 *= sc; v2 *= sc; v3 *= sc;
                    }
                    if (f & 4u) {
                        __half* op = (__half*)Os[s] + (size_t)node * ost;
                        __half2 h0 = __floats2half2_rn(v0, v1);
                        __half2 h1 = __floats2half2_rn(v2, v3);
                        *(unsigned*)(op + o0 + t * 2)     = *reinterpret_cast<unsigned*>(&h0);
                        *(unsigned*)(op + o0 + 8 + t * 2) = *reinterpret_cast<unsigned*>(&h1);
                    } else {
                        float* op = (float*)Os[s] + (size_t)node * ost;
                        *(float2*)(op + o0 + t * 2)     = make_float2(v0, v1);
                        *(float2*)(op + o0 + 8 + t * 2) = make_float2(v2, v3);
                    }
                }
            }
        }
    }
}

// ---------------- GCN aggregation (fp16 in, fp16 out): a_i = dinv_i*(sum hs_j + hs_i) ----
template <int D>
__device__ void agg_stage(const __half* __restrict__ hs, __half* __restrict__ out, int n) {
    const int LPN = D / 4, NPW = 32 / LPN;
    int lane = threadIdx.x & 31;
    int gw = (blockIdx.x * NT + threadIdx.x) >> 5;
    const int TOTW = NB * (NT / 32);
    int sub = lane / LPN;
    int c = (lane % LPN) * 4;
    for (int b = gw; b * NPW < n; b += TOTW) {
        int node = b * NPW + sub;
        if (node < n) {
            uint2 us = *(const uint2*)(hs + (size_t)node * D + c);
            float2 f0 = h22f2(us.x), f1 = h22f2(us.y);
            float4 acc = make_float4(f0.x, f0.y, f1.x, f1.y);
            int j0 = d_off[node], j1 = d_off[node + 1];
            int j = j0;
            for (; j + 3 < j1; j += 4) {
                int i0 = d_srcs[j], i1 = d_srcs[j + 1], i2 = d_srcs[j + 2], i3 = d_srcs[j + 3];
                uint2 u0 = *(const uint2*)(hs + (size_t)i0 * D + c);
                uint2 u1 = *(const uint2*)(hs + (size_t)i1 * D + c);
                uint2 u2 = *(const uint2*)(hs + (size_t)i2 * D + c);
                uint2 u3 = *(const uint2*)(hs + (size_t)i3 * D + c);
                float2 a0 = h22f2(u0.x), a1 = h22f2(u0.y);
                float2 b0 = h22f2(u1.x), b1 = h22f2(u1.y);
                float2 c0 = h22f2(u2.x), c1 = h22f2(u2.y);
                float2 e0 = h22f2(u3.x), e1 = h22f2(u3.y);
                acc.x += (a0.x + b0.x) + (c0.x + e0.x);
                acc.y += (a0.y + b0.y) + (c0.y + e0.y);
                acc.z += (a1.x + b1.x) + (c1.x + e1.x);
                acc.w += (a1.y + b1.y) + (c1.y + e1.y);
            }
            for (; j < j1; j++) {
                int i0 = d_srcs[j];
                uint2 u0 = *(const uint2*)(hs + (size_t)i0 * D + c);
                float2 a0 = h22f2(u0.x), a1 = h22f2(u0.y);
                acc.x += a0.x; acc.y += a0.y; acc.z += a1.x; acc.w += a1.y;
            }
            float dv = d_dinv[node];
            __half2 o0 = __floats2half2_rn(acc.x * dv, acc.y * dv);
            __half2 o1 = __floats2half2_rn(acc.z * dv, acc.w * dv);
            uint2 u;
            u.x = *reinterpret_cast<unsigned*>(&o0);
            u.y = *reinterpret_cast<unsigned*>(&o1);
            *(uint2*)(out + (size_t)node * D + c) = u;
        }
    }
}

// ---------------- the megakernel ----------------
extern __shared__ float smem_buf[];

__global__ __launch_bounds__(NT, 1) void mega(
    const float* __restrict__ x, const int* __restrict__ src, const int* __restrict__ dst,
    const float* __restrict__ pos,
    const float* __restrict__ emb_w, const float* __restrict__ emb_b,
    const float* __restrict__ c1_w, const float* __restrict__ c1_b,
    const float* __restrict__ c2_w, const float* __restrict__ c2_b,
    const float* __restrict__ bw1, const float* __restrict__ bb1,
    const float* __restrict__ bw2, const float* __restrict__ bb2,
    const float* __restrict__ hw1, const float* __restrict__ hb1,
    const float* __restrict__ hw2, const float* __restrict__ hb2,
    const float* __restrict__ hw3, const float* __restrict__ hb3,
    const float* __restrict__ ew1, const float* __restrict__ eb1,
    const float* __restrict__ ew2, const float* __restrict__ eb2,
    const float* __restrict__ ew3, const float* __restrict__ eb3,
    float* __restrict__ out, int n, int e) {

    __shared__ float s_red[32];
    __shared__ int   s_ired[32];
    __shared__ int   s_all[NB];
    __shared__ int   s_base;
    __shared__ float s3w[64];

    int tid = threadIdx.x, bid = blockIdx.x;
    int lane = tid & 31, wid = tid >> 5;
    int gt = bid * NT + tid;
    const int GSTR = NB * NT;
    __half* sWh = (__half*)smem_buf;                    // [64][K+8] fp16
    __half* sXh = (__half*)((char*)smem_buf + 17408);   // [128][K] fp16 swizzled

    // ---- S0: zero degrees + build combined bias ----
    for (int i = gt; i < n; i += GSTR) d_deg[i] = 0;
    if (bid == 0 && tid < 64) d_b2c[tid] = (tid < 32) ? hb2[tid] : eb2[tid - 32];
    gbar();

    // ---- S1: count in-degrees ----
    for (int i = gt; i < e; i += GSTR) atomicAdd(&d_deg[dst[i]], 1);
    gbar();

    // ---- S2a: per-block chunk sums ----
    int chunk = (n + NB - 1) / NB;
    int lo = bid * chunk;
    int len = n - lo; if (len < 0) len = 0; if (len > chunk) len = chunk;
    int v = (tid < len) ? d_deg[lo + tid] : 0;
    {
        int wv = v;
        #pragma unroll
        for (int st = 16; st > 0; st >>= 1) wv += __shfl_down_sync(0xffffffffu, wv, st);
        if (lane == 0) s_ired[wid] = wv;
        __syncthreads();
        if (tid < 32) {
            int s = s_ired[tid];
            #pragma unroll
            for (int st = 16; st > 0; st >>= 1) s += __shfl_down_sync(0xffffffffu, s, st);
            if (tid == 0) d_bsum[bid] = s;
        }
    }
    gbar();

    // ---- S2c: base + local exclusive scan -> off/cur/dinv ----
    if (tid < NB) s_all[tid] = d_bsum[tid];
    __syncthreads();
    if (tid == 0) {
        int b = 0;
        for (int j = 0; j < bid; j++) b += s_all[j];
        s_base = b;
        if (bid == NB - 1) d_off[n] = b + s_all[NB - 1];
    }
    {
        int* a = (int*)smem_buf;
        a[tid] = v;
        __syncthreads();
        for (int st = 1; st < NT; st <<= 1) {
            int t = (tid >= st) ? a[tid - st] : 0;
            __syncthreads();
            a[tid] += t;
            __syncthreads();
        }
        int excl = a[tid] - v;
        if (tid < len) {
            int o = s_base + excl;
            d_off[lo + tid] = o;
            d_cur[lo + tid] = o;
            d_dinv[lo + tid] = rsqrtf((float)(v + 1));
        }
    }
    gbar();

    // ---- S3: CSR fill + embedding GEMM (fp32 x converted at staging) ----
    for (int i = gt; i < e; i += GSTR) {
        int dd = dst[i];
        int p = atomicAdd(&d_cur[dd], 1);
        d_srcs[p] = src[i];
    }
    {
        const float* Ws[1] = {emb_w}; const float* Bs[1] = {emb_b};
        void* Os[1] = {(void*)d_h0h}; int ost[1] = {64}; unsigned fl[1] = {1u | 2u | 4u};
        gemm_multi<128, true, 1>(x, Ws, Ws, Bs, Os, ost, fl, n, sWh, sXh);
    }
    gbar();

    // ---- S4: aggregate 64 ----
    agg_stage<64>(d_h0h, d_a0h, n);
    gbar();

    // ---- S5: GCN1 GEMM (64->128, relu, pre-scale) ----
    {
        const float* Ws[2] = {c1_w, c1_w + 64 * 64};
        const float* Bs[2] = {c1_b, c1_b + 64};
        void* Os[2] = {(void*)d_l1h, (void*)(d_l1h + 64)};
        int ost[2] = {128, 128}; unsigned fl[2] = {7u, 7u};
        gemm_multi<64, false, 2>(d_a0h, Ws, Ws, Bs, Os, ost, fl, n, sWh, sXh);
    }
    gbar();

    // ---- S6: aggregate 128 ----
    agg_stage<128>(d_l1h, d_agh, n);
    gbar();

    // ---- S7: GCN2 GEMM (128->128, relu) ----
    {
        const float* Ws[2] = {c2_w, c2_w + 64 * 128};
        const float* Bs[2] = {c2_b, c2_b + 64};
        void* Os[2] = {(void*)d_l2h, (void*)(d_l2h + 64)};
        int ost[2] = {128, 128}; unsigned fl[2] = {1u | 4u, 1u | 4u};
        gemm_multi<128, false, 2>(d_agh, Ws, Ws, Bs, Os, ost, fl, n, sWh, sXh);
    }
    gbar();

    // ---- S8: tail projections (X = l2 staged once; g, t1h, t1e all fp16) ----
    {
        const float* Ws[3] = {bw1, hw1, ew1};
        const float* Bs[3] = {bb1, hb1, eb1};
        void* Os[3] = {(void*)d_gh, (void*)d_t12h, (void*)(d_t12h + 64)};
        int ost[3] = {64, 128, 128}; unsigned fl[3] = {4u, 5u, 5u};
        gemm_multi<128, false, 3>(d_l2h, Ws, Ws, Bs, Os, ost, fl, n, sWh, sXh);
    }
    gbar();

    // ---- S9: tm layer-2 GEMM (block-diag) + bond energy ----
    {
        const float* Ws[1] = {hw2}; const float* W2s[1] = {ew2};
        const float* Bs[1] = {(const float*)d_b2c};
        void* Os[1] = {(void*)d_t2x}; int ost[1] = {64}; unsigned fl[1] = {1u | 4u | 8u};
        gemm_multi<128, false, 1>(d_t12h, Ws, W2s, Bs, Os, ost, fl, n, sWh, sXh);
    }
    {
        int sub = tid & 7;
        float wreg[8];
        #pragma unroll
        for (int j = 0; j < 8; j++) wreg[j] = bw2[sub * 8 + j];
        float b2v = bb2[0];
        const int GROUPS = NB * (NT / 8);
        int g0 = (bid * NT + tid) >> 3;
        float accq = 0.f;
        int cnt = 0;
        for (int eid = g0; eid < e; eid += GROUPS) {
            int s = src[eid], d = dst[eid];
            uint4 us = *(const uint4*)(d_gh + (size_t)s * 64 + sub * 8);
            uint4 ud = *(const uint4*)(d_gh + (size_t)d * 64 + sub * 8);
            float2 s0 = h22f2(us.x), s1 = h22f2(us.y), s2 = h22f2(us.z), s3 = h22f2(us.w);
            float2 t0 = h22f2(ud.x), t1 = h22f2(ud.y), t2 = h22f2(ud.z), t3 = h22f2(ud.w);
            float p = 0.f;
            p += fmaxf(0.5f * (s0.x + t0.x), 0.f) * wreg[0];
            p += fmaxf(0.5f * (s0.y + t0.y), 0.f) * wreg[1];
            p += fmaxf(0.5f * (s1.x + t1.x), 0.f) * wreg[2];
            p += fmaxf(0.5f * (s1.y + t1.y), 0.f) * wreg[3];
            p += fmaxf(0.5f * (s2.x + t2.x), 0.f) * wreg[4];
            p += fmaxf(0.5f * (s2.y + t2.y), 0.f) * wreg[5];
            p += fmaxf(0.5f * (s3.x + t3.x), 0.f) * wreg[6];
            p += fmaxf(0.5f * (s3.y + t3.y), 0.f) * wreg[7];
            p += __shfl_down_sync(0xffffffffu, p, 4, 8);
            p += __shfl_down_sync(0xffffffffu, p, 2, 8);
            p += __shfl_down_sync(0xffffffffu, p, 1, 8);
            if (sub == 0) {
                float dx = pos[d * 3 + 0] - pos[s * 3 + 0];
                float dy = pos[d * 3 + 1] - pos[s * 3 + 1];
                float dz = pos[d * 3 + 2] - pos[s * 3 + 2];
                float L = sqrtf(dx * dx + dy * dy + dz * dz);
                float t = L - 1.5f;
                accq += p + 1000.f * t * t;
                cnt++;
            }
        }
        float vv = accq + b2v * (float)cnt;
        vv += __shfl_down_sync(0xffffffffu, vv, 16);
        vv += __shfl_down_sync(0xffffffffu, vv, 8);
        __syncthreads();                       // smem (s_red) free after GEMM section
        if (lane == 0) s_red[wid] = vv;
        __syncthreads();
        if (tid < 32) {
            float s = s_red[tid];
            #pragma unroll
            for (int st = 16; st > 0; st >>= 1) s += __shfl_down_sync(0xffffffffu, s, st);
            if (tid == 0) d_pb[bid] = (double)s;
        }
    }
    gbar();

    // ---- S10: tm final dots + sigmoid + mean partials (warp per node) ----
    {
        if (tid < 64) s3w[tid] = (tid < 32) ? hw3[tid] : ew3[tid - 32];
        __syncthreads();
        float b3hv = hb3[0], b3ev = eb3[0];
        float accv = 0.f;
        int part = lane >> 4, li = lane & 15;
        for (int node = bid * 32 + wid; node < n; node += NB * 32) {
            unsigned u = *(const unsigned*)(d_t2x + (size_t)node * 64 + part * 32 + li * 2);
            float2 fv = h22f2(u);
            float p = fv.x * s3w[part * 32 + li * 2] + fv.y * s3w[part * 32 + li * 2 + 1];
            p += __shfl_down_sync(0xffffffffu, p, 8, 16);
            p += __shfl_down_sync(0xffffffffu, p, 4, 16);
            p += __shfl_down_sync(0xffffffffu, p, 2, 16);
            p += __shfl_down_sync(0xffffffffu, p, 1, 16);
            float pe = __shfl_sync(0xffffffffu, p, 16);
            if (lane == 0)
                accv += 0.5f * (1.f / (1.f + expf(-(p + b3hv))) + 1.f / (1.f + expf(-(pe + b3ev))));
        }
        if (lane == 0) s_red[wid] = accv;
        __syncthreads();
        if (tid < 32) {
            float s = s_red[tid];
            #pragma unroll
            for (int st = 16; st > 0; st >>= 1) s += __shfl_down_sync(0xffffffffu, s, st);
            if (tid == 0) d_pt[bid] = (double)s;
        }
    }
    gbar();

    // ---- S11: final scalars (block 0) ----
    if (bid == 0) {
        double* db = (double*)smem_buf;
        if (tid < NB) { db[tid] = d_pb[tid]; db[NB + tid] = d_pt[tid]; }
        __syncthreads();
        if (tid == 0) {
            double eb = 0.0, tm = 0.0;
            for (int i = 0; i < NB; i++) { eb += db[i]; tm += db[NB + i]; }
            tm /= (double)n;
            double et = eb + 3.0;
            if (tm < 0.5) et += (1.0 - tm) * 10.0;
            out[0] = (float)eb;
            out[1] = 1.0f; out[2] = 1.0f; out[3] = 1.0f;
            out[4] = (float)et;
            out[5] = (float)tm;
        }
    }
}

// ---------------- host launcher: ONE kernel launch ----------------
extern "C" void kernel_launch(void* const* d_in, const int* in_sizes, int n_in,
                              void* d_out, int out_size) {
    const float* x     = (const float*)d_in[0];
    const int*   ei    = (const int*)  d_in[1];
    const float* pos   = (const float*)d_in[2];
    /* d_in[3] = batch (unused) */
    const float* emb_w = (const float*)d_in[4];
    const float* emb_b = (const float*)d_in[5];
    const float* c1_w  = (const float*)d_in[6];
    const float* c1_b  = (const float*)d_in[7];
    const float* c2_w  = (const float*)d_in[8];
    const float* c2_b  = (const float*)d_in[9];
    const float* bw1   = (const float*)d_in[10];
    const float* bb1   = (const float*)d_in[11];
    const float* bw2   = (const float*)d_in[12];
    const float* bb2   = (const float*)d_in[13];
    const float* hw1   = (const float*)d_in[14];
    const float* hb1   = (const float*)d_in[15];
    const float* hw2   = (const float*)d_in[16];
    const float* hb2   = (const float*)d_in[17];
    const float* hw3   = (const float*)d_in[18];
    const float* hb3   = (const float*)d_in[19];
    const float* ew1   = (const float*)d_in[20];
    const float* eb1   = (const float*)d_in[21];
    const float* ew2   = (const float*)d_in[22];
    const float* eb2   = (const float*)d_in[23];
    const float* ew3   = (const float*)d_in[24];
    const float* eb3   = (const float*)d_in[25];

    int n = in_sizes[0] / 128;
    int e = in_sizes[1] / 2;
    const int* src = ei;
    const int* dst = ei + e;
    float* out = (float*)d_out;

    const int SMEM = 17408 + 32768;   // sW fp16 [64][136] + sX fp16 [128][128] = 50,176 B
    cudaFuncSetAttribute((const void*)mega, cudaFuncAttributeMaxDynamicSharedMemorySize, SMEM);

    mega<<<NB, NT, SMEM>>>(x, src, dst, pos,
                           emb_w, emb_b, c1_w, c1_b, c2_w, c2_b,
                           bw1, bb1, bw2, bb2,
                           hw1, hb1, hw2, hb2, hw3, hb3,
                           ew1, eb1, ew2, eb2, ew3, eb3,
                           out, n, e);
}